// round 1
// baseline (speedup 1.0000x reference)
#include <cuda_runtime.h>
#include <math.h>
#include <stdint.h>

#define N_ 1024
#define M_ 1024
#define D_ 1024
#define G_ 16
#define DG_ 64

// ---------------- scratch (device globals; no allocation allowed) ----------------
__device__ float g_q[(size_t)N_ * D_];          // (N, G*DG) row-major
__device__ float g_k[(size_t)M_ * D_];          // (M, G*DG)
__device__ float g_v[(size_t)M_ * D_];          // V[g,m,o] stored as (M, g*64+o)
__device__ float g_w[(size_t)N_ * G_ * M_];     // relu(posw)+1e-6, layout (N, G, M)
__device__ float g_boxA[N_ * 6];                // cx, cy, 1/w, 1/h, log w, log h
__device__ float g_boxB[M_ * 6];

// ---------------- fast exp for x <= 0 (pure FMA pipe, no MUFU) ----------------
__device__ __forceinline__ float exp_nonpos(float x) {
    float t = fmaxf(x * 1.4426950408889634f, -126.0f);
    float fi = floorf(t);
    float f = t - fi;                       // [0,1)
    float p = 1.5403530393e-4f;
    p = fmaf(p, f, 1.3333558146e-3f);
    p = fmaf(p, f, 9.6181291076e-3f);
    p = fmaf(p, f, 5.5504108664e-2f);
    p = fmaf(p, f, 2.4022650696e-1f);
    p = fmaf(p, f, 6.9314718056e-1f);
    p = fmaf(p, f, 1.0f);
    int e = (int)fi;                        // [-126, 0]
    return p * __int_as_float((e + 127) << 23);
}

// ---------------- box preprocessing ----------------
__global__ void box_prep(const float* __restrict__ rois1, const float* __restrict__ rois2) {
    int i = blockIdx.x * blockDim.x + threadIdx.x;
    if (i < N_) {
        float xmin = rois1[i * 4 + 0], ymin = rois1[i * 4 + 1];
        float xmax = rois1[i * 4 + 2], ymax = rois1[i * 4 + 3];
        float w = xmax - xmin + 1.0f, h = ymax - ymin + 1.0f;
        g_boxA[i * 6 + 0] = 0.5f * (xmin + xmax);
        g_boxA[i * 6 + 1] = 0.5f * (ymin + ymax);
        g_boxA[i * 6 + 2] = 1.0f / w;
        g_boxA[i * 6 + 3] = 1.0f / h;
        g_boxA[i * 6 + 4] = logf(w);
        g_boxA[i * 6 + 5] = logf(h);
    }
    if (i < M_) {
        float xmin = rois2[i * 4 + 0], ymin = rois2[i * 4 + 1];
        float xmax = rois2[i * 4 + 2], ymax = rois2[i * 4 + 3];
        float w = xmax - xmin + 1.0f, h = ymax - ymin + 1.0f;
        g_boxB[i * 6 + 0] = 0.5f * (xmin + xmax);
        g_boxB[i * 6 + 1] = 0.5f * (ymin + ymax);
        g_boxB[i * 6 + 2] = 1.0f / w;
        g_boxB[i * 6 + 3] = 1.0f / h;
        g_boxB[i * 6 + 4] = logf(w);
        g_boxB[i * 6 + 5] = logf(h);
    }
}

// ---------------- tiled SGEMM: C = A * op(B) + bias(col) ----------------
// A: 1024x1024 row-major. BT=false: B[k][j]; BT=true: B[j][k]. C: 1024x1024.
template <bool BT>
__global__ void sgemm_bias(const float* __restrict__ A, const float* __restrict__ B,
                           const float* __restrict__ bias, float* __restrict__ C) {
    __shared__ float As[16][68];  // As[k][i]
    __shared__ float Bs[16][68];  // Bs[k][j]
    const int tx = threadIdx.x, ty = threadIdx.y;
    const int tid = ty * 16 + tx;
    const int i0 = blockIdx.y * 64, j0 = blockIdx.x * 64;

    float acc[4][4] = {};

    for (int kt = 0; kt < D_; kt += 16) {
        {   // A tile 64x16 -> As[k][i]
            int i = tid >> 2;
            int k4 = (tid & 3) * 4;
            float4 a = *(const float4*)&A[(size_t)(i0 + i) * D_ + kt + k4];
            As[k4 + 0][i] = a.x; As[k4 + 1][i] = a.y; As[k4 + 2][i] = a.z; As[k4 + 3][i] = a.w;
        }
        if (!BT) {  // B tile 16x64 -> Bs[k][j]
            int k = tid >> 4;
            int j4 = (tid & 15) * 4;
            float4 b = *(const float4*)&B[(size_t)(kt + k) * D_ + j0 + j4];
            Bs[k][j4 + 0] = b.x; Bs[k][j4 + 1] = b.y; Bs[k][j4 + 2] = b.z; Bs[k][j4 + 3] = b.w;
        } else {    // B tile 64x16 (rows j, cols k) -> Bs[k][j]
            int j = tid >> 2;
            int k4 = (tid & 3) * 4;
            float4 b = *(const float4*)&B[(size_t)(j0 + j) * D_ + kt + k4];
            Bs[k4 + 0][j] = b.x; Bs[k4 + 1][j] = b.y; Bs[k4 + 2][j] = b.z; Bs[k4 + 3][j] = b.w;
        }
        __syncthreads();
#pragma unroll
        for (int k = 0; k < 16; k++) {
            float4 a = *(const float4*)&As[k][ty * 4];
            float4 b = *(const float4*)&Bs[k][tx * 4];
            float ar[4] = {a.x, a.y, a.z, a.w};
            float br[4] = {b.x, b.y, b.z, b.w};
#pragma unroll
            for (int ii = 0; ii < 4; ii++)
#pragma unroll
                for (int jj = 0; jj < 4; jj++)
                    acc[ii][jj] = fmaf(ar[ii], br[jj], acc[ii][jj]);
        }
        __syncthreads();
    }

    float4 bb = make_float4(0.f, 0.f, 0.f, 0.f);
    if (bias) bb = *(const float4*)&bias[j0 + tx * 4];
#pragma unroll
    for (int ii = 0; ii < 4; ii++) {
        float4 o;
        o.x = acc[ii][0] + bb.x;
        o.y = acc[ii][1] + bb.y;
        o.z = acc[ii][2] + bb.z;
        o.w = acc[ii][3] + bb.w;
        *(float4*)&C[(size_t)(i0 + ty * 4 + ii) * D_ + j0 + tx * 4] = o;
    }
}

// ---------------- position-weight kernel: g_w[n,g,m] = relu(emb.Wg + bg) + 1e-6 ----------------
__global__ void posw_kernel(const float* __restrict__ Wg, const float* __restrict__ bg) {
    __shared__ float wgs[G_][64];
    __shared__ float bgs[G_];
    const int tl = threadIdx.x;  // 256 threads
    for (int e = tl; e < G_ * 64; e += 256) wgs[e >> 6][e & 63] = Wg[e];
    if (tl < G_) bgs[tl] = bg[tl];
    __syncthreads();

    const int n = blockIdx.y;
    const int m = blockIdx.x * 256 + tl;

    const float cxn = g_boxA[n * 6 + 0], cyn = g_boxA[n * 6 + 1];
    const float iwn = g_boxA[n * 6 + 2], ihn = g_boxA[n * 6 + 3];
    const float lwn = g_boxA[n * 6 + 4], lhn = g_boxA[n * 6 + 5];
    const float cxm = g_boxB[m * 6 + 0], cym = g_boxB[m * 6 + 1];
    const float lwm = g_boxB[m * 6 + 4], lhm = g_boxB[m * 6 + 5];

    float pos[4];
    pos[0] = logf(fabsf(cxn - cxm) * iwn + 1e-3f);
    pos[1] = logf(fabsf(cyn - cym) * ihn + 1e-3f);
    pos[2] = lwn - lwm;
    pos[3] = lhn - lhm;

    // cf[f] = 100 / 1000^(f/8)
    const float cf[8] = {100.0f, 42.169650f, 17.782794f, 7.4989421f,
                         3.1622776f, 1.3335214f, 0.56234133f, 0.23713737f};

    float sum[G_];
#pragma unroll
    for (int g = 0; g < G_; g++) sum[g] = bgs[g];

#pragma unroll
    for (int d = 0; d < 4; d++) {
#pragma unroll
        for (int f = 0; f < 8; f++) {
            float s, c;
            sincosf(pos[d] * cf[f], &s, &c);
#pragma unroll
            for (int g = 0; g < G_; g++) {
                sum[g] = fmaf(s, wgs[g][d * 16 + f], sum[g]);
                sum[g] = fmaf(c, wgs[g][d * 16 + 8 + f], sum[g]);
            }
        }
    }

    const size_t base = (size_t)n * G_ * M_ + m;
#pragma unroll
    for (int g = 0; g < G_; g++)
        g_w[base + (size_t)g * M_] = fmaxf(sum[g], 0.0f) + 1e-6f;
}

// ---------------- fused attention: logits + online softmax + P.V ----------------
// grid (N/64, G), block (16,16). Per block: 64 n-rows, one group g.
__global__ void flash_kernel(const float* __restrict__ bv, float* __restrict__ out) {
    extern __shared__ float smem[];
    float(*qs)[68] = (float(*)[68])smem;                 // qs[d][r]
    float(*ks)[68] = (float(*)[68])(smem + 64 * 68);     // ks[d][c]
    float(*vs)[68] = (float(*)[68])(smem + 2 * 64 * 68); // vs[m][o]
    float(*ps)[68] = (float(*)[68])(smem + 3 * 64 * 68); // ps[m][r]

    const int tx = threadIdx.x, ty = threadIdx.y;
    const int tid = ty * 16 + tx;
    const int g = blockIdx.y;
    const int n0 = blockIdx.x * 64;

    // load q tile transposed: qs[d][r] = q[n0+r][g*64+d]
#pragma unroll
    for (int it = 0; it < 4; it++) {
        int r = tid >> 2;
        int d4 = ((tid & 3) + it * 4) * 4;
        float4 x = *(const float4*)&g_q[(size_t)(n0 + r) * D_ + g * 64 + d4];
        qs[d4 + 0][r] = x.x; qs[d4 + 1][r] = x.y; qs[d4 + 2][r] = x.z; qs[d4 + 3][r] = x.w;
    }

    float acc[4][4] = {};
    float mrun[4], lrun[4];
#pragma unroll
    for (int i = 0; i < 4; i++) { mrun[i] = -1e30f; lrun[i] = 0.0f; }

    for (int mt = 0; mt < 16; mt++) {
        const int m0 = mt * 64;
        __syncthreads();  // protect ks/vs/ps from previous iteration

#pragma unroll
        for (int it = 0; it < 4; it++) {
            int r = tid >> 2;
            int d4 = ((tid & 3) + it * 4) * 4;
            float4 x = *(const float4*)&g_k[(size_t)(m0 + r) * D_ + g * 64 + d4];
            ks[d4 + 0][r] = x.x; ks[d4 + 1][r] = x.y; ks[d4 + 2][r] = x.z; ks[d4 + 3][r] = x.w;
        }
#pragma unroll
        for (int it = 0; it < 4; it++) {
            int m = tid >> 2;
            int o4 = ((tid & 3) + it * 4) * 4;
            float4 x = *(const float4*)&g_v[(size_t)(m0 + m) * D_ + g * 64 + o4];
            *(float4*)&vs[m][o4] = x;
        }
        float wreg[4][4];
#pragma unroll
        for (int ii = 0; ii < 4; ii++) {
            float4 w4 = *(const float4*)&g_w[((size_t)(n0 + ty * 4 + ii) * G_ + g) * M_ + m0 + tx * 4];
            wreg[ii][0] = w4.x; wreg[ii][1] = w4.y; wreg[ii][2] = w4.z; wreg[ii][3] = w4.w;
        }
        __syncthreads();

        // S = q . k^T  (4x4 microtile)
        float s[4][4] = {};
#pragma unroll
        for (int d = 0; d < 64; d++) {
            float4 a = *(const float4*)&qs[d][ty * 4];
            float4 b = *(const float4*)&ks[d][tx * 4];
            float ar[4] = {a.x, a.y, a.z, a.w};
            float br[4] = {b.x, b.y, b.z, b.w};
#pragma unroll
            for (int ii = 0; ii < 4; ii++)
#pragma unroll
                for (int jj = 0; jj < 4; jj++)
                    s[ii][jj] = fmaf(ar[ii], br[jj], s[ii][jj]);
        }

        // scale + online softmax (p = w * exp(aff - max(aff)))
#pragma unroll
        for (int ii = 0; ii < 4; ii++) {
#pragma unroll
            for (int jj = 0; jj < 4; jj++) s[ii][jj] *= 0.125f;
            float rm = fmaxf(fmaxf(s[ii][0], s[ii][1]), fmaxf(s[ii][2], s[ii][3]));
#pragma unroll
            for (int off = 1; off < 16; off <<= 1)
                rm = fmaxf(rm, __shfl_xor_sync(0xffffffffu, rm, off, 16));
            float mn = fmaxf(mrun[ii], rm);
            float alpha = exp_nonpos(mrun[ii] - mn);
            mrun[ii] = mn;
            lrun[ii] *= alpha;
#pragma unroll
            for (int jj = 0; jj < 4; jj++) acc[ii][jj] *= alpha;
            float psum = 0.0f;
#pragma unroll
            for (int jj = 0; jj < 4; jj++) {
                float p = wreg[ii][jj] * exp_nonpos(s[ii][jj] - mn);
                s[ii][jj] = p;
                psum += p;
            }
            lrun[ii] += psum;
        }

        // stage P transposed: ps[m][r]
#pragma unroll
        for (int jj = 0; jj < 4; jj++) {
            float4 pv = make_float4(s[0][jj], s[1][jj], s[2][jj], s[3][jj]);
            *(float4*)&ps[tx * 4 + jj][ty * 4] = pv;
        }
        __syncthreads();

        // acc += P . V
#pragma unroll
        for (int m = 0; m < 64; m++) {
            float4 p4 = *(const float4*)&ps[m][ty * 4];
            float4 v4 = *(const float4*)&vs[m][tx * 4];
            float pr[4] = {p4.x, p4.y, p4.z, p4.w};
            float vr[4] = {v4.x, v4.y, v4.z, v4.w};
#pragma unroll
            for (int ii = 0; ii < 4; ii++)
#pragma unroll
                for (int jj = 0; jj < 4; jj++)
                    acc[ii][jj] = fmaf(pr[ii], vr[jj], acc[ii][jj]);
        }
    }

    // epilogue: normalize, add bv, store
    const int col = g * 64 + tx * 4;
    float4 b4 = *(const float4*)&bv[col];
#pragma unroll
    for (int ii = 0; ii < 4; ii++) {
        float l = lrun[ii];
#pragma unroll
        for (int off = 1; off < 16; off <<= 1)
            l += __shfl_xor_sync(0xffffffffu, l, off, 16);
        float inv = 1.0f / l;
        float4 o;
        o.x = fmaf(acc[ii][0], inv, b4.x);
        o.y = fmaf(acc[ii][1], inv, b4.y);
        o.z = fmaf(acc[ii][2], inv, b4.z);
        o.w = fmaf(acc[ii][3], inv, b4.w);
        *(float4*)&out[(size_t)(n0 + ty * 4 + ii) * D_ + col] = o;
    }
}

// ---------------- host launcher ----------------
extern "C" void kernel_launch(void* const* d_in, const int* in_sizes, int n_in,
                              void* d_out, int out_size) {
    const float* roi   = (const float*)d_in[0];
    const float* ref   = (const float*)d_in[1];
    const float* rois1 = (const float*)d_in[2];
    const float* rois2 = (const float*)d_in[3];
    const float* Wq    = (const float*)d_in[4];
    const float* bq    = (const float*)d_in[5];
    const float* Wk    = (const float*)d_in[6];
    const float* bk    = (const float*)d_in[7];
    const float* Wg    = (const float*)d_in[8];
    const float* bg    = (const float*)d_in[9];
    const float* Wv    = (const float*)d_in[10];
    const float* bv    = (const float*)d_in[11];
    float* out = (float*)d_out;

    float *qp, *kp, *vp;
    cudaGetSymbolAddress((void**)&qp, g_q);
    cudaGetSymbolAddress((void**)&kp, g_k);
    cudaGetSymbolAddress((void**)&vp, g_v);

    const int FLASH_SMEM = 4 * 64 * 68 * (int)sizeof(float);  // 69632 B
    cudaFuncSetAttribute(flash_kernel, cudaFuncAttributeMaxDynamicSharedMemorySize, FLASH_SMEM);

    dim3 blk(16, 16), grd(16, 16);

    box_prep<<<4, 256>>>(rois1, rois2);
    sgemm_bias<false><<<grd, blk>>>(roi, Wq, bq, qp);
    sgemm_bias<false><<<grd, blk>>>(ref, Wk, bk, kp);
    sgemm_bias<true><<<grd, blk>>>(ref, Wv, nullptr, vp);   // V[g] = ref @ Wv[g]^T
    posw_kernel<<<dim3(4, 1024), 256>>>(Wg, bg);
    flash_kernel<<<dim3(16, 16), dim3(16, 16), FLASH_SMEM>>>(bv, out);
}

// round 2
// speedup vs baseline: 1.2048x; 1.2048x over previous
#include <cuda_runtime.h>
#include <math.h>
#include <stdint.h>

#define N_ 1024
#define M_ 1024
#define D_ 1024
#define G_ 16
#define DG_ 64

// ---------------- scratch ----------------
__device__ float g_q[(size_t)N_ * D_];
__device__ float g_k[(size_t)M_ * D_];
__device__ float g_v[(size_t)M_ * D_];          // V[m][g*64+o]
__device__ float g_w[(size_t)N_ * G_ * M_];     // (N, G, M)
__device__ float g_boxA[N_ * 4];                // cx, cy, 1/w, 1/h
__device__ float g_boxB[M_ * 4];
__device__ float g_trigA[N_ * 32];              // [n][f]: sw8, cw8, sh8, ch8
__device__ float g_trigBt[32 * M_];             // transposed: [f][m]

__device__ __forceinline__ float fast_exp(float x) {
    float t = x * 1.4426950408889634f;
    t = fminf(fmaxf(t, -120.0f), 120.0f);
    float fi = floorf(t);
    float f = t - fi;
    float p = 1.5403530393e-4f;
    p = fmaf(p, f, 1.3333558146e-3f);
    p = fmaf(p, f, 9.6181291076e-3f);
    p = fmaf(p, f, 5.5504108664e-2f);
    p = fmaf(p, f, 2.4022650696e-1f);
    p = fmaf(p, f, 6.9314718056e-1f);
    p = fmaf(p, f, 1.0f);
    return p * __int_as_float(((int)fi + 127) << 23);
}

__constant__ float c_cf[8] = {100.0f, 42.169650f, 17.782794f, 7.4989421f,
                              3.1622776f, 1.3335214f, 0.56234133f, 0.23713737f};

// ---------------- box prep + per-box trig ----------------
__global__ void box_prep(const float* __restrict__ rois1, const float* __restrict__ rois2) {
    int i = blockIdx.x * blockDim.x + threadIdx.x;
    if (i >= N_) return;
    {
        float xmin = rois1[i * 4 + 0], ymin = rois1[i * 4 + 1];
        float xmax = rois1[i * 4 + 2], ymax = rois1[i * 4 + 3];
        float w = xmax - xmin + 1.0f, h = ymax - ymin + 1.0f;
        g_boxA[i * 4 + 0] = 0.5f * (xmin + xmax);
        g_boxA[i * 4 + 1] = 0.5f * (ymin + ymax);
        g_boxA[i * 4 + 2] = 1.0f / w;
        g_boxA[i * 4 + 3] = 1.0f / h;
        float lw = logf(w), lh = logf(h);
#pragma unroll
        for (int f = 0; f < 8; f++) {
            float s, c;
            sincosf(lw * c_cf[f], &s, &c);
            g_trigA[i * 32 + f] = s;
            g_trigA[i * 32 + 8 + f] = c;
            sincosf(lh * c_cf[f], &s, &c);
            g_trigA[i * 32 + 16 + f] = s;
            g_trigA[i * 32 + 24 + f] = c;
        }
    }
    {
        float xmin = rois2[i * 4 + 0], ymin = rois2[i * 4 + 1];
        float xmax = rois2[i * 4 + 2], ymax = rois2[i * 4 + 3];
        float w = xmax - xmin + 1.0f, h = ymax - ymin + 1.0f;
        g_boxB[i * 4 + 0] = 0.5f * (xmin + xmax);
        g_boxB[i * 4 + 1] = 0.5f * (ymin + ymax);
        g_boxB[i * 4 + 2] = 1.0f / w;
        g_boxB[i * 4 + 3] = 1.0f / h;
        float lw = logf(w), lh = logf(h);
#pragma unroll
        for (int f = 0; f < 8; f++) {
            float s, c;
            sincosf(lw * c_cf[f], &s, &c);
            g_trigBt[f * M_ + i] = s;
            g_trigBt[(8 + f) * M_ + i] = c;
            sincosf(lh * c_cf[f], &s, &c);
            g_trigBt[(16 + f) * M_ + i] = s;
            g_trigBt[(24 + f) * M_ + i] = c;
        }
    }
}

// ---------------- fused triple SGEMM: 128x64 tiles, 8x4 micro, reg-pipelined ----------------
__global__ __launch_bounds__(256) void gemm3(
    const float* __restrict__ roi, const float* __restrict__ ref,
    const float* __restrict__ Wq, const float* __restrict__ bq,
    const float* __restrict__ Wk, const float* __restrict__ bk,
    const float* __restrict__ Wv) {
    __shared__ float As[16][132];
    __shared__ float Bs[16][68];

    const int t = threadIdx.x;
    const int tx = t & 15, ty = t >> 4;
    const int i0 = blockIdx.y * 128, j0 = blockIdx.x * 64;
    const int z = blockIdx.z;

    const float* A;
    const float* B;
    const float* bias;
    float* C;
    bool bt;
    if (z == 0)      { A = roi; B = Wq; bias = bq; C = g_q; bt = false; }
    else if (z == 1) { A = ref; B = Wk; bias = bk; C = g_k; bt = false; }
    else             { A = ref; B = Wv; bias = nullptr; C = g_v; bt = true; }

    // loader indices
    const int ar = t >> 2;               // 0..63 (+64 for second)
    const int ak4 = (t & 3) << 2;
    const int bkr = t >> 4;              // BT=false: k row 0..15
    const int bj4 = (t & 15) << 2;
    const int bjr = t >> 2;              // BT=true: j row 0..63
    const int bk4 = (t & 3) << 2;

    float4 a0g, a1g, bg4;

    auto loadG = [&](int kt) {
        a0g = *(const float4*)&A[(size_t)(i0 + ar) * D_ + kt + ak4];
        a1g = *(const float4*)&A[(size_t)(i0 + ar + 64) * D_ + kt + ak4];
        if (!bt) bg4 = *(const float4*)&B[(size_t)(kt + bkr) * D_ + j0 + bj4];
        else     bg4 = *(const float4*)&B[(size_t)(j0 + bjr) * D_ + kt + bk4];
    };
    auto storeS = [&]() {
        As[ak4 + 0][ar] = a0g.x; As[ak4 + 1][ar] = a0g.y;
        As[ak4 + 2][ar] = a0g.z; As[ak4 + 3][ar] = a0g.w;
        As[ak4 + 0][ar + 64] = a1g.x; As[ak4 + 1][ar + 64] = a1g.y;
        As[ak4 + 2][ar + 64] = a1g.z; As[ak4 + 3][ar + 64] = a1g.w;
        if (!bt) *(float4*)&Bs[bkr][bj4] = bg4;
        else {
            Bs[bk4 + 0][bjr] = bg4.x; Bs[bk4 + 1][bjr] = bg4.y;
            Bs[bk4 + 2][bjr] = bg4.z; Bs[bk4 + 3][bjr] = bg4.w;
        }
    };

    float acc[8][4] = {};

    loadG(0);
    storeS();
    __syncthreads();

    for (int kt = 16; kt <= D_; kt += 16) {
        const bool more = (kt < D_);
        if (more) loadG(kt);
#pragma unroll
        for (int k = 0; k < 16; k++) {
            float4 a0 = *(const float4*)&As[k][ty * 8];
            float4 a1 = *(const float4*)&As[k][ty * 8 + 4];
            float4 b = *(const float4*)&Bs[k][tx * 4];
            float ar8[8] = {a0.x, a0.y, a0.z, a0.w, a1.x, a1.y, a1.z, a1.w};
            float br[4] = {b.x, b.y, b.z, b.w};
#pragma unroll
            for (int ii = 0; ii < 8; ii++)
#pragma unroll
                for (int jj = 0; jj < 4; jj++)
                    acc[ii][jj] = fmaf(ar8[ii], br[jj], acc[ii][jj]);
        }
        if (!more) break;
        __syncthreads();
        storeS();
        __syncthreads();
    }

    float4 bb = make_float4(0.f, 0.f, 0.f, 0.f);
    if (bias) bb = *(const float4*)&bias[j0 + tx * 4];
#pragma unroll
    for (int ii = 0; ii < 8; ii++) {
        float4 o;
        o.x = acc[ii][0] + bb.x;
        o.y = acc[ii][1] + bb.y;
        o.z = acc[ii][2] + bb.z;
        o.w = acc[ii][3] + bb.w;
        *(float4*)&C[(size_t)(i0 + ty * 8 + ii) * D_ + j0 + tx * 4] = o;
    }
}

// ---------------- position-weight kernel ----------------
__global__ __launch_bounds__(256) void posw_kernel(const float* __restrict__ Wg,
                                                   const float* __restrict__ bg) {
    __shared__ float4 wgs4[G_][16];
    __shared__ float bgs[G_];
    const int t = threadIdx.x;
    wgs4[t >> 4][t & 15] = ((const float4*)Wg)[t];
    if (t < G_) bgs[t] = bg[t];
    __syncthreads();

    const int n = blockIdx.y;
    const int m = blockIdx.x * 256 + t;

    const float4 bn = *(const float4*)&g_boxA[n * 4];
    const float4 bm = *(const float4*)&g_boxB[m * 4];

    float emb[64];

    // separable dims (dw, dh) first
#pragma unroll
    for (int f = 0; f < 8; f++) {
        float snf = g_trigA[n * 32 + f];
        float cnf = g_trigA[n * 32 + 8 + f];
        float smf = g_trigBt[f * M_ + m];
        float cmf = g_trigBt[(8 + f) * M_ + m];
        emb[32 + f] = snf * cmf - cnf * smf;
        emb[40 + f] = fmaf(cnf, cmf, snf * smf);
    }
#pragma unroll
    for (int f = 0; f < 8; f++) {
        float snf = g_trigA[n * 32 + 16 + f];
        float cnf = g_trigA[n * 32 + 24 + f];
        float smf = g_trigBt[(16 + f) * M_ + m];
        float cmf = g_trigBt[(24 + f) * M_ + m];
        emb[48 + f] = snf * cmf - cnf * smf;
        emb[56 + f] = fmaf(cnf, cmf, snf * smf);
    }

    // non-separable dims (dx, dy)
    float px = logf(fabsf(bn.x - bm.x) * bn.z + 1e-3f);
    float py = logf(fabsf(bn.y - bm.y) * bn.w + 1e-3f);
#pragma unroll
    for (int f = 0; f < 8; f++) {
        float s, c;
        sincosf(px * c_cf[f], &s, &c);
        emb[f] = s; emb[8 + f] = c;
        sincosf(py * c_cf[f], &s, &c);
        emb[16 + f] = s; emb[24 + f] = c;
    }

    const size_t base = ((size_t)n * G_) * M_ + m;
#pragma unroll
    for (int g = 0; g < G_; g++) {
        float s = bgs[g];
#pragma unroll
        for (int e4 = 0; e4 < 16; e4++) {
            float4 w = wgs4[g][e4];
            s = fmaf(w.x, emb[e4 * 4 + 0], s);
            s = fmaf(w.y, emb[e4 * 4 + 1], s);
            s = fmaf(w.z, emb[e4 * 4 + 2], s);
            s = fmaf(w.w, emb[e4 * 4 + 3], s);
        }
        g_w[base + (size_t)g * M_] = fmaxf(s, 0.0f) + 1e-6f;
    }
}

// ---------------- fused attention: 128 n-rows x 64 m-cols tiles, 8x4 micro ----------------
// grid (N/128, G) = (8, 16), block 256 threads.
__global__ __launch_bounds__(256, 2) void flash_kernel(const float* __restrict__ bv,
                                                       float* __restrict__ out) {
    extern __shared__ float smem[];
    float(*qs)[132] = (float(*)[132])smem;                      // [64][132]  qs[d][r]
    float(*ks)[68] = (float(*)[68])(smem + 64 * 132);           // [64][68]   ks[d][c]
    float(*vs)[68] = (float(*)[68])(smem + 64 * 132 + 64 * 68); // [64][68]   vs[m][o]
    float(*ps)[68] = (float(*)[68])(smem + 64 * 132 + 2 * 64 * 68); // [128][68] ps[r][m]

    const int t = threadIdx.x;
    const int tx = t & 15, ty = t >> 4;
    const int g = blockIdx.y;
    const int n0 = blockIdx.x * 128;

    // q tile: 128 rows x 64 d, transposed -> qs[d][r]
#pragma unroll
    for (int it = 0; it < 8; it++) {
        int idx = it * 256 + t;
        int r = idx >> 4;
        int d4 = (idx & 15) << 2;
        float4 x = *(const float4*)&g_q[(size_t)(n0 + r) * D_ + g * 64 + d4];
        qs[d4 + 0][r] = x.x; qs[d4 + 1][r] = x.y; qs[d4 + 2][r] = x.z; qs[d4 + 3][r] = x.w;
    }

    float acc[8][4] = {};
    float lrun[8] = {};

    for (int mt = 0; mt < 16; mt++) {
        const int m0 = mt * 64;
        __syncthreads();
#pragma unroll
        for (int it = 0; it < 4; it++) {
            int idx = it * 256 + t;
            int r = idx >> 4;
            int d4 = (idx & 15) << 2;
            float4 x = *(const float4*)&g_k[(size_t)(m0 + r) * D_ + g * 64 + d4];
            ks[d4 + 0][r] = x.x; ks[d4 + 1][r] = x.y; ks[d4 + 2][r] = x.z; ks[d4 + 3][r] = x.w;
        }
#pragma unroll
        for (int it = 0; it < 4; it++) {
            int idx = it * 256 + t;
            int r = idx >> 4;
            int o4 = (idx & 15) << 2;
            *(float4*)&vs[r][o4] = *(const float4*)&g_v[(size_t)(m0 + r) * D_ + g * 64 + o4];
        }
        __syncthreads();

        // S = q.k^T
        float s[8][4] = {};
#pragma unroll
        for (int d = 0; d < 64; d++) {
            float4 a0 = *(const float4*)&qs[d][ty * 8];
            float4 a1 = *(const float4*)&qs[d][ty * 8 + 4];
            float4 b = *(const float4*)&ks[d][tx * 4];
            float ar8[8] = {a0.x, a0.y, a0.z, a0.w, a1.x, a1.y, a1.z, a1.w};
            float br[4] = {b.x, b.y, b.z, b.w};
#pragma unroll
            for (int ii = 0; ii < 8; ii++)
#pragma unroll
                for (int jj = 0; jj < 4; jj++)
                    s[ii][jj] = fmaf(ar8[ii], br[jj], s[ii][jj]);
        }

        // p = w * exp(aff); no max-subtraction needed (|aff| small, fp32 safe)
#pragma unroll
        for (int ii = 0; ii < 8; ii++) {
            const int n = n0 + ty * 8 + ii;
            float4 w4 = *(const float4*)&g_w[((size_t)n * G_ + g) * M_ + m0 + tx * 4];
            float p0 = w4.x * fast_exp(s[ii][0] * 0.125f);
            float p1 = w4.y * fast_exp(s[ii][1] * 0.125f);
            float p2 = w4.z * fast_exp(s[ii][2] * 0.125f);
            float p3 = w4.w * fast_exp(s[ii][3] * 0.125f);
            lrun[ii] += (p0 + p1) + (p2 + p3);
            float4 pv = make_float4(p0, p1, p2, p3);
            *(float4*)&ps[ty * 8 + ii][tx * 4] = pv;
        }
        __syncthreads();

        // acc += P.V
#pragma unroll
        for (int m4 = 0; m4 < 64; m4 += 4) {
            float4 pr[8];
#pragma unroll
            for (int ii = 0; ii < 8; ii++) pr[ii] = *(const float4*)&ps[ty * 8 + ii][m4];
#pragma unroll
            for (int mm = 0; mm < 4; mm++) {
                float4 v4 = *(const float4*)&vs[m4 + mm][tx * 4];
                float vr[4] = {v4.x, v4.y, v4.z, v4.w};
#pragma unroll
                for (int ii = 0; ii < 8; ii++) {
                    float pe = (mm == 0) ? pr[ii].x : (mm == 1) ? pr[ii].y : (mm == 2) ? pr[ii].z : pr[ii].w;
#pragma unroll
                    for (int jj = 0; jj < 4; jj++)
                        acc[ii][jj] = fmaf(pe, vr[jj], acc[ii][jj]);
                }
            }
        }
    }

    // epilogue
    const int col = g * 64 + tx * 4;
    const float4 b4 = *(const float4*)&bv[col];
#pragma unroll
    for (int ii = 0; ii < 8; ii++) {
        float l = lrun[ii];
#pragma unroll
        for (int off = 1; off < 16; off <<= 1)
            l += __shfl_xor_sync(0xffffffffu, l, off, 16);
        float inv = 1.0f / l;
        float4 o;
        o.x = fmaf(acc[ii][0], inv, b4.x);
        o.y = fmaf(acc[ii][1], inv, b4.y);
        o.z = fmaf(acc[ii][2], inv, b4.z);
        o.w = fmaf(acc[ii][3], inv, b4.w);
        *(float4*)&out[(size_t)(n0 + ty * 8 + ii) * D_ + col] = o;
    }
}

// ---------------- host launcher ----------------
extern "C" void kernel_launch(void* const* d_in, const int* in_sizes, int n_in,
                              void* d_out, int out_size) {
    const float* roi   = (const float*)d_in[0];
    const float* ref   = (const float*)d_in[1];
    const float* rois1 = (const float*)d_in[2];
    const float* rois2 = (const float*)d_in[3];
    const float* Wq    = (const float*)d_in[4];
    const float* bq    = (const float*)d_in[5];
    const float* Wk    = (const float*)d_in[6];
    const float* bk    = (const float*)d_in[7];
    const float* Wg    = (const float*)d_in[8];
    const float* bg    = (const float*)d_in[9];
    const float* Wv    = (const float*)d_in[10];
    const float* bv    = (const float*)d_in[11];
    float* out = (float*)d_out;

    const int FLASH_SMEM = (64 * 132 + 2 * 64 * 68 + 128 * 68) * (int)sizeof(float);
    static bool attr_set = false;
    if (!attr_set) {
        cudaFuncSetAttribute(flash_kernel, cudaFuncAttributeMaxDynamicSharedMemorySize, FLASH_SMEM);
        attr_set = true;
    }

    box_prep<<<4, 256>>>(rois1, rois2);
    gemm3<<<dim3(16, 8, 3), 256>>>(roi, ref, Wq, bq, Wk, bk, Wv);
    posw_kernel<<<dim3(4, 1024), 256>>>(Wg, bg);
    flash_kernel<<<dim3(8, 16), 256, FLASH_SMEM>>>(bv, out);
}

// round 4
// speedup vs baseline: 1.2271x; 1.0185x over previous
#include <cuda_runtime.h>
#include <math.h>
#include <stdint.h>

#define N_ 1024
#define M_ 1024
#define D_ 1024
#define G_ 16
#define DG_ 64

// ---------------- scratch ----------------
__device__ float g_q[(size_t)N_ * D_];
__device__ float g_k[(size_t)M_ * D_];
__device__ float g_v[(size_t)M_ * D_];           // V[m][g*64+o]
__device__ float g_w[(size_t)N_ * G_ * M_];      // (N, G, M)
__device__ float g_boxA[N_ * 4];
__device__ float g_boxB[M_ * 4];
__device__ float g_trigA[N_ * 32];
__device__ float g_trigBt[32 * M_];
__device__ float g_pacc[2][(size_t)N_ * D_];     // partial PV accumulators
__device__ float g_pl[2][(size_t)N_ * G_];       // partial softmax denominators

__device__ __forceinline__ float fast_exp(float x) {
    float t = x * 1.4426950408889634f;
    t = fminf(fmaxf(t, -120.0f), 120.0f);
    float fi = floorf(t);
    float f = t - fi;
    float p = 1.5403530393e-4f;
    p = fmaf(p, f, 1.3333558146e-3f);
    p = fmaf(p, f, 9.6181291076e-3f);
    p = fmaf(p, f, 5.5504108664e-2f);
    p = fmaf(p, f, 2.4022650696e-1f);
    p = fmaf(p, f, 6.9314718056e-1f);
    p = fmaf(p, f, 1.0f);
    return p * __int_as_float(((int)fi + 127) << 23);
}

__constant__ float c_cf[8] = {100.0f, 42.169650f, 17.782794f, 7.4989421f,
                              3.1622776f, 1.3335214f, 0.56234133f, 0.23713737f};

// ---------------- box prep + per-box trig (accurate; only 2048 boxes) ----------------
__global__ void box_prep(const float* __restrict__ rois1, const float* __restrict__ rois2) {
    int i = blockIdx.x * blockDim.x + threadIdx.x;
    if (i >= N_) return;
    {
        float xmin = rois1[i * 4 + 0], ymin = rois1[i * 4 + 1];
        float xmax = rois1[i * 4 + 2], ymax = rois1[i * 4 + 3];
        float w = xmax - xmin + 1.0f, h = ymax - ymin + 1.0f;
        g_boxA[i * 4 + 0] = 0.5f * (xmin + xmax);
        g_boxA[i * 4 + 1] = 0.5f * (ymin + ymax);
        g_boxA[i * 4 + 2] = 1.0f / w;
        g_boxA[i * 4 + 3] = 1.0f / h;
        float lw = logf(w), lh = logf(h);
#pragma unroll
        for (int f = 0; f < 8; f++) {
            float s, c;
            sincosf(lw * c_cf[f], &s, &c);
            g_trigA[i * 32 + f] = s;
            g_trigA[i * 32 + 8 + f] = c;
            sincosf(lh * c_cf[f], &s, &c);
            g_trigA[i * 32 + 16 + f] = s;
            g_trigA[i * 32 + 24 + f] = c;
        }
    }
    {
        float xmin = rois2[i * 4 + 0], ymin = rois2[i * 4 + 1];
        float xmax = rois2[i * 4 + 2], ymax = rois2[i * 4 + 3];
        float w = xmax - xmin + 1.0f, h = ymax - ymin + 1.0f;
        g_boxB[i * 4 + 0] = 0.5f * (xmin + xmax);
        g_boxB[i * 4 + 1] = 0.5f * (ymin + ymax);
        g_boxB[i * 4 + 2] = 1.0f / w;
        g_boxB[i * 4 + 3] = 1.0f / h;
        float lw = logf(w), lh = logf(h);
#pragma unroll
        for (int f = 0; f < 8; f++) {
            float s, c;
            sincosf(lw * c_cf[f], &s, &c);
            g_trigBt[f * M_ + i] = s;
            g_trigBt[(8 + f) * M_ + i] = c;
            sincosf(lh * c_cf[f], &s, &c);
            g_trigBt[(16 + f) * M_ + i] = s;
            g_trigBt[(24 + f) * M_ + i] = c;
        }
    }
}

// ---------------- fused triple SGEMM: 64x128 tiles, 8x8 micro, 128 threads ----------------
__global__ __launch_bounds__(128) void gemm3(
    const float* __restrict__ roi, const float* __restrict__ ref,
    const float* __restrict__ Wq, const float* __restrict__ bq,
    const float* __restrict__ Wk, const float* __restrict__ bk,
    const float* __restrict__ Wv) {
    __shared__ float As[16][68];    // As[k][i], 64 rows
    __shared__ float Bs[16][132];   // Bs[k][j], 128 cols

    const int t = threadIdx.x;
    const int tx = t & 15, ty = t >> 4;
    const int i0 = blockIdx.y * 64, j0 = blockIdx.x * 128;
    const int z = blockIdx.z;

    const float* A;
    const float* B;
    const float* bias;
    float* C;
    bool bt;
    if (z == 0)      { A = roi; B = Wq; bias = bq; C = g_q; bt = false; }
    else if (z == 1) { A = ref; B = Wk; bias = bk; C = g_k; bt = false; }
    else             { A = ref; B = Wv; bias = nullptr; C = g_v; bt = true; }

    const int ar = t >> 2;               // 0..31, +32
    const int ak4 = (t & 3) << 2;
    const int bk1 = t >> 4;              // 0..7, +8
    const int bj8 = (t & 15) << 3;

    float4 a0g, a1g, b0g, b1g, b2g, b3g;

    auto loadG = [&](int kt) {
        a0g = *(const float4*)&A[(size_t)(i0 + ar) * D_ + kt + ak4];
        a1g = *(const float4*)&A[(size_t)(i0 + ar + 32) * D_ + kt + ak4];
        if (!bt) {
            b0g = *(const float4*)&B[(size_t)(kt + bk1) * D_ + j0 + bj8];
            b1g = *(const float4*)&B[(size_t)(kt + bk1) * D_ + j0 + bj8 + 4];
            b2g = *(const float4*)&B[(size_t)(kt + bk1 + 8) * D_ + j0 + bj8];
            b3g = *(const float4*)&B[(size_t)(kt + bk1 + 8) * D_ + j0 + bj8 + 4];
        } else {
            const int j = t >> 2;
            b0g = *(const float4*)&B[(size_t)(j0 + j) * D_ + kt + ak4];
            b1g = *(const float4*)&B[(size_t)(j0 + j + 32) * D_ + kt + ak4];
            b2g = *(const float4*)&B[(size_t)(j0 + j + 64) * D_ + kt + ak4];
            b3g = *(const float4*)&B[(size_t)(j0 + j + 96) * D_ + kt + ak4];
        }
    };
    auto storeS = [&]() {
        As[ak4 + 0][ar] = a0g.x; As[ak4 + 1][ar] = a0g.y;
        As[ak4 + 2][ar] = a0g.z; As[ak4 + 3][ar] = a0g.w;
        As[ak4 + 0][ar + 32] = a1g.x; As[ak4 + 1][ar + 32] = a1g.y;
        As[ak4 + 2][ar + 32] = a1g.z; As[ak4 + 3][ar + 32] = a1g.w;
        if (!bt) {
            *(float4*)&Bs[bk1][bj8] = b0g;
            *(float4*)&Bs[bk1][bj8 + 4] = b1g;
            *(float4*)&Bs[bk1 + 8][bj8] = b2g;
            *(float4*)&Bs[bk1 + 8][bj8 + 4] = b3g;
        } else {
            const int j = t >> 2;
            Bs[ak4 + 0][j] = b0g.x; Bs[ak4 + 1][j] = b0g.y;
            Bs[ak4 + 2][j] = b0g.z; Bs[ak4 + 3][j] = b0g.w;
            Bs[ak4 + 0][j + 32] = b1g.x; Bs[ak4 + 1][j + 32] = b1g.y;
            Bs[ak4 + 2][j + 32] = b1g.z; Bs[ak4 + 3][j + 32] = b1g.w;
            Bs[ak4 + 0][j + 64] = b2g.x; Bs[ak4 + 1][j + 64] = b2g.y;
            Bs[ak4 + 2][j + 64] = b2g.z; Bs[ak4 + 3][j + 64] = b2g.w;
            Bs[ak4 + 0][j + 96] = b3g.x; Bs[ak4 + 1][j + 96] = b3g.y;
            Bs[ak4 + 2][j + 96] = b3g.z; Bs[ak4 + 3][j + 96] = b3g.w;
        }
    };

    float acc[8][8] = {};

    loadG(0);
    storeS();
    __syncthreads();

    for (int kt = 16; kt <= D_; kt += 16) {
        const bool more = (kt < D_);
        if (more) loadG(kt);
#pragma unroll
        for (int k = 0; k < 16; k++) {
            float4 a0 = *(const float4*)&As[k][ty * 8];
            float4 a1 = *(const float4*)&As[k][ty * 8 + 4];
            float4 b0 = *(const float4*)&Bs[k][tx * 8];
            float4 b1 = *(const float4*)&Bs[k][tx * 8 + 4];
            float ar8[8] = {a0.x, a0.y, a0.z, a0.w, a1.x, a1.y, a1.z, a1.w};
            float br8[8] = {b0.x, b0.y, b0.z, b0.w, b1.x, b1.y, b1.z, b1.w};
#pragma unroll
            for (int ii = 0; ii < 8; ii++)
#pragma unroll
                for (int jj = 0; jj < 8; jj++)
                    acc[ii][jj] = fmaf(ar8[ii], br8[jj], acc[ii][jj]);
        }
        if (!more) break;
        __syncthreads();
        storeS();
        __syncthreads();
    }

    float4 bb0 = make_float4(0.f, 0.f, 0.f, 0.f), bb1 = bb0;
    if (bias) {
        bb0 = *(const float4*)&bias[j0 + tx * 8];
        bb1 = *(const float4*)&bias[j0 + tx * 8 + 4];
    }
#pragma unroll
    for (int ii = 0; ii < 8; ii++) {
        float4 o0, o1;
        o0.x = acc[ii][0] + bb0.x; o0.y = acc[ii][1] + bb0.y;
        o0.z = acc[ii][2] + bb0.z; o0.w = acc[ii][3] + bb0.w;
        o1.x = acc[ii][4] + bb1.x; o1.y = acc[ii][5] + bb1.y;
        o1.z = acc[ii][6] + bb1.z; o1.w = acc[ii][7] + bb1.w;
        *(float4*)&C[(size_t)(i0 + ty * 8 + ii) * D_ + j0 + tx * 8] = o0;
        *(float4*)&C[(size_t)(i0 + ty * 8 + ii) * D_ + j0 + tx * 8 + 4] = o1;
    }
}

// ---------------- position-weight kernel (fast trig) ----------------
__global__ __launch_bounds__(256) void posw_kernel(const float* __restrict__ Wg,
                                                   const float* __restrict__ bg) {
    __shared__ float4 wgs4[G_][16];
    __shared__ float bgs[G_];
    const int t = threadIdx.x;
    wgs4[t >> 4][t & 15] = ((const float4*)Wg)[t];
    if (t < G_) bgs[t] = bg[t];
    __syncthreads();

    const int n = blockIdx.y;
    const int m = blockIdx.x * 256 + t;

    const float4 bn = *(const float4*)&g_boxA[n * 4];
    const float4 bm = *(const float4*)&g_boxB[m * 4];

    float emb[64];

#pragma unroll
    for (int f = 0; f < 8; f++) {
        float snf = g_trigA[n * 32 + f];
        float cnf = g_trigA[n * 32 + 8 + f];
        float smf = g_trigBt[f * M_ + m];
        float cmf = g_trigBt[(8 + f) * M_ + m];
        emb[32 + f] = snf * cmf - cnf * smf;
        emb[40 + f] = fmaf(cnf, cmf, snf * smf);
    }
#pragma unroll
    for (int f = 0; f < 8; f++) {
        float snf = g_trigA[n * 32 + 16 + f];
        float cnf = g_trigA[n * 32 + 24 + f];
        float smf = g_trigBt[(16 + f) * M_ + m];
        float cmf = g_trigBt[(24 + f) * M_ + m];
        emb[48 + f] = snf * cmf - cnf * smf;
        emb[56 + f] = fmaf(cnf, cmf, snf * smf);
    }

    float px = __logf(fabsf(bn.x - bm.x) * bn.z + 1e-3f);
    float py = __logf(fabsf(bn.y - bm.y) * bn.w + 1e-3f);
#pragma unroll
    for (int f = 0; f < 8; f++) {
        float s, c;
        __sincosf(px * c_cf[f], &s, &c);
        emb[f] = s; emb[8 + f] = c;
        __sincosf(py * c_cf[f], &s, &c);
        emb[16 + f] = s; emb[24 + f] = c;
    }

    const size_t base = ((size_t)n * G_) * M_ + m;
#pragma unroll
    for (int g = 0; g < G_; g++) {
        float s = bgs[g];
#pragma unroll
        for (int e4 = 0; e4 < 16; e4++) {
            float4 w = wgs4[g][e4];
            s = fmaf(w.x, emb[e4 * 4 + 0], s);
            s = fmaf(w.y, emb[e4 * 4 + 1], s);
            s = fmaf(w.z, emb[e4 * 4 + 2], s);
            s = fmaf(w.w, emb[e4 * 4 + 3], s);
        }
        g_w[base + (size_t)g * M_] = fmaxf(s, 0.0f) + 1e-6f;
    }
}

// ---------------- fused attention: 64x64 tiles, M split in 2, 128 threads ----------------
// grid (16 n-tiles, 16 g, 2 halves), block 128 = 16(tx) x 8(ty), micro 8x4.
__global__ __launch_bounds__(128, 4) void flash_kernel() {
    extern __shared__ float smem[];
    float(*qs)[68] = (float(*)[68])smem;                 // [64][68]  qs[d][r]
    float(*ks)[68] = (float(*)[68])(smem + 64 * 68);     // [64][68]  ks[d][c]  (aliased by ps)
    float(*vs)[68] = (float(*)[68])(smem + 2 * 64 * 68); // [64][68]  vs[m][o]
    float(*ps)[68] = ks;                                 // [64][68]  ps[r][m]

    const int t = threadIdx.x;
    const int tx = t & 15, ty = t >> 4;
    const int g = blockIdx.y;
    const int n0 = blockIdx.x * 64;
    const int z = blockIdx.z;

    // q tile: 64x64 transposed -> qs[d][r]; 1024 float4, 8 per thread
#pragma unroll
    for (int it = 0; it < 8; it++) {
        int idx = it * 128 + t;
        int r = idx >> 4;
        int d4 = (idx & 15) << 2;
        float4 x = *(const float4*)&g_q[(size_t)(n0 + r) * D_ + g * 64 + d4];
        qs[d4 + 0][r] = x.x; qs[d4 + 1][r] = x.y; qs[d4 + 2][r] = x.z; qs[d4 + 3][r] = x.w;
    }

    float acc[8][4] = {};
    float lrun[8] = {};

    for (int mt = z * 8; mt < z * 8 + 8; mt++) {
        const int m0 = mt * 64;
        __syncthreads();  // prior iter's ps/vs readers done (also covers qs stores, iter 0)
        // K tile: 64x64 -> 1024 float4, 8 per thread  (FIX: was 4 iterations)
#pragma unroll
        for (int it = 0; it < 8; it++) {
            int idx = it * 128 + t;
            int r = idx >> 4;
            int d4 = (idx & 15) << 2;
            float4 x = *(const float4*)&g_k[(size_t)(m0 + r) * D_ + g * 64 + d4];
            ks[d4 + 0][r] = x.x; ks[d4 + 1][r] = x.y; ks[d4 + 2][r] = x.z; ks[d4 + 3][r] = x.w;
        }
        // V tile: 64x64 -> 1024 float4, 8 per thread  (FIX: was 4 iterations)
#pragma unroll
        for (int it = 0; it < 8; it++) {
            int idx = it * 128 + t;
            int r = idx >> 4;
            int o4 = (idx & 15) << 2;
            *(float4*)&vs[r][o4] = *(const float4*)&g_v[(size_t)(m0 + r) * D_ + g * 64 + o4];
        }
        __syncthreads();

        // S = q.k^T (8x4 micro)
        float s[8][4] = {};
#pragma unroll
        for (int d = 0; d < 64; d++) {
            float4 a0 = *(const float4*)&qs[d][ty * 8];
            float4 a1 = *(const float4*)&qs[d][ty * 8 + 4];
            float4 b = *(const float4*)&ks[d][tx * 4];
            float ar8[8] = {a0.x, a0.y, a0.z, a0.w, a1.x, a1.y, a1.z, a1.w};
            float br[4] = {b.x, b.y, b.z, b.w};
#pragma unroll
            for (int ii = 0; ii < 8; ii++)
#pragma unroll
                for (int jj = 0; jj < 4; jj++)
                    s[ii][jj] = fmaf(ar8[ii], br[jj], s[ii][jj]);
        }

        // p = w * exp(aff/8); linear partial softmax
#pragma unroll
        for (int ii = 0; ii < 8; ii++) {
            const int n = n0 + ty * 8 + ii;
            float4 w4 = *(const float4*)&g_w[((size_t)n * G_ + g) * M_ + m0 + tx * 4];
            s[ii][0] = w4.x * fast_exp(s[ii][0] * 0.125f);
            s[ii][1] = w4.y * fast_exp(s[ii][1] * 0.125f);
            s[ii][2] = w4.z * fast_exp(s[ii][2] * 0.125f);
            s[ii][3] = w4.w * fast_exp(s[ii][3] * 0.125f);
            lrun[ii] += (s[ii][0] + s[ii][1]) + (s[ii][2] + s[ii][3]);
        }

        __syncthreads();  // all S reads of ks done before ps overwrite
#pragma unroll
        for (int ii = 0; ii < 8; ii++)
            *(float4*)&ps[ty * 8 + ii][tx * 4] = *(float4*)&s[ii][0];
        __syncthreads();

        // acc += P.V
#pragma unroll
        for (int m4 = 0; m4 < 64; m4 += 4) {
            float4 pr[8];
#pragma unroll
            for (int ii = 0; ii < 8; ii++) pr[ii] = *(const float4*)&ps[ty * 8 + ii][m4];
#pragma unroll
            for (int mm = 0; mm < 4; mm++) {
                float4 v4 = *(const float4*)&vs[m4 + mm][tx * 4];
                float vr[4] = {v4.x, v4.y, v4.z, v4.w};
#pragma unroll
                for (int ii = 0; ii < 8; ii++) {
                    float pe = (mm == 0) ? pr[ii].x : (mm == 1) ? pr[ii].y
                             : (mm == 2) ? pr[ii].z : pr[ii].w;
#pragma unroll
                    for (int jj = 0; jj < 4; jj++)
                        acc[ii][jj] = fmaf(pe, vr[jj], acc[ii][jj]);
                }
            }
        }
    }

    // store partials
    const int col = g * 64 + tx * 4;
#pragma unroll
    for (int ii = 0; ii < 8; ii++) {
        const int n = n0 + ty * 8 + ii;
        float l = lrun[ii];
#pragma unroll
        for (int off = 1; off < 16; off <<= 1)
            l += __shfl_xor_sync(0xffffffffu, l, off, 16);
        if (tx == 0) g_pl[z][(size_t)n * G_ + g] = l;
        *(float4*)&g_pacc[z][(size_t)n * D_ + col] = *(float4*)&acc[ii][0];
    }
}

// ---------------- combine halves: out = (acc0+acc1)/(l0+l1) + bv ----------------
__global__ __launch_bounds__(256) void reduce_kernel(const float* __restrict__ bv,
                                                     float* __restrict__ out) {
    int idx = blockIdx.x * 256 + threadIdx.x;
    int n = idx >> 8;
    int col = (idx & 255) << 2;
    int g = col >> 6;
    float l = g_pl[0][(size_t)n * G_ + g] + g_pl[1][(size_t)n * G_ + g];
    float inv = 1.0f / l;
    float4 a0 = *(const float4*)&g_pacc[0][(size_t)n * D_ + col];
    float4 a1 = *(const float4*)&g_pacc[1][(size_t)n * D_ + col];
    float4 b4 = *(const float4*)&bv[col];
    float4 o;
    o.x = fmaf(a0.x + a1.x, inv, b4.x);
    o.y = fmaf(a0.y + a1.y, inv, b4.y);
    o.z = fmaf(a0.z + a1.z, inv, b4.z);
    o.w = fmaf(a0.w + a1.w, inv, b4.w);
    *(float4*)&out[(size_t)n * D_ + col] = o;
}

// ---------------- host launcher ----------------
extern "C" void kernel_launch(void* const* d_in, const int* in_sizes, int n_in,
                              void* d_out, int out_size) {
    const float* roi   = (const float*)d_in[0];
    const float* ref   = (const float*)d_in[1];
    const float* rois1 = (const float*)d_in[2];
    const float* rois2 = (const float*)d_in[3];
    const float* Wq    = (const float*)d_in[4];
    const float* bq    = (const float*)d_in[5];
    const float* Wk    = (const float*)d_in[6];
    const float* bk    = (const float*)d_in[7];
    const float* Wg    = (const float*)d_in[8];
    const float* bg    = (const float*)d_in[9];
    const float* Wv    = (const float*)d_in[10];
    const float* bv    = (const float*)d_in[11];
    float* out = (float*)d_out;

    const int FLASH_SMEM = 3 * 64 * 68 * (int)sizeof(float);  // 52224 B
    static bool attr_set = false;
    if (!attr_set) {
        cudaFuncSetAttribute(flash_kernel, cudaFuncAttributeMaxDynamicSharedMemorySize, FLASH_SMEM);
        attr_set = true;
    }

    box_prep<<<4, 256>>>(rois1, rois2);
    gemm3<<<dim3(8, 16, 3), 128>>>(roi, ref, Wq, bq, Wk, bk, Wv);
    posw_kernel<<<dim3(4, 1024), 256>>>(Wg, bg);
    flash_kernel<<<dim3(16, 16, 2), 128, FLASH_SMEM>>>();
    reduce_kernel<<<1024, 256>>>(bv, out);
}

// round 5
// speedup vs baseline: 1.3486x; 1.0991x over previous
#include <cuda_runtime.h>
#include <math.h>
#include <stdint.h>

#define N_ 1024
#define M_ 1024
#define D_ 1024
#define G_ 16
#define DG_ 64
#define SPLITS 8

typedef unsigned long long u64;

// ---------------- scratch ----------------
__device__ float g_qt[(size_t)D_ * N_];          // q transposed: [d_global][n]
__device__ float g_kt[(size_t)D_ * M_];          // k transposed: [d_global][m]
__device__ float g_v [(size_t)M_ * D_];          // [m][g*64+o]
__device__ float g_part[6][(size_t)D_ * N_];     // gemm split-k partials
__device__ float g_w[(size_t)N_ * G_ * M_];      // (N, G, M)
__device__ float g_boxA[N_ * 4];
__device__ float g_boxB[M_ * 4];
__device__ float g_trigA[N_ * 32];
__device__ float g_trigBt[32 * M_];
__device__ float g_pacc[SPLITS][(size_t)N_ * D_];
__device__ float g_pl[SPLITS][(size_t)N_ * G_];

// ---------------- f32x2 helpers ----------------
__device__ __forceinline__ void fma2(u64& d, u64 a, u64 b) {
    asm("fma.rn.f32x2 %0, %1, %2, %0;" : "+l"(d) : "l"(a), "l"(b));
}
__device__ __forceinline__ u64 pack2(float x, float y) {
    u64 r;
    asm("mov.b64 %0, {%1, %2};" : "=l"(r) : "f"(x), "f"(y));
    return r;
}
__device__ __forceinline__ void unpack2(u64 p, float& x, float& y) {
    asm("mov.b64 {%0, %1}, %2;" : "=f"(x), "=f"(y) : "l"(p));
}
__device__ __forceinline__ u64 dup2(float x) { return pack2(x, x); }

__device__ __forceinline__ float fast_exp(float x) {
    float t = x * 1.4426950408889634f;
    t = fminf(fmaxf(t, -120.0f), 120.0f);
    float fi = floorf(t);
    float f = t - fi;
    float p = 1.5403530393e-4f;
    p = fmaf(p, f, 1.3333558146e-3f);
    p = fmaf(p, f, 9.6181291076e-3f);
    p = fmaf(p, f, 5.5504108664e-2f);
    p = fmaf(p, f, 2.4022650696e-1f);
    p = fmaf(p, f, 6.9314718056e-1f);
    p = fmaf(p, f, 1.0f);
    return p * __int_as_float(((int)fi + 127) << 23);
}

__constant__ float c_cf[8] = {100.0f, 42.169650f, 17.782794f, 7.4989421f,
                              3.1622776f, 1.3335214f, 0.56234133f, 0.23713737f};

// ---------------- box prep ----------------
__global__ void box_prep(const float* __restrict__ rois1, const float* __restrict__ rois2) {
    int i = blockIdx.x * blockDim.x + threadIdx.x;
    if (i >= N_) return;
    {
        float xmin = rois1[i*4+0], ymin = rois1[i*4+1], xmax = rois1[i*4+2], ymax = rois1[i*4+3];
        float w = xmax - xmin + 1.0f, h = ymax - ymin + 1.0f;
        g_boxA[i*4+0] = 0.5f*(xmin+xmax); g_boxA[i*4+1] = 0.5f*(ymin+ymax);
        g_boxA[i*4+2] = 1.0f/w;           g_boxA[i*4+3] = 1.0f/h;
        float lw = logf(w), lh = logf(h);
#pragma unroll
        for (int f = 0; f < 8; f++) {
            float s, c;
            sincosf(lw * c_cf[f], &s, &c);
            g_trigA[i*32 + f] = s;      g_trigA[i*32 + 8 + f] = c;
            sincosf(lh * c_cf[f], &s, &c);
            g_trigA[i*32 + 16 + f] = s; g_trigA[i*32 + 24 + f] = c;
        }
    }
    {
        float xmin = rois2[i*4+0], ymin = rois2[i*4+1], xmax = rois2[i*4+2], ymax = rois2[i*4+3];
        float w = xmax - xmin + 1.0f, h = ymax - ymin + 1.0f;
        g_boxB[i*4+0] = 0.5f*(xmin+xmax); g_boxB[i*4+1] = 0.5f*(ymin+ymax);
        g_boxB[i*4+2] = 1.0f/w;           g_boxB[i*4+3] = 1.0f/h;
        float lw = logf(w), lh = logf(h);
#pragma unroll
        for (int f = 0; f < 8; f++) {
            float s, c;
            sincosf(lw * c_cf[f], &s, &c);
            g_trigBt[f*M_ + i] = s;        g_trigBt[(8+f)*M_ + i] = c;
            sincosf(lh * c_cf[f], &s, &c);
            g_trigBt[(16+f)*M_ + i] = s;   g_trigBt[(24+f)*M_ + i] = c;
        }
    }
}

// ---------------- split-k GEMM: 128x128 tiles, 8x8 micro (f32x2), 256 threads ----------------
// grid (8 j, 8 i, 6): z = mat*2 + khalf.  mat 0: qt=roi@Wq (transposed out),
// mat 1: kt=ref@Wk (transposed out), mat 2: v=ref@Wv^T (row-major out).
__global__ __launch_bounds__(256, 2) void gemm3(
    const float* __restrict__ roi, const float* __restrict__ ref,
    const float* __restrict__ Wq, const float* __restrict__ Wk,
    const float* __restrict__ Wv) {
    __shared__ float As[16][132];   // As[k][i]
    __shared__ float Bs[16][132];   // Bs[k][j]

    const int t = threadIdx.x;
    const int tx = t & 15, ty = t >> 4;
    const int j0 = blockIdx.x * 128, i0 = blockIdx.y * 128;
    const int z = blockIdx.z;
    const int mat = z >> 1;
    const int kbase = (z & 1) * 512;

    const float* A = (mat == 0) ? roi : ref;
    const float* B = (mat == 0) ? Wq : (mat == 1) ? Wk : Wv;
    const bool bt = (mat == 2);
    float* P = g_part[z];

    // A loader: 128 rows x 16 k = 512 float4, 2/thread: r = idx>>2, k4 = (idx&3)*4
    // B (!bt): 16 k x 128 j = 512 float4: k = idx>>5, j4 = (idx&31)*4
    // B (bt) : 128 j x 16 k = 512 float4: j = idx>>2, k4 = (idx&3)*4 (store transposed)
    float4 ag[2], bg[2];

    auto loadG = [&](int kt) {
#pragma unroll
        for (int it = 0; it < 2; it++) {
            int idx = it * 256 + t;
            int r = idx >> 2, k4 = (idx & 3) << 2;
            ag[it] = *(const float4*)&A[(size_t)(i0 + r) * D_ + kbase + kt + k4];
            if (!bt) {
                int kk = idx >> 5, j4 = (idx & 31) << 2;
                bg[it] = *(const float4*)&B[(size_t)(kbase + kt + kk) * D_ + j0 + j4];
            } else {
                bg[it] = *(const float4*)&B[(size_t)(j0 + r) * D_ + kbase + kt + k4];
            }
        }
    };
    auto storeS = [&]() {
#pragma unroll
        for (int it = 0; it < 2; it++) {
            int idx = it * 256 + t;
            int r = idx >> 2, k4 = (idx & 3) << 2;
            As[k4+0][r] = ag[it].x; As[k4+1][r] = ag[it].y;
            As[k4+2][r] = ag[it].z; As[k4+3][r] = ag[it].w;
            if (!bt) {
                int kk = idx >> 5, j4 = (idx & 31) << 2;
                *(float4*)&Bs[kk][j4] = bg[it];
            } else {
                Bs[k4+0][r] = bg[it].x; Bs[k4+1][r] = bg[it].y;
                Bs[k4+2][r] = bg[it].z; Bs[k4+3][r] = bg[it].w;
            }
        }
    };

    u64 acc2[4][8];
#pragma unroll
    for (int a = 0; a < 4; a++)
#pragma unroll
        for (int b = 0; b < 8; b++) acc2[a][b] = 0ull;

    loadG(0);
    storeS();
    __syncthreads();

    for (int kt = 16; kt <= 512; kt += 16) {
        const bool more = (kt < 512);
        if (more) loadG(kt);
#pragma unroll
        for (int k = 0; k < 16; k++) {
            ulonglong2 A0 = *(const ulonglong2*)&As[k][ty * 8];
            ulonglong2 A1 = *(const ulonglong2*)&As[k][ty * 8 + 4];
            u64 pa[4] = {A0.x, A0.y, A1.x, A1.y};
            float4 b0 = *(const float4*)&Bs[k][tx * 8];
            float4 b1 = *(const float4*)&Bs[k][tx * 8 + 4];
            u64 bd[8] = {dup2(b0.x), dup2(b0.y), dup2(b0.z), dup2(b0.w),
                         dup2(b1.x), dup2(b1.y), dup2(b1.z), dup2(b1.w)};
#pragma unroll
            for (int rp = 0; rp < 4; rp++)
#pragma unroll
                for (int jj = 0; jj < 8; jj++)
                    fma2(acc2[rp][jj], pa[rp], bd[jj]);
        }
        if (!more) break;
        __syncthreads();
        storeS();
        __syncthreads();
    }

    // unpack to c[8i][8j]
    float c[8][8];
#pragma unroll
    for (int rp = 0; rp < 4; rp++)
#pragma unroll
        for (int jj = 0; jj < 8; jj++)
            unpack2(acc2[rp][jj], c[2*rp][jj], c[2*rp+1][jj]);

    if (mat != 2) {
        // transposed store: P[j][i]
#pragma unroll
        for (int jj = 0; jj < 8; jj++) {
            float4 v0 = make_float4(c[0][jj], c[1][jj], c[2][jj], c[3][jj]);
            float4 v1 = make_float4(c[4][jj], c[5][jj], c[6][jj], c[7][jj]);
            size_t row = (size_t)(j0 + tx * 8 + jj) * N_ + i0 + ty * 8;
            *(float4*)&P[row] = v0;
            *(float4*)&P[row + 4] = v1;
        }
    } else {
        // row-major store: P[i][j]
#pragma unroll
        for (int ii = 0; ii < 8; ii++) {
            size_t row = (size_t)(i0 + ty * 8 + ii) * D_ + j0 + tx * 8;
            *(float4*)&P[row]     = make_float4(c[ii][0], c[ii][1], c[ii][2], c[ii][3]);
            *(float4*)&P[row + 4] = make_float4(c[ii][4], c[ii][5], c[ii][6], c[ii][7]);
        }
    }
}

// ---------------- combine split-k partials + bias ----------------
// grid (1024, 3), 256 thr; each thread one float4.
__global__ __launch_bounds__(256) void gemm_combine(const float* __restrict__ bq,
                                                    const float* __restrict__ bk) {
    const int mat = blockIdx.y;
    int idx = blockIdx.x * 256 + threadIdx.x;      // 0..262143
    int row = idx >> 8;
    int col = (idx & 255) << 2;
    size_t off = (size_t)row * 1024 + col;
    float4 p0 = *(const float4*)&g_part[mat*2][off];
    float4 p1 = *(const float4*)&g_part[mat*2+1][off];
    float b = 0.0f;
    float* dst;
    if (mat == 0)      { b = bq[row]; dst = g_qt; }
    else if (mat == 1) { b = bk[row]; dst = g_kt; }
    else               { dst = g_v; }
    float4 o;
    o.x = p0.x + p1.x + b;
    o.y = p0.y + p1.y + b;
    o.z = p0.z + p1.z + b;
    o.w = p0.w + p1.w + b;
    *(float4*)&dst[off] = o;
}

// ---------------- position-weight kernel (f32x2 matvec) ----------------
__global__ __launch_bounds__(256) void posw_kernel(const float* __restrict__ Wg,
                                                   const float* __restrict__ bg) {
    __shared__ float4 wgs4[G_][16];
    __shared__ float bgs[G_];
    const int t = threadIdx.x;
    wgs4[t >> 4][t & 15] = ((const float4*)Wg)[t];
    if (t < G_) bgs[t] = bg[t];
    __syncthreads();

    const int n = blockIdx.y;
    const int m = blockIdx.x * 256 + t;

    const float4 bn = *(const float4*)&g_boxA[n * 4];
    const float4 bm = *(const float4*)&g_boxB[m * 4];

    u64 emb2[32];   // pairs of consecutive emb elements

    // dx (emb 0..15), dy (16..31): fast trig
    float px = __logf(fabsf(bn.x - bm.x) * bn.z + 1e-3f);
    float py = __logf(fabsf(bn.y - bm.y) * bn.w + 1e-3f);
#pragma unroll
    for (int f2 = 0; f2 < 4; f2++) {
        float s0, c0, s1, c1;
        __sincosf(px * c_cf[2*f2],   &s0, &c0);
        __sincosf(px * c_cf[2*f2+1], &s1, &c1);
        emb2[f2] = pack2(s0, s1);      // sin pairs e 0..7
        emb2[4 + f2] = pack2(c0, c1);  // cos pairs e 8..15
        __sincosf(py * c_cf[2*f2],   &s0, &c0);
        __sincosf(py * c_cf[2*f2+1], &s1, &c1);
        emb2[8 + f2] = pack2(s0, s1);
        emb2[12 + f2] = pack2(c0, c1);
    }
    // dw (emb 32..47), dh (48..63): angle-difference from precomputed trig
#pragma unroll
    for (int f2 = 0; f2 < 4; f2++) {
        int f = 2 * f2;
        float sn0 = g_trigA[n*32 + f],     cn0 = g_trigA[n*32 + 8 + f];
        float sn1 = g_trigA[n*32 + f + 1], cn1 = g_trigA[n*32 + 8 + f + 1];
        float sm0 = g_trigBt[f*M_ + m],        cm0 = g_trigBt[(8+f)*M_ + m];
        float sm1 = g_trigBt[(f+1)*M_ + m],    cm1 = g_trigBt[(8+f+1)*M_ + m];
        emb2[16 + f2] = pack2(sn0*cm0 - cn0*sm0, sn1*cm1 - cn1*sm1);
        emb2[20 + f2] = pack2(fmaf(cn0, cm0, sn0*sm0), fmaf(cn1, cm1, sn1*sm1));
        sn0 = g_trigA[n*32 + 16 + f];     cn0 = g_trigA[n*32 + 24 + f];
        sn1 = g_trigA[n*32 + 16 + f + 1]; cn1 = g_trigA[n*32 + 24 + f + 1];
        sm0 = g_trigBt[(16+f)*M_ + m];     cm0 = g_trigBt[(24+f)*M_ + m];
        sm1 = g_trigBt[(16+f+1)*M_ + m];   cm1 = g_trigBt[(24+f+1)*M_ + m];
        emb2[24 + f2] = pack2(sn0*cm0 - cn0*sm0, sn1*cm1 - cn1*sm1);
        emb2[28 + f2] = pack2(fmaf(cn0, cm0, sn0*sm0), fmaf(cn1, cm1, sn1*sm1));
    }

    const size_t base = ((size_t)n * G_) * M_ + m;
#pragma unroll
    for (int g = 0; g < G_; g++) {
        u64 s2 = pack2(bgs[g], 0.0f);
        const ulonglong2* w2 = (const ulonglong2*)&wgs4[g][0];
#pragma unroll
        for (int e2 = 0; e2 < 16; e2++) {
            ulonglong2 wp = w2[e2];
            fma2(s2, emb2[2*e2],     wp.x);
            fma2(s2, emb2[2*e2 + 1], wp.y);
        }
        float lo, hi;
        unpack2(s2, lo, hi);
        g_w[base + (size_t)g * M_] = fmaxf(lo + hi, 0.0f) + 1e-6f;
    }
}

// ---------------- fused attention: 128n x 64m tiles, f32x2 micro, M-split8 ----------------
// grid (8 n-tiles, 16 g, 8 splits), 256 thr = 16(tx) x 16(ty).
// S micro: 8r x 4m (4 r-pairs); PV micro: 8r x 4o (4 r-pairs).
__global__ __launch_bounds__(256, 2) void flash_kernel() {
    extern __shared__ float smem[];
    float(*qs)[128] = (float(*)[128])smem;                // [64 d][128 r]
    float(*ks)[64]  = (float(*)[64])(smem + 64 * 128);    // [64 d][64 m]
    float(*vs)[64]  = (float(*)[64])(smem + 64*128 + 64*64);  // [64 m][64 o]
    float(*ps)[128] = (float(*)[128])(smem + 64*128 + 2*64*64); // [64 m][128 r]

    const int t = threadIdx.x;
    const int tx = t & 15, ty = t >> 4;
    const int g = blockIdx.y;
    const int n0 = blockIdx.x * 128;
    const int z = blockIdx.z;

    // fill qs[d][r] from g_qt[(g*64+d)][n0+r] — coalesced, 8 float4/thread
#pragma unroll
    for (int it = 0; it < 8; it++) {
        int idx = it * 256 + t;
        int d = idx >> 5, r4 = (idx & 31) << 2;
        *(float4*)&qs[d][r4] = *(const float4*)&g_qt[(size_t)(g*64 + d) * N_ + n0 + r4];
    }

    u64 acc2[4][4];
#pragma unroll
    for (int a = 0; a < 4; a++)
#pragma unroll
        for (int b = 0; b < 4; b++) acc2[a][b] = 0ull;
    float lrun[8] = {};

    for (int mi = 0; mi < 2; mi++) {
        const int m0 = (z * 2 + mi) * 64;
        __syncthreads();   // prior PV readers done; (iter 0: qs stores visible after next sync)
#pragma unroll
        for (int it = 0; it < 4; it++) {
            int idx = it * 256 + t;
            int d = idx >> 4, m4 = (idx & 15) << 2;
            *(float4*)&ks[d][m4] = *(const float4*)&g_kt[(size_t)(g*64 + d) * M_ + m0 + m4];
        }
#pragma unroll
        for (int it = 0; it < 4; it++) {
            int idx = it * 256 + t;
            int m = idx >> 4, o4 = (idx & 15) << 2;
            *(float4*)&vs[m][o4] = *(const float4*)&g_v[(size_t)(m0 + m) * D_ + g*64 + o4];
        }
        __syncthreads();

        // S = q.k^T : s2[rpair][m]
        u64 s2[4][4];
#pragma unroll
        for (int a = 0; a < 4; a++)
#pragma unroll
            for (int b = 0; b < 4; b++) s2[a][b] = 0ull;

#pragma unroll 8
        for (int d = 0; d < 64; d++) {
            ulonglong2 A0 = *(const ulonglong2*)&qs[d][ty * 8];
            ulonglong2 A1 = *(const ulonglong2*)&qs[d][ty * 8 + 4];
            u64 pa[4] = {A0.x, A0.y, A1.x, A1.y};
            float4 b4 = *(const float4*)&ks[d][tx * 4];
            u64 bd[4] = {dup2(b4.x), dup2(b4.y), dup2(b4.z), dup2(b4.w)};
#pragma unroll
            for (int rp = 0; rp < 4; rp++)
#pragma unroll
                for (int jm = 0; jm < 4; jm++)
                    fma2(s2[rp][jm], pa[rp], bd[jm]);
        }

        // p = w * exp(aff/8); accumulate partial denominators; store ps[m][r] as pairs
#pragma unroll
        for (int rp = 0; rp < 4; rp++) {
            const int r0 = ty * 8 + 2 * rp;
            float4 w0 = *(const float4*)&g_w[((size_t)(n0 + r0) * G_ + g) * M_ + m0 + tx * 4];
            float4 w1 = *(const float4*)&g_w[((size_t)(n0 + r0 + 1) * G_ + g) * M_ + m0 + tx * 4];
            float wl[4] = {w0.x, w0.y, w0.z, w0.w};
            float wh[4] = {w1.x, w1.y, w1.z, w1.w};
#pragma unroll
            for (int jm = 0; jm < 4; jm++) {
                float a0, a1;
                unpack2(s2[rp][jm], a0, a1);
                float p0 = wl[jm] * fast_exp(a0 * 0.125f);
                float p1 = wh[jm] * fast_exp(a1 * 0.125f);
                lrun[2*rp]   += p0;
                lrun[2*rp+1] += p1;
                s2[rp][jm] = pack2(p0, p1);
            }
        }
        // store transposed: ps[m][r], pairs contiguous in r
#pragma unroll
        for (int jm = 0; jm < 4; jm++) {
            ulonglong2 v0; v0.x = s2[0][jm]; v0.y = s2[1][jm];
            ulonglong2 v1; v1.x = s2[2][jm]; v1.y = s2[3][jm];
            *(ulonglong2*)&ps[tx * 4 + jm][ty * 8] = v0;
            *(ulonglong2*)&ps[tx * 4 + jm][ty * 8 + 4] = v1;
        }
        __syncthreads();

        // acc += P.V  (pairs on r, dup on v)
#pragma unroll 4
        for (int m = 0; m < 64; m++) {
            ulonglong2 P0 = *(const ulonglong2*)&ps[m][ty * 8];
            ulonglong2 P1 = *(const ulonglong2*)&ps[m][ty * 8 + 4];
            u64 pp[4] = {P0.x, P0.y, P1.x, P1.y};
            float4 v4 = *(const float4*)&vs[m][tx * 4];
            u64 vd[4] = {dup2(v4.x), dup2(v4.y), dup2(v4.z), dup2(v4.w)};
#pragma unroll
            for (int rp = 0; rp < 4; rp++)
#pragma unroll
                for (int o = 0; o < 4; o++)
                    fma2(acc2[rp][o], pp[rp], vd[o]);
        }
    }

    // store partials
    const int col = g * 64 + tx * 4;
#pragma unroll
    for (int rp = 0; rp < 4; rp++) {
        float a0[4], a1[4];
#pragma unroll
        for (int o = 0; o < 4; o++) unpack2(acc2[rp][o], a0[o], a1[o]);
        const int r0 = n0 + ty * 8 + 2 * rp;
        *(float4*)&g_pacc[z][(size_t)r0 * D_ + col]       = make_float4(a0[0], a0[1], a0[2], a0[3]);
        *(float4*)&g_pacc[z][(size_t)(r0 + 1) * D_ + col] = make_float4(a1[0], a1[1], a1[2], a1[3]);
    }
#pragma unroll
    for (int r = 0; r < 8; r++) {
        float l = lrun[r];
#pragma unroll
        for (int off = 1; off < 16; off <<= 1)
            l += __shfl_xor_sync(0xffffffffu, l, off, 16);
        if (tx == 0) g_pl[z][(size_t)(n0 + ty * 8 + r) * G_ + g] = l;
    }
}

// ---------------- combine 8 partials: out = sum(acc)/sum(l) + bv ----------------
__global__ __launch_bounds__(256) void reduce_kernel(const float* __restrict__ bv,
                                                     float* __restrict__ out) {
    int idx = blockIdx.x * 256 + threadIdx.x;
    int n = idx >> 8;
    int col = (idx & 255) << 2;
    int g = col >> 6;
    float l = 0.0f;
    float4 a = make_float4(0.f, 0.f, 0.f, 0.f);
#pragma unroll
    for (int zz = 0; zz < SPLITS; zz++) {
        l += g_pl[zz][(size_t)n * G_ + g];
        float4 p = *(const float4*)&g_pacc[zz][(size_t)n * D_ + col];
        a.x += p.x; a.y += p.y; a.z += p.z; a.w += p.w;
    }
    float inv = 1.0f / l;
    float4 b4 = *(const float4*)&bv[col];
    float4 o;
    o.x = fmaf(a.x, inv, b4.x);
    o.y = fmaf(a.y, inv, b4.y);
    o.z = fmaf(a.z, inv, b4.z);
    o.w = fmaf(a.w, inv, b4.w);
    *(float4*)&out[(size_t)n * D_ + col] = o;
}

// ---------------- host launcher ----------------
extern "C" void kernel_launch(void* const* d_in, const int* in_sizes, int n_in,
                              void* d_out, int out_size) {
    const float* roi   = (const float*)d_in[0];
    const float* ref   = (const float*)d_in[1];
    const float* rois1 = (const float*)d_in[2];
    const float* rois2 = (const float*)d_in[3];
    const float* Wq    = (const float*)d_in[4];
    const float* bq    = (const float*)d_in[5];
    const float* Wk    = (const float*)d_in[6];
    const float* bk    = (const float*)d_in[7];
    const float* Wg    = (const float*)d_in[8];
    const float* bg    = (const float*)d_in[9];
    const float* Wv    = (const float*)d_in[10];
    const float* bv    = (const float*)d_in[11];
    float* out = (float*)d_out;

    const int FLASH_SMEM = (64*128 + 64*64 + 64*64 + 64*128) * (int)sizeof(float); // 98304
    static bool attr_set = false;
    if (!attr_set) {
        cudaFuncSetAttribute(flash_kernel, cudaFuncAttributeMaxDynamicSharedMemorySize, FLASH_SMEM);
        attr_set = true;
    }

    box_prep<<<4, 256>>>(rois1, rois2);
    gemm3<<<dim3(8, 8, 6), 256>>>(roi, ref, Wq, Wk, Wv);
    gemm_combine<<<dim3(1024, 3), 256>>>(bq, bk);
    posw_kernel<<<dim3(4, 1024), 256>>>(Wg, bg);
    flash_kernel<<<dim3(8, 16, 8), 256, FLASH_SMEM>>>();
    reduce_kernel<<<1024, 256>>>(bv, out);
}

// round 6
// speedup vs baseline: 1.4589x; 1.0817x over previous
#include <cuda_runtime.h>
#include <math.h>
#include <stdint.h>

#define N_ 1024
#define M_ 1024
#define D_ 1024
#define G_ 16
#define DG_ 64
#define SPLITS 8

typedef unsigned long long u64;

// ---------------- scratch ----------------
__device__ float g_qt[(size_t)D_ * N_];          // q transposed: [d_global][n]
__device__ float g_kt[(size_t)D_ * M_];          // k transposed: [d_global][m]
__device__ float g_v [(size_t)M_ * D_];          // [m][g*64+o]
__device__ float g_part[6][(size_t)D_ * N_];     // gemm split-k partials
__device__ float g_w[(size_t)N_ * G_ * M_];      // (N, G, M)
__device__ float g_boxA[N_ * 4];
__device__ float g_boxB[M_ * 4];
__device__ float g_trigA[N_ * 32];
__device__ float g_trigBt[32 * M_];
__device__ float g_pacc[SPLITS][(size_t)N_ * D_];
__device__ float g_pl[SPLITS][(size_t)N_ * G_];

// ---------------- f32x2 helpers ----------------
__device__ __forceinline__ void fma2(u64& d, u64 a, u64 b) {
    asm("fma.rn.f32x2 %0, %1, %2, %0;" : "+l"(d) : "l"(a), "l"(b));
}
__device__ __forceinline__ u64 pack2(float x, float y) {
    u64 r;
    asm("mov.b64 %0, {%1, %2};" : "=l"(r) : "f"(x), "f"(y));
    return r;
}
__device__ __forceinline__ void unpack2(u64 p, float& x, float& y) {
    asm("mov.b64 {%0, %1}, %2;" : "=f"(x), "=f"(y) : "l"(p));
}
__device__ __forceinline__ u64 dup2(float x) { return pack2(x, x); }

__device__ __forceinline__ float fast_exp(float x) {
    float t = x * 1.4426950408889634f;
    t = fminf(fmaxf(t, -120.0f), 120.0f);
    float fi = floorf(t);
    float f = t - fi;
    float p = 1.5403530393e-4f;
    p = fmaf(p, f, 1.3333558146e-3f);
    p = fmaf(p, f, 9.6181291076e-3f);
    p = fmaf(p, f, 5.5504108664e-2f);
    p = fmaf(p, f, 2.4022650696e-1f);
    p = fmaf(p, f, 6.9314718056e-1f);
    p = fmaf(p, f, 1.0f);
    return p * __int_as_float(((int)fi + 127) << 23);
}

__constant__ float c_cf[8] = {100.0f, 42.169650f, 17.782794f, 7.4989421f,
                              3.1622776f, 1.3335214f, 0.56234133f, 0.23713737f};

// ---------------- box prep ----------------
__global__ void box_prep(const float* __restrict__ rois1, const float* __restrict__ rois2) {
    int i = blockIdx.x * blockDim.x + threadIdx.x;
    if (i >= N_) return;
    {
        float xmin = rois1[i*4+0], ymin = rois1[i*4+1], xmax = rois1[i*4+2], ymax = rois1[i*4+3];
        float w = xmax - xmin + 1.0f, h = ymax - ymin + 1.0f;
        g_boxA[i*4+0] = 0.5f*(xmin+xmax); g_boxA[i*4+1] = 0.5f*(ymin+ymax);
        g_boxA[i*4+2] = 1.0f/w;           g_boxA[i*4+3] = 1.0f/h;
        float lw = logf(w), lh = logf(h);
#pragma unroll
        for (int f = 0; f < 8; f++) {
            float s, c;
            sincosf(lw * c_cf[f], &s, &c);
            g_trigA[i*32 + f] = s;      g_trigA[i*32 + 8 + f] = c;
            sincosf(lh * c_cf[f], &s, &c);
            g_trigA[i*32 + 16 + f] = s; g_trigA[i*32 + 24 + f] = c;
        }
    }
    {
        float xmin = rois2[i*4+0], ymin = rois2[i*4+1], xmax = rois2[i*4+2], ymax = rois2[i*4+3];
        float w = xmax - xmin + 1.0f, h = ymax - ymin + 1.0f;
        g_boxB[i*4+0] = 0.5f*(xmin+xmax); g_boxB[i*4+1] = 0.5f*(ymin+ymax);
        g_boxB[i*4+2] = 1.0f/w;           g_boxB[i*4+3] = 1.0f/h;
        float lw = logf(w), lh = logf(h);
#pragma unroll
        for (int f = 0; f < 8; f++) {
            float s, c;
            sincosf(lw * c_cf[f], &s, &c);
            g_trigBt[f*M_ + i] = s;        g_trigBt[(8+f)*M_ + i] = c;
            sincosf(lh * c_cf[f], &s, &c);
            g_trigBt[(16+f)*M_ + i] = s;   g_trigBt[(24+f)*M_ + i] = c;
        }
    }
}

// ---------------- split-k GEMM: 128x128 tiles, 8x8 micro (f32x2), 256 threads ----------------
__global__ __launch_bounds__(256, 2) void gemm3(
    const float* __restrict__ roi, const float* __restrict__ ref,
    const float* __restrict__ Wq, const float* __restrict__ Wk,
    const float* __restrict__ Wv) {
    __shared__ float As[16][132];   // As[k][i]
    __shared__ float Bs[16][132];   // Bs[k][j]

    const int t = threadIdx.x;
    const int tx = t & 15, ty = t >> 4;
    const int j0 = blockIdx.x * 128, i0 = blockIdx.y * 128;
    const int z = blockIdx.z;
    const int mat = z >> 1;
    const int kbase = (z & 1) * 512;

    const float* A = (mat == 0) ? roi : ref;
    const float* B = (mat == 0) ? Wq : (mat == 1) ? Wk : Wv;
    const bool bt = (mat == 2);
    float* P = g_part[z];

    float4 ag[2], bg[2];

    auto loadG = [&](int kt) {
#pragma unroll
        for (int it = 0; it < 2; it++) {
            int idx = it * 256 + t;
            int r = idx >> 2, k4 = (idx & 3) << 2;
            ag[it] = *(const float4*)&A[(size_t)(i0 + r) * D_ + kbase + kt + k4];
            if (!bt) {
                int kk = idx >> 5, j4 = (idx & 31) << 2;
                bg[it] = *(const float4*)&B[(size_t)(kbase + kt + kk) * D_ + j0 + j4];
            } else {
                bg[it] = *(const float4*)&B[(size_t)(j0 + r) * D_ + kbase + kt + k4];
            }
        }
    };
    auto storeS = [&]() {
#pragma unroll
        for (int it = 0; it < 2; it++) {
            int idx = it * 256 + t;
            int r = idx >> 2, k4 = (idx & 3) << 2;
            As[k4+0][r] = ag[it].x; As[k4+1][r] = ag[it].y;
            As[k4+2][r] = ag[it].z; As[k4+3][r] = ag[it].w;
            if (!bt) {
                int kk = idx >> 5, j4 = (idx & 31) << 2;
                *(float4*)&Bs[kk][j4] = bg[it];
            } else {
                Bs[k4+0][r] = bg[it].x; Bs[k4+1][r] = bg[it].y;
                Bs[k4+2][r] = bg[it].z; Bs[k4+3][r] = bg[it].w;
            }
        }
    };

    u64 acc2[4][8];
#pragma unroll
    for (int a = 0; a < 4; a++)
#pragma unroll
        for (int b = 0; b < 8; b++) acc2[a][b] = 0ull;

    loadG(0);
    storeS();
    __syncthreads();

    for (int kt = 16; kt <= 512; kt += 16) {
        const bool more = (kt < 512);
        if (more) loadG(kt);
#pragma unroll
        for (int k = 0; k < 16; k++) {
            ulonglong2 A0 = *(const ulonglong2*)&As[k][ty * 8];
            ulonglong2 A1 = *(const ulonglong2*)&As[k][ty * 8 + 4];
            u64 pa[4] = {A0.x, A0.y, A1.x, A1.y};
            float4 b0 = *(const float4*)&Bs[k][tx * 8];
            float4 b1 = *(const float4*)&Bs[k][tx * 8 + 4];
            u64 bd[8] = {dup2(b0.x), dup2(b0.y), dup2(b0.z), dup2(b0.w),
                         dup2(b1.x), dup2(b1.y), dup2(b1.z), dup2(b1.w)};
#pragma unroll
            for (int rp = 0; rp < 4; rp++)
#pragma unroll
                for (int jj = 0; jj < 8; jj++)
                    fma2(acc2[rp][jj], pa[rp], bd[jj]);
        }
        if (!more) break;
        __syncthreads();
        storeS();
        __syncthreads();
    }

    float c[8][8];
#pragma unroll
    for (int rp = 0; rp < 4; rp++)
#pragma unroll
        for (int jj = 0; jj < 8; jj++)
            unpack2(acc2[rp][jj], c[2*rp][jj], c[2*rp+1][jj]);

    if (mat != 2) {
#pragma unroll
        for (int jj = 0; jj < 8; jj++) {
            float4 v0 = make_float4(c[0][jj], c[1][jj], c[2][jj], c[3][jj]);
            float4 v1 = make_float4(c[4][jj], c[5][jj], c[6][jj], c[7][jj]);
            size_t row = (size_t)(j0 + tx * 8 + jj) * N_ + i0 + ty * 8;
            *(float4*)&P[row] = v0;
            *(float4*)&P[row + 4] = v1;
        }
    } else {
#pragma unroll
        for (int ii = 0; ii < 8; ii++) {
            size_t row = (size_t)(i0 + ty * 8 + ii) * D_ + j0 + tx * 8;
            *(float4*)&P[row]     = make_float4(c[ii][0], c[ii][1], c[ii][2], c[ii][3]);
            *(float4*)&P[row + 4] = make_float4(c[ii][4], c[ii][5], c[ii][6], c[ii][7]);
        }
    }
}

// ---------------- combine split-k partials + bias ----------------
__global__ __launch_bounds__(256) void gemm_combine(const float* __restrict__ bq,
                                                    const float* __restrict__ bk) {
    const int mat = blockIdx.y;
    int idx = blockIdx.x * 256 + threadIdx.x;
    int row = idx >> 8;
    int col = (idx & 255) << 2;
    size_t off = (size_t)row * 1024 + col;
    float4 p0 = *(const float4*)&g_part[mat*2][off];
    float4 p1 = *(const float4*)&g_part[mat*2+1][off];
    float b = 0.0f;
    float* dst;
    if (mat == 0)      { b = bq[row]; dst = g_qt; }
    else if (mat == 1) { b = bk[row]; dst = g_kt; }
    else               { dst = g_v; }
    float4 o;
    o.x = p0.x + p1.x + b;
    o.y = p0.y + p1.y + b;
    o.z = p0.z + p1.z + b;
    o.w = p0.w + p1.w + b;
    *(float4*)&dst[off] = o;
}

// ---------------- position-weight kernel: 2 m per thread, transposed weights ----------------
// grid (2, 1024), 256 thr. Each thread: m0 = bx*512+t, m1 = m0+256.
// Lanes = g-pairs; weights from smem wgt[e][g] (broadcast LDS.128), reused for both m.
__global__ __launch_bounds__(256, 2) void posw_kernel(const float* __restrict__ Wg,
                                                      const float* __restrict__ bg) {
    __shared__ float wgt[64][16];   // wgt[e][g]; rows 64B -> 16B-aligned for ulonglong2
    __shared__ float bgs[G_];
    const int t = threadIdx.x;
#pragma unroll
    for (int i = t; i < 1024; i += 256) {
        int g = i >> 6, e = i & 63;
        wgt[e][g] = Wg[i];
    }
    if (t < G_) bgs[t] = bg[t];
    __syncthreads();

    const int n = blockIdx.y;
    const int m0 = blockIdx.x * 512 + t;
    const int m1 = m0 + 256;

    u64 acc0[8], acc1[8];
#pragma unroll
    for (int gp = 0; gp < 8; gp++) {
        u64 b2 = pack2(bgs[2*gp], bgs[2*gp+1]);
        acc0[gp] = b2;
        acc1[gp] = b2;
    }

    // update both m's accumulators for embedding element e with values v0 (m0), v1 (m1)
    auto upd = [&](int e, float v0, float v1) {
        const ulonglong2* wr = (const ulonglong2*)&wgt[e][0];
        ulonglong2 wa = wr[0], wb = wr[1];
        u64 d0 = dup2(v0), d1 = dup2(v1);
        fma2(acc0[0], d0, wa.x); fma2(acc1[0], d1, wa.x);
        fma2(acc0[1], d0, wa.y); fma2(acc1[1], d1, wa.y);
        fma2(acc0[2], d0, wb.x); fma2(acc1[2], d1, wb.x);
        fma2(acc0[3], d0, wb.y); fma2(acc1[3], d1, wb.y);
        ulonglong2 wc = wr[2], wd = wr[3];
        fma2(acc0[4], d0, wc.x); fma2(acc1[4], d1, wc.x);
        fma2(acc0[5], d0, wc.y); fma2(acc1[5], d1, wc.y);
        fma2(acc0[6], d0, wd.x); fma2(acc1[6], d1, wd.x);
        fma2(acc0[7], d0, wd.y); fma2(acc1[7], d1, wd.y);
    };

    const float4 bn = *(const float4*)&g_boxA[n * 4];
    const float4 bm0 = *(const float4*)&g_boxB[m0 * 4];
    const float4 bm1 = *(const float4*)&g_boxB[m1 * 4];

    // dx (e 0..15), dy (e 16..31): fast log + fast sincos per m
    {
        float px0 = __logf(fabsf(bn.x - bm0.x) * bn.z + 1e-3f);
        float px1 = __logf(fabsf(bn.x - bm1.x) * bn.z + 1e-3f);
#pragma unroll
        for (int f = 0; f < 8; f++) {
            float s0, c0, s1, c1;
            __sincosf(px0 * c_cf[f], &s0, &c0);
            __sincosf(px1 * c_cf[f], &s1, &c1);
            upd(f, s0, s1);
            upd(8 + f, c0, c1);
        }
        float py0 = __logf(fabsf(bn.y - bm0.y) * bn.w + 1e-3f);
        float py1 = __logf(fabsf(bn.y - bm1.y) * bn.w + 1e-3f);
#pragma unroll
        for (int f = 0; f < 8; f++) {
            float s0, c0, s1, c1;
            __sincosf(py0 * c_cf[f], &s0, &c0);
            __sincosf(py1 * c_cf[f], &s1, &c1);
            upd(16 + f, s0, s1);
            upd(24 + f, c0, c1);
        }
    }

    // dw (e 32..47): angle-difference from precomputed trig; trigA shared across both m
#pragma unroll
    for (int f = 0; f < 8; f++) {
        float snf = g_trigA[n*32 + f], cnf = g_trigA[n*32 + 8 + f];
        float sm0 = g_trigBt[f*M_ + m0], cm0 = g_trigBt[(8+f)*M_ + m0];
        float sm1 = g_trigBt[f*M_ + m1], cm1 = g_trigBt[(8+f)*M_ + m1];
        upd(32 + f, snf*cm0 - cnf*sm0, snf*cm1 - cnf*sm1);
        upd(40 + f, fmaf(cnf, cm0, snf*sm0), fmaf(cnf, cm1, snf*sm1));
    }
    // dh (e 48..63)
#pragma unroll
    for (int f = 0; f < 8; f++) {
        float snf = g_trigA[n*32 + 16 + f], cnf = g_trigA[n*32 + 24 + f];
        float sm0 = g_trigBt[(16+f)*M_ + m0], cm0 = g_trigBt[(24+f)*M_ + m0];
        float sm1 = g_trigBt[(16+f)*M_ + m1], cm1 = g_trigBt[(24+f)*M_ + m1];
        upd(48 + f, snf*cm0 - cnf*sm0, snf*cm1 - cnf*sm1);
        upd(56 + f, fmaf(cnf, cm0, snf*sm0), fmaf(cnf, cm1, snf*sm1));
    }

    const size_t base = (size_t)n * G_ * M_;
#pragma unroll
    for (int gp = 0; gp < 8; gp++) {
        float x0, y0, x1, y1;
        unpack2(acc0[gp], x0, y0);
        unpack2(acc1[gp], x1, y1);
        g_w[base + (size_t)(2*gp)   * M_ + m0] = fmaxf(x0, 0.0f) + 1e-6f;
        g_w[base + (size_t)(2*gp+1) * M_ + m0] = fmaxf(y0, 0.0f) + 1e-6f;
        g_w[base + (size_t)(2*gp)   * M_ + m1] = fmaxf(x1, 0.0f) + 1e-6f;
        g_w[base + (size_t)(2*gp+1) * M_ + m1] = fmaxf(y1, 0.0f) + 1e-6f;
    }
}

// ---------------- fused attention: 128n x 64m tiles, f32x2 micro, M-split8 ----------------
__global__ __launch_bounds__(256, 2) void flash_kernel() {
    extern __shared__ float smem[];
    float(*qs)[128] = (float(*)[128])smem;                // [64 d][128 r]
    float(*ks)[64]  = (float(*)[64])(smem + 64 * 128);    // [64 d][64 m]
    float(*vs)[64]  = (float(*)[64])(smem + 64*128 + 64*64);
    float(*ps)[128] = (float(*)[128])(smem + 64*128 + 2*64*64);

    const int t = threadIdx.x;
    const int tx = t & 15, ty = t >> 4;
    const int g = blockIdx.y;
    const int n0 = blockIdx.x * 128;
    const int z = blockIdx.z;

#pragma unroll
    for (int it = 0; it < 8; it++) {
        int idx = it * 256 + t;
        int d = idx >> 5, r4 = (idx & 31) << 2;
        *(float4*)&qs[d][r4] = *(const float4*)&g_qt[(size_t)(g*64 + d) * N_ + n0 + r4];
    }

    u64 acc2[4][4];
#pragma unroll
    for (int a = 0; a < 4; a++)
#pragma unroll
        for (int b = 0; b < 4; b++) acc2[a][b] = 0ull;
    float lrun[8] = {};

    for (int mi = 0; mi < 2; mi++) {
        const int m0 = (z * 2 + mi) * 64;
        __syncthreads();
#pragma unroll
        for (int it = 0; it < 4; it++) {
            int idx = it * 256 + t;
            int d = idx >> 4, m4 = (idx & 15) << 2;
            *(float4*)&ks[d][m4] = *(const float4*)&g_kt[(size_t)(g*64 + d) * M_ + m0 + m4];
        }
#pragma unroll
        for (int it = 0; it < 4; it++) {
            int idx = it * 256 + t;
            int m = idx >> 4, o4 = (idx & 15) << 2;
            *(float4*)&vs[m][o4] = *(const float4*)&g_v[(size_t)(m0 + m) * D_ + g*64 + o4];
        }
        __syncthreads();

        u64 s2[4][4];
#pragma unroll
        for (int a = 0; a < 4; a++)
#pragma unroll
            for (int b = 0; b < 4; b++) s2[a][b] = 0ull;

#pragma unroll 8
        for (int d = 0; d < 64; d++) {
            ulonglong2 A0 = *(const ulonglong2*)&qs[d][ty * 8];
            ulonglong2 A1 = *(const ulonglong2*)&qs[d][ty * 8 + 4];
            u64 pa[4] = {A0.x, A0.y, A1.x, A1.y};
            float4 b4 = *(const float4*)&ks[d][tx * 4];
            u64 bd[4] = {dup2(b4.x), dup2(b4.y), dup2(b4.z), dup2(b4.w)};
#pragma unroll
            for (int rp = 0; rp < 4; rp++)
#pragma unroll
                for (int jm = 0; jm < 4; jm++)
                    fma2(s2[rp][jm], pa[rp], bd[jm]);
        }

#pragma unroll
        for (int rp = 0; rp < 4; rp++) {
            const int r0 = ty * 8 + 2 * rp;
            float4 w0 = *(const float4*)&g_w[((size_t)(n0 + r0) * G_ + g) * M_ + m0 + tx * 4];
            float4 w1 = *(const float4*)&g_w[((size_t)(n0 + r0 + 1) * G_ + g) * M_ + m0 + tx * 4];
            float wl[4] = {w0.x, w0.y, w0.z, w0.w};
            float wh[4] = {w1.x, w1.y, w1.z, w1.w};
#pragma unroll
            for (int jm = 0; jm < 4; jm++) {
                float a0, a1;
                unpack2(s2[rp][jm], a0, a1);
                float p0 = wl[jm] * fast_exp(a0 * 0.125f);
                float p1 = wh[jm] * fast_exp(a1 * 0.125f);
                lrun[2*rp]   += p0;
                lrun[2*rp+1] += p1;
                s2[rp][jm] = pack2(p0, p1);
            }
        }
#pragma unroll
        for (int jm = 0; jm < 4; jm++) {
            ulonglong2 v0; v0.x = s2[0][jm]; v0.y = s2[1][jm];
            ulonglong2 v1; v1.x = s2[2][jm]; v1.y = s2[3][jm];
            *(ulonglong2*)&ps[tx * 4 + jm][ty * 8] = v0;
            *(ulonglong2*)&ps[tx * 4 + jm][ty * 8 + 4] = v1;
        }
        __syncthreads();

#pragma unroll 4
        for (int m = 0; m < 64; m++) {
            ulonglong2 P0 = *(const ulonglong2*)&ps[m][ty * 8];
            ulonglong2 P1 = *(const ulonglong2*)&ps[m][ty * 8 + 4];
            u64 pp[4] = {P0.x, P0.y, P1.x, P1.y};
            float4 v4 = *(const float4*)&vs[m][tx * 4];
            u64 vd[4] = {dup2(v4.x), dup2(v4.y), dup2(v4.z), dup2(v4.w)};
#pragma unroll
            for (int rp = 0; rp < 4; rp++)
#pragma unroll
                for (int o = 0; o < 4; o++)
                    fma2(acc2[rp][o], pp[rp], vd[o]);
        }
    }

    const int col = g * 64 + tx * 4;
#pragma unroll
    for (int rp = 0; rp < 4; rp++) {
        float a0[4], a1[4];
#pragma unroll
        for (int o = 0; o < 4; o++) unpack2(acc2[rp][o], a0[o], a1[o]);
        const int r0 = n0 + ty * 8 + 2 * rp;
        *(float4*)&g_pacc[z][(size_t)r0 * D_ + col]       = make_float4(a0[0], a0[1], a0[2], a0[3]);
        *(float4*)&g_pacc[z][(size_t)(r0 + 1) * D_ + col] = make_float4(a1[0], a1[1], a1[2], a1[3]);
    }
#pragma unroll
    for (int r = 0; r < 8; r++) {
        float l = lrun[r];
#pragma unroll
        for (int off = 1; off < 16; off <<= 1)
            l += __shfl_xor_sync(0xffffffffu, l, off, 16);
        if (tx == 0) g_pl[z][(size_t)(n0 + ty * 8 + r) * G_ + g] = l;
    }
}

// ---------------- combine 8 partials ----------------
__global__ __launch_bounds__(256) void reduce_kernel(const float* __restrict__ bv,
                                                     float* __restrict__ out) {
    int idx = blockIdx.x * 256 + threadIdx.x;
    int n = idx >> 8;
    int col = (idx & 255) << 2;
    int g = col >> 6;
    float l = 0.0f;
    float4 a = make_float4(0.f, 0.f, 0.f, 0.f);
#pragma unroll
    for (int zz = 0; zz < SPLITS; zz++) {
        l += g_pl[zz][(size_t)n * G_ + g];
        float4 p = *(const float4*)&g_pacc[zz][(size_t)n * D_ + col];
        a.x += p.x; a.y += p.y; a.z += p.z; a.w += p.w;
    }
    float inv = 1.0f / l;
    float4 b4 = *(const float4*)&bv[col];
    float4 o;
    o.x = fmaf(a.x, inv, b4.x);
    o.y = fmaf(a.y, inv, b4.y);
    o.z = fmaf(a.z, inv, b4.z);
    o.w = fmaf(a.w, inv, b4.w);
    *(float4*)&out[(size_t)n * D_ + col] = o;
}

// ---------------- host launcher ----------------
extern "C" void kernel_launch(void* const* d_in, const int* in_sizes, int n_in,
                              void* d_out, int out_size) {
    const float* roi   = (const float*)d_in[0];
    const float* ref   = (const float*)d_in[1];
    const float* rois1 = (const float*)d_in[2];
    const float* rois2 = (const float*)d_in[3];
    const float* Wq    = (const float*)d_in[4];
    const float* bq    = (const float*)d_in[5];
    const float* Wk    = (const float*)d_in[6];
    const float* bk    = (const float*)d_in[7];
    const float* Wg    = (const float*)d_in[8];
    const float* bg    = (const float*)d_in[9];
    const float* Wv    = (const float*)d_in[10];
    const float* bv    = (const float*)d_in[11];
    float* out = (float*)d_out;

    const int FLASH_SMEM = (64*128 + 64*64 + 64*64 + 64*128) * (int)sizeof(float); // 98304
    static bool attr_set = false;
    if (!attr_set) {
        cudaFuncSetAttribute(flash_kernel, cudaFuncAttributeMaxDynamicSharedMemorySize, FLASH_SMEM);
        attr_set = true;
    }

    box_prep<<<4, 256>>>(rois1, rois2);
    gemm3<<<dim3(8, 8, 6), 256>>>(roi, ref, Wq, Wk, Wv);
    gemm_combine<<<dim3(1024, 3), 256>>>(bq, bk);
    posw_kernel<<<dim3(2, 1024), 256>>>(Wg, bg);
    flash_kernel<<<dim3(8, 16, 8), 256, FLASH_SMEM>>>();
    reduce_kernel<<<1024, 256>>>(bv, out);
}

// round 8
// speedup vs baseline: 1.7701x; 1.2134x over previous
#include <cuda_runtime.h>
#include <cuda_bf16.h>
#include <math.h>
#include <stdint.h>

#define N_ 1024
#define M_ 1024
#define D_ 1024
#define G_ 16
#define DG_ 64
#define SPLITS 8

typedef unsigned long long u64;

// ---------------- scratch ----------------
__device__ float g_qt[(size_t)D_ * N_];          // q transposed: [d_global][n]
__device__ float g_kt[(size_t)D_ * M_];          // k transposed: [d_global][m]
__device__ float g_v [(size_t)M_ * D_];          // [m][g*64+o]
__device__ float g_w[(size_t)N_ * G_ * M_];      // (N, G, M)
__device__ float g_boxA[N_ * 4];
__device__ float g_boxB[M_ * 4];
__device__ float g_trigA[N_ * 32];
__device__ float g_trigBt[32 * M_];
__device__ float g_pacc[SPLITS][(size_t)N_ * D_];
__device__ float g_pl[SPLITS][(size_t)N_ * G_];

// bf16 hi/lo operand buffers
#define MEG (1024 * 1024)
__device__ __align__(16) uint16_t g_roiH[MEG], g_roiL[MEG];
__device__ __align__(16) uint16_t g_refH[MEG], g_refL[MEG];
__device__ __align__(16) uint16_t g_wvH[MEG],  g_wvL[MEG];
__device__ __align__(16) uint16_t g_wqtH[MEG], g_wqtL[MEG];   // Wq^T [j][k]
__device__ __align__(16) uint16_t g_wktH[MEG], g_wktL[MEG];   // Wk^T [j][k]

// ---------------- f32x2 helpers ----------------
__device__ __forceinline__ void fma2(u64& d, u64 a, u64 b) {
    asm("fma.rn.f32x2 %0, %1, %2, %0;" : "+l"(d) : "l"(a), "l"(b));
}
__device__ __forceinline__ u64 pack2(float x, float y) {
    u64 r;
    asm("mov.b64 %0, {%1, %2};" : "=l"(r) : "f"(x), "f"(y));
    return r;
}
__device__ __forceinline__ void unpack2(u64 p, float& x, float& y) {
    asm("mov.b64 {%0, %1}, %2;" : "=f"(x), "=f"(y) : "l"(p));
}
__device__ __forceinline__ u64 dup2(float x) { return pack2(x, x); }

__device__ __forceinline__ float fast_exp(float x) {
    float t = x * 1.4426950408889634f;
    t = fminf(fmaxf(t, -120.0f), 120.0f);
    float fi = floorf(t);
    float f = t - fi;
    float p = 1.5403530393e-4f;
    p = fmaf(p, f, 1.3333558146e-3f);
    p = fmaf(p, f, 9.6181291076e-3f);
    p = fmaf(p, f, 5.5504108664e-2f);
    p = fmaf(p, f, 2.4022650696e-1f);
    p = fmaf(p, f, 6.9314718056e-1f);
    p = fmaf(p, f, 1.0f);
    return p * __int_as_float(((int)fi + 127) << 23);
}

__constant__ float c_cf[8] = {100.0f, 42.169650f, 17.782794f, 7.4989421f,
                              3.1622776f, 1.3335214f, 0.56234133f, 0.23713737f};

// ---------------- warp-mma helpers (baseline PTX, no 'a' features) ----------------
__device__ __forceinline__ uint32_t smem_to_u32(const void* p) {
    uint32_t a;
    asm("{ .reg .u64 t; cvta.to.shared.u64 t, %1; cvt.u32.u64 %0, t; }" : "=r"(a) : "l"(p));
    return a;
}
__device__ __forceinline__ void mma16816(float* d, const uint32_t* a, const uint32_t* b) {
    asm volatile(
        "mma.sync.aligned.m16n8k16.row.col.f32.bf16.bf16.f32 "
        "{%0,%1,%2,%3}, {%4,%5,%6,%7}, {%8,%9}, {%0,%1,%2,%3};"
        : "+f"(d[0]), "+f"(d[1]), "+f"(d[2]), "+f"(d[3])
        : "r"(a[0]), "r"(a[1]), "r"(a[2]), "r"(a[3]), "r"(b[0]), "r"(b[1]));
}
__device__ __forceinline__ void ldsm_x4(uint32_t* r, uint32_t addr) {
    asm volatile("ldmatrix.sync.aligned.m8n8.x4.shared.b16 {%0,%1,%2,%3}, [%4];"
                 : "=r"(r[0]), "=r"(r[1]), "=r"(r[2]), "=r"(r[3]) : "r"(addr));
}
__device__ __forceinline__ void ldsm_x2(uint32_t* r, uint32_t addr) {
    asm volatile("ldmatrix.sync.aligned.m8n8.x2.shared.b16 {%0,%1}, [%2];"
                 : "=r"(r[0]), "=r"(r[1]) : "r"(addr));
}
#define SWZ(bo) ((bo) ^ (((bo) >> 3) & 0x70))

// ---------------- box prep ----------------
__global__ void box_prep(const float* __restrict__ rois1, const float* __restrict__ rois2) {
    int i = blockIdx.x * blockDim.x + threadIdx.x;
    if (i >= N_) return;
    {
        float xmin = rois1[i*4+0], ymin = rois1[i*4+1], xmax = rois1[i*4+2], ymax = rois1[i*4+3];
        float w = xmax - xmin + 1.0f, h = ymax - ymin + 1.0f;
        g_boxA[i*4+0] = 0.5f*(xmin+xmax); g_boxA[i*4+1] = 0.5f*(ymin+ymax);
        g_boxA[i*4+2] = 1.0f/w;           g_boxA[i*4+3] = 1.0f/h;
        float lw = logf(w), lh = logf(h);
#pragma unroll
        for (int f = 0; f < 8; f++) {
            float s, c;
            sincosf(lw * c_cf[f], &s, &c);
            g_trigA[i*32 + f] = s;      g_trigA[i*32 + 8 + f] = c;
            sincosf(lh * c_cf[f], &s, &c);
            g_trigA[i*32 + 16 + f] = s; g_trigA[i*32 + 24 + f] = c;
        }
    }
    {
        float xmin = rois2[i*4+0], ymin = rois2[i*4+1], xmax = rois2[i*4+2], ymax = rois2[i*4+3];
        float w = xmax - xmin + 1.0f, h = ymax - ymin + 1.0f;
        g_boxB[i*4+0] = 0.5f*(xmin+xmax); g_boxB[i*4+1] = 0.5f*(ymin+ymax);
        g_boxB[i*4+2] = 1.0f/w;           g_boxB[i*4+3] = 1.0f/h;
        float lw = logf(w), lh = logf(h);
#pragma unroll
        for (int f = 0; f < 8; f++) {
            float s, c;
            sincosf(lw * c_cf[f], &s, &c);
            g_trigBt[f*M_ + i] = s;        g_trigBt[(8+f)*M_ + i] = c;
            sincosf(lh * c_cf[f], &s, &c);
            g_trigBt[(16+f)*M_ + i] = s;   g_trigBt[(24+f)*M_ + i] = c;
        }
    }
}

// ---------------- fp32 -> bf16 hi/lo (row-major tensors) ----------------
__global__ __launch_bounds__(256) void conv_a(const float* __restrict__ roi,
                                              const float* __restrict__ ref,
                                              const float* __restrict__ wv) {
    const int z = blockIdx.y;
    const float4* src = (const float4*)(z == 0 ? roi : z == 1 ? ref : wv);
    uint2* dh = (uint2*)(z == 0 ? g_roiH : z == 1 ? g_refH : g_wvH);
    uint2* dl = (uint2*)(z == 0 ? g_roiL : z == 1 ? g_refL : g_wvL);
    int i = blockIdx.x * 256 + threadIdx.x;
    float4 x = src[i];
    __nv_bfloat16 h0 = __float2bfloat16(x.x), h1 = __float2bfloat16(x.y);
    __nv_bfloat16 h2 = __float2bfloat16(x.z), h3 = __float2bfloat16(x.w);
    __nv_bfloat16 e0 = __float2bfloat16(x.x - __bfloat162float(h0));
    __nv_bfloat16 e1 = __float2bfloat16(x.y - __bfloat162float(h1));
    __nv_bfloat16 e2 = __float2bfloat16(x.z - __bfloat162float(h2));
    __nv_bfloat16 e3 = __float2bfloat16(x.w - __bfloat162float(h3));
    uint2 H, L;
    H.x = ((uint32_t)__bfloat16_as_ushort(h1) << 16) | __bfloat16_as_ushort(h0);
    H.y = ((uint32_t)__bfloat16_as_ushort(h3) << 16) | __bfloat16_as_ushort(h2);
    L.x = ((uint32_t)__bfloat16_as_ushort(e1) << 16) | __bfloat16_as_ushort(e0);
    L.y = ((uint32_t)__bfloat16_as_ushort(e3) << 16) | __bfloat16_as_ushort(e2);
    dh[i] = H;
    dl[i] = L;
}

// ---------------- Wq/Wk transpose + bf16 hi/lo: W[k][j] -> Wt[j][k] ----------------
__global__ __launch_bounds__(256) void conv_w(const float* __restrict__ Wq,
                                              const float* __restrict__ Wk) {
    __shared__ float ts[64][65];
    const int z = blockIdx.z;
    const float* W = z ? Wk : Wq;
    uint2* dh = (uint2*)(z ? g_wktH : g_wqtH);
    uint2* dl = (uint2*)(z ? g_wktL : g_wqtL);
    const int j0 = blockIdx.x * 64, k0 = blockIdx.y * 64;
    const int t = threadIdx.x;
#pragma unroll
    for (int it = 0; it < 4; it++) {
        int lin = it * 256 + t;
        int k = lin >> 4, j4 = (lin & 15) << 2;
        float4 v = *(const float4*)&W[(size_t)(k0 + k) * D_ + j0 + j4];
        ts[j4 + 0][k] = v.x; ts[j4 + 1][k] = v.y; ts[j4 + 2][k] = v.z; ts[j4 + 3][k] = v.w;
    }
    __syncthreads();
#pragma unroll
    for (int it = 0; it < 4; it++) {
        int lin = it * 256 + t;
        int j = lin >> 4, k4 = (lin & 15) << 2;
        float a = ts[j][k4 + 0], b = ts[j][k4 + 1], c = ts[j][k4 + 2], d = ts[j][k4 + 3];
        __nv_bfloat16 h0 = __float2bfloat16(a), h1 = __float2bfloat16(b);
        __nv_bfloat16 h2 = __float2bfloat16(c), h3 = __float2bfloat16(d);
        __nv_bfloat16 e0 = __float2bfloat16(a - __bfloat162float(h0));
        __nv_bfloat16 e1 = __float2bfloat16(b - __bfloat162float(h1));
        __nv_bfloat16 e2 = __float2bfloat16(c - __bfloat162float(h2));
        __nv_bfloat16 e3 = __float2bfloat16(d - __bfloat162float(h3));
        uint2 H, L;
        H.x = ((uint32_t)__bfloat16_as_ushort(h1) << 16) | __bfloat16_as_ushort(h0);
        H.y = ((uint32_t)__bfloat16_as_ushort(h3) << 16) | __bfloat16_as_ushort(h2);
        L.x = ((uint32_t)__bfloat16_as_ushort(e1) << 16) | __bfloat16_as_ushort(e0);
        L.y = ((uint32_t)__bfloat16_as_ushort(e3) << 16) | __bfloat16_as_ushort(e2);
        size_t idx = ((size_t)(j0 + j) * D_ + k0 + k4) >> 2;
        dh[idx] = H;
        dl[idx] = L;
    }
}

// ---------------- tensor-core GEMM via mma.sync (bf16 hi/lo, fp32 acc) ----------------
// grid (8 j, 8 i, 3 mats), 256 thr (8 warps; warp tile 64m x 32n).
// mat 0: g_qt[j][i] = roi@Wq + bq; mat 1: g_kt = ref@Wk + bk; mat 2: g_v[i][j] = ref@Wv^T.
#define OFF_AH 0
#define OFF_AL 16384
#define OFF_BH 32768
#define OFF_BL 49152
#define TC_SMEM (128 * 132 * 4)   // 67584 (>= 65536 operand area)

__global__ __launch_bounds__(256) void tc_gemm(const float* __restrict__ bq,
                                               const float* __restrict__ bk) {
    extern __shared__ char smem[];
    const uint32_t sb = smem_to_u32(smem);
    const int t = threadIdx.x;
    const int wid = t >> 5, lane = t & 31;
    const int j0 = blockIdx.x * 128, i0 = blockIdx.y * 128;
    const int mat = blockIdx.z;

    const uint4* Ah;
    const uint4* Al;
    const uint4* Bh;
    const uint4* Bl;
    if (mat == 0)      { Ah = (const uint4*)g_roiH; Al = (const uint4*)g_roiL; Bh = (const uint4*)g_wqtH; Bl = (const uint4*)g_wqtL; }
    else if (mat == 1) { Ah = (const uint4*)g_refH; Al = (const uint4*)g_refL; Bh = (const uint4*)g_wktH; Bl = (const uint4*)g_wktL; }
    else               { Ah = (const uint4*)g_refH; Al = (const uint4*)g_refL; Bh = (const uint4*)g_wvH;  Bl = (const uint4*)g_wvL; }

    const int wm = wid & 1, wn = wid >> 1;    // warp tile origin: (wm*64, wn*32)
    const int lr = lane & 7, lq = lane >> 3;

    float d[4][4][4];
#pragma unroll
    for (int a = 0; a < 4; a++)
#pragma unroll
        for (int b = 0; b < 4; b++)
#pragma unroll
            for (int c = 0; c < 4; c++) d[a][b][c] = 0.0f;

    // precomputed ldmatrix lane-address offsets (within a 128x64bf16 SW128 tile)
    const uint32_t a_off0 = (uint32_t)((wm*64 + (lq & 1)*8 + lr) * 128 + (lq >> 1) * 16);
    const uint32_t b_off0 = (uint32_t)((wn*32 + lr) * 128 + (lq & 1) * 16);

    for (int ch = 0; ch < 16; ch++) {
        __syncthreads();   // prior chunk's ldmatrix reads complete
#pragma unroll
        for (int it = 0; it < 4; it++) {
            int idx = it * 256 + t;
            int row = idx >> 3, u = idx & 7;
            uint32_t so = SWZ((uint32_t)(row * 128 + u * 16));
            size_t gi = (size_t)(i0 + row) * 128 + ch * 8 + u;
            size_t gj = (size_t)(j0 + row) * 128 + ch * 8 + u;
            *(uint4*)(smem + OFF_AH + so) = Ah[gi];
            *(uint4*)(smem + OFF_AL + so) = Al[gi];
            *(uint4*)(smem + OFF_BH + so) = Bh[gj];
            *(uint4*)(smem + OFF_BL + so) = Bl[gj];
        }
        __syncthreads();

#pragma unroll
        for (int ks = 0; ks < 4; ks++) {
            const uint32_t kb = (uint32_t)(ks * 32);   // 16 bf16 = 32 bytes
            uint32_t ah[4][4], al[4][4], bh[4][2], bl[4][2];
#pragma unroll
            for (int ma = 0; ma < 4; ma++) {
                uint32_t off = SWZ(a_off0 + (uint32_t)(ma * 16 * 128) + kb);
                ldsm_x4(ah[ma], sb + OFF_AH + off);
                ldsm_x4(al[ma], sb + OFF_AL + off);
            }
#pragma unroll
            for (int na = 0; na < 4; na++) {
                uint32_t off = SWZ(b_off0 + (uint32_t)(na * 8 * 128) + kb);
                ldsm_x2(bh[na], sb + OFF_BH + off);
                ldsm_x2(bl[na], sb + OFF_BL + off);
            }
#pragma unroll
            for (int ma = 0; ma < 4; ma++)
#pragma unroll
                for (int na = 0; na < 4; na++) {
                    mma16816(d[ma][na], ah[ma], bh[na]);
                    mma16816(d[ma][na], ah[ma], bl[na]);
                    mma16816(d[ma][na], al[ma], bh[na]);
                }
        }
    }

    __syncthreads();
    // stage D in smem: sd[128 i][132] cols j
    float* sd = (float*)smem;
    const int gid = lane >> 2, tig = lane & 3;
#pragma unroll
    for (int ma = 0; ma < 4; ma++)
#pragma unroll
        for (int na = 0; na < 4; na++) {
            int row = wm * 64 + ma * 16 + gid;
            int col = wn * 32 + na * 8 + 2 * tig;
            sd[row * 132 + col]           = d[ma][na][0];
            sd[row * 132 + col + 1]       = d[ma][na][1];
            sd[(row + 8) * 132 + col]     = d[ma][na][2];
            sd[(row + 8) * 132 + col + 1] = d[ma][na][3];
        }
    __syncthreads();

    if (mat != 2) {
        const float* bias = (mat == 0) ? bq : bk;
        float* dst = (mat == 0) ? g_qt : g_kt;
        int j = t >> 1, mh = (t & 1) * 64;
        float bb = bias[j0 + j];
#pragma unroll
        for (int mm = 0; mm < 64; mm += 4) {
            float4 v;
            v.x = sd[(mh + mm + 0) * 132 + j] + bb;
            v.y = sd[(mh + mm + 1) * 132 + j] + bb;
            v.z = sd[(mh + mm + 2) * 132 + j] + bb;
            v.w = sd[(mh + mm + 3) * 132 + j] + bb;
            *(float4*)&dst[(size_t)(j0 + j) * N_ + i0 + mh + mm] = v;
        }
    } else {
        int m = t >> 1, jh = (t & 1) * 64;
#pragma unroll
        for (int jj = 0; jj < 64; jj += 4) {
            float4 v = *(const float4*)&sd[m * 132 + jh + jj];
            *(float4*)&g_v[(size_t)(i0 + m) * D_ + j0 + jh + jj] = v;
        }
    }
}

// ---------------- position-weight kernel: 2 m per thread, transposed weights ----------------
__global__ __launch_bounds__(256, 2) void posw_kernel(const float* __restrict__ Wg,
                                                      const float* __restrict__ bg) {
    __shared__ float wgt[64][16];
    __shared__ float bgs[G_];
    const int t = threadIdx.x;
#pragma unroll
    for (int i = t; i < 1024; i += 256) {
        int g = i >> 6, e = i & 63;
        wgt[e][g] = Wg[i];
    }
    if (t < G_) bgs[t] = bg[t];
    __syncthreads();

    const int n = blockIdx.y;
    const int m0 = blockIdx.x * 512 + t;
    const int m1 = m0 + 256;

    u64 acc0[8], acc1[8];
#pragma unroll
    for (int gp = 0; gp < 8; gp++) {
        u64 b2 = pack2(bgs[2*gp], bgs[2*gp+1]);
        acc0[gp] = b2;
        acc1[gp] = b2;
    }

    auto upd = [&](int e, float v0, float v1) {
        const ulonglong2* wr = (const ulonglong2*)&wgt[e][0];
        ulonglong2 wa = wr[0], wb = wr[1];
        u64 d0 = dup2(v0), d1 = dup2(v1);
        fma2(acc0[0], d0, wa.x); fma2(acc1[0], d1, wa.x);
        fma2(acc0[1], d0, wa.y); fma2(acc1[1], d1, wa.y);
        fma2(acc0[2], d0, wb.x); fma2(acc1[2], d1, wb.x);
        fma2(acc0[3], d0, wb.y); fma2(acc1[3], d1, wb.y);
        ulonglong2 wc = wr[2], wd = wr[3];
        fma2(acc0[4], d0, wc.x); fma2(acc1[4], d1, wc.x);
        fma2(acc0[5], d0, wc.y); fma2(acc1[5], d1, wc.y);
        fma2(acc0[6], d0, wd.x); fma2(acc1[6], d1, wd.x);
        fma2(acc0[7], d0, wd.y); fma2(acc1[7], d1, wd.y);
    };

    const float4 bn = *(const float4*)&g_boxA[n * 4];
    const float4 bm0 = *(const float4*)&g_boxB[m0 * 4];
    const float4 bm1 = *(const float4*)&g_boxB[m1 * 4];

    {
        float px0 = __logf(fabsf(bn.x - bm0.x) * bn.z + 1e-3f);
        float px1 = __logf(fabsf(bn.x - bm1.x) * bn.z + 1e-3f);
#pragma unroll
        for (int f = 0; f < 8; f++) {
            float s0, c0, s1, c1;
            __sincosf(px0 * c_cf[f], &s0, &c0);
            __sincosf(px1 * c_cf[f], &s1, &c1);
            upd(f, s0, s1);
            upd(8 + f, c0, c1);
        }
        float py0 = __logf(fabsf(bn.y - bm0.y) * bn.w + 1e-3f);
        float py1 = __logf(fabsf(bn.y - bm1.y) * bn.w + 1e-3f);
#pragma unroll
        for (int f = 0; f < 8; f++) {
            float s0, c0, s1, c1;
            __sincosf(py0 * c_cf[f], &s0, &c0);
            __sincosf(py1 * c_cf[f], &s1, &c1);
            upd(16 + f, s0, s1);
            upd(24 + f, c0, c1);
        }
    }

#pragma unroll
    for (int f = 0; f < 8; f++) {
        float snf = g_trigA[n*32 + f], cnf = g_trigA[n*32 + 8 + f];
        float sm0 = g_trigBt[f*M_ + m0], cm0 = g_trigBt[(8+f)*M_ + m0];
        float sm1 = g_trigBt[f*M_ + m1], cm1 = g_trigBt[(8+f)*M_ + m1];
        upd(32 + f, snf*cm0 - cnf*sm0, snf*cm1 - cnf*sm1);
        upd(40 + f, fmaf(cnf, cm0, snf*sm0), fmaf(cnf, cm1, snf*sm1));
    }
#pragma unroll
    for (int f = 0; f < 8; f++) {
        float snf = g_trigA[n*32 + 16 + f], cnf = g_trigA[n*32 + 24 + f];
        float sm0 = g_trigBt[(16+f)*M_ + m0], cm0 = g_trigBt[(24+f)*M_ + m0];
        float sm1 = g_trigBt[(16+f)*M_ + m1], cm1 = g_trigBt[(24+f)*M_ + m1];
        upd(48 + f, snf*cm0 - cnf*sm0, snf*cm1 - cnf*sm1);
        upd(56 + f, fmaf(cnf, cm0, snf*sm0), fmaf(cnf, cm1, snf*sm1));
    }

    const size_t base = (size_t)n * G_ * M_;
#pragma unroll
    for (int gp = 0; gp < 8; gp++) {
        float x0, y0, x1, y1;
        unpack2(acc0[gp], x0, y0);
        unpack2(acc1[gp], x1, y1);
        g_w[base + (size_t)(2*gp)   * M_ + m0] = fmaxf(x0, 0.0f) + 1e-6f;
        g_w[base + (size_t)(2*gp+1) * M_ + m0] = fmaxf(y0, 0.0f) + 1e-6f;
        g_w[base + (size_t)(2*gp)   * M_ + m1] = fmaxf(x1, 0.0f) + 1e-6f;
        g_w[base + (size_t)(2*gp+1) * M_ + m1] = fmaxf(y1, 0.0f) + 1e-6f;
    }
}

// ---------------- fused attention: 128n x 64m tiles, f32x2 micro, M-split8 ----------------
__global__ __launch_bounds__(256, 2) void flash_kernel() {
    extern __shared__ float smemf[];
    float(*qs)[128] = (float(*)[128])smemf;
    float(*ks)[64]  = (float(*)[64])(smemf + 64 * 128);
    float(*vs)[64]  = (float(*)[64])(smemf + 64*128 + 64*64);
    float(*ps)[128] = (float(*)[128])(smemf + 64*128 + 2*64*64);

    const int t = threadIdx.x;
    const int tx = t & 15, ty = t >> 4;
    const int g = blockIdx.y;
    const int n0 = blockIdx.x * 128;
    const int z = blockIdx.z;

#pragma unroll
    for (int it = 0; it < 8; it++) {
        int idx = it * 256 + t;
        int d = idx >> 5, r4 = (idx & 31) << 2;
        *(float4*)&qs[d][r4] = *(const float4*)&g_qt[(size_t)(g*64 + d) * N_ + n0 + r4];
    }

    u64 acc2[4][4];
#pragma unroll
    for (int a = 0; a < 4; a++)
#pragma unroll
        for (int b = 0; b < 4; b++) acc2[a][b] = 0ull;
    float lrun[8] = {};

    for (int mi = 0; mi < 2; mi++) {
        const int m0 = (z * 2 + mi) * 64;
        __syncthreads();
#pragma unroll
        for (int it = 0; it < 4; it++) {
            int idx = it * 256 + t;
            int d = idx >> 4, m4 = (idx & 15) << 2;
            *(float4*)&ks[d][m4] = *(const float4*)&g_kt[(size_t)(g*64 + d) * M_ + m0 + m4];
        }
#pragma unroll
        for (int it = 0; it < 4; it++) {
            int idx = it * 256 + t;
            int m = idx >> 4, o4 = (idx & 15) << 2;
            *(float4*)&vs[m][o4] = *(const float4*)&g_v[(size_t)(m0 + m) * D_ + g*64 + o4];
        }
        __syncthreads();

        u64 s2[4][4];
#pragma unroll
        for (int a = 0; a < 4; a++)
#pragma unroll
            for (int b = 0; b < 4; b++) s2[a][b] = 0ull;

#pragma unroll 8
        for (int d = 0; d < 64; d++) {
            ulonglong2 A0 = *(const ulonglong2*)&qs[d][ty * 8];
            ulonglong2 A1 = *(const ulonglong2*)&qs[d][ty * 8 + 4];
            u64 pa[4] = {A0.x, A0.y, A1.x, A1.y};
            float4 b4 = *(const float4*)&ks[d][tx * 4];
            u64 bd[4] = {dup2(b4.x), dup2(b4.y), dup2(b4.z), dup2(b4.w)};
#pragma unroll
            for (int rp = 0; rp < 4; rp++)
#pragma unroll
                for (int jm = 0; jm < 4; jm++)
                    fma2(s2[rp][jm], pa[rp], bd[jm]);
        }

#pragma unroll
        for (int rp = 0; rp < 4; rp++) {
            const int r0 = ty * 8 + 2 * rp;
            float4 w0 = *(const float4*)&g_w[((size_t)(n0 + r0) * G_ + g) * M_ + m0 + tx * 4];
            float4 w1 = *(const float4*)&g_w[((size_t)(n0 + r0 + 1) * G_ + g) * M_ + m0 + tx * 4];
            float wl[4] = {w0.x, w0.y, w0.z, w0.w};
            float wh[4] = {w1.x, w1.y, w1.z, w1.w};
#pragma unroll
            for (int jm = 0; jm < 4; jm++) {
                float a0, a1;
                unpack2(s2[rp][jm], a0, a1);
                float p0 = wl[jm] * fast_exp(a0 * 0.125f);
                float p1 = wh[jm] * fast_exp(a1 * 0.125f);
                lrun[2*rp]   += p0;
                lrun[2*rp+1] += p1;
                s2[rp][jm] = pack2(p0, p1);
            }
        }
#pragma unroll
        for (int jm = 0; jm < 4; jm++) {
            ulonglong2 v0; v0.x = s2[0][jm]; v0.y = s2[1][jm];
            ulonglong2 v1; v1.x = s2[2][jm]; v1.y = s2[3][jm];
            *(ulonglong2*)&ps[tx * 4 + jm][ty * 8] = v0;
            *(ulonglong2*)&ps[tx * 4 + jm][ty * 8 + 4] = v1;
        }
        __syncthreads();

#pragma unroll 4
        for (int m = 0; m < 64; m++) {
            ulonglong2 P0 = *(const ulonglong2*)&ps[m][ty * 8];
            ulonglong2 P1 = *(const ulonglong2*)&ps[m][ty * 8 + 4];
            u64 pp[4] = {P0.x, P0.y, P1.x, P1.y};
            float4 v4 = *(const float4*)&vs[m][tx * 4];
            u64 vd[4] = {dup2(v4.x), dup2(v4.y), dup2(v4.z), dup2(v4.w)};
#pragma unroll
            for (int rp = 0; rp < 4; rp++)
#pragma unroll
                for (int o = 0; o < 4; o++)
                    fma2(acc2[rp][o], pp[rp], vd[o]);
        }
    }

    const int col = g * 64 + tx * 4;
#pragma unroll
    for (int rp = 0; rp < 4; rp++) {
        float a0[4], a1[4];
#pragma unroll
        for (int o = 0; o < 4; o++) unpack2(acc2[rp][o], a0[o], a1[o]);
        const int r0 = n0 + ty * 8 + 2 * rp;
        *(float4*)&g_pacc[z][(size_t)r0 * D_ + col]       = make_float4(a0[0], a0[1], a0[2], a0[3]);
        *(float4*)&g_pacc[z][(size_t)(r0 + 1) * D_ + col] = make_float4(a1[0], a1[1], a1[2], a1[3]);
    }
#pragma unroll
    for (int r = 0; r < 8; r++) {
        float l = lrun[r];
#pragma unroll
        for (int off = 1; off < 16; off <<= 1)
            l += __shfl_xor_sync(0xffffffffu, l, off, 16);
        if (tx == 0) g_pl[z][(size_t)(n0 + ty * 8 + r) * G_ + g] = l;
    }
}

// ---------------- combine 8 partials ----------------
__global__ __launch_bounds__(256) void reduce_kernel(const float* __restrict__ bv,
                                                     float* __restrict__ out) {
    int idx = blockIdx.x * 256 + threadIdx.x;
    int n = idx >> 8;
    int col = (idx & 255) << 2;
    int g = col >> 6;
    float l = 0.0f;
    float4 a = make_float4(0.f, 0.f, 0.f, 0.f);
#pragma unroll
    for (int zz = 0; zz < SPLITS; zz++) {
        l += g_pl[zz][(size_t)n * G_ + g];
        float4 p = *(const float4*)&g_pacc[zz][(size_t)n * D_ + col];
        a.x += p.x; a.y += p.y; a.z += p.z; a.w += p.w;
    }
    float inv = 1.0f / l;
    float4 b4 = *(const float4*)&bv[col];
    float4 o;
    o.x = fmaf(a.x, inv, b4.x);
    o.y = fmaf(a.y, inv, b4.y);
    o.z = fmaf(a.z, inv, b4.z);
    o.w = fmaf(a.w, inv, b4.w);
    *(float4*)&out[(size_t)n * D_ + col] = o;
}

// ---------------- host launcher ----------------
extern "C" void kernel_launch(void* const* d_in, const int* in_sizes, int n_in,
                              void* d_out, int out_size) {
    const float* roi   = (const float*)d_in[0];
    const float* ref   = (const float*)d_in[1];
    const float* rois1 = (const float*)d_in[2];
    const float* rois2 = (const float*)d_in[3];
    const float* Wq    = (const float*)d_in[4];
    const float* bq    = (const float*)d_in[5];
    const float* Wk    = (const float*)d_in[6];
    const float* bk    = (const float*)d_in[7];
    const float* Wg    = (const float*)d_in[8];
    const float* bg    = (const float*)d_in[9];
    const float* Wv    = (const float*)d_in[10];
    const float* bv    = (const float*)d_in[11];
    float* out = (float*)d_out;

    const int FLASH_SMEM = (64*128 + 64*64 + 64*64 + 64*128) * (int)sizeof(float); // 98304
    static bool attr_set = false;
    if (!attr_set) {
        cudaFuncSetAttribute(flash_kernel, cudaFuncAttributeMaxDynamicSharedMemorySize, FLASH_SMEM);
        cudaFuncSetAttribute(tc_gemm, cudaFuncAttributeMaxDynamicSharedMemorySize, TC_SMEM);
        attr_set = true;
    }

    box_prep<<<4, 256>>>(rois1, rois2);
    conv_a<<<dim3(1024, 3), 256>>>(roi, ref, Wv);
    conv_w<<<dim3(16, 16, 2), 256>>>(Wq, Wk);
    tc_gemm<<<dim3(8, 8, 3), 256, TC_SMEM>>>(bq, bk);
    posw_kernel<<<dim3(2, 1024), 256>>>(Wg, bg);
    flash_kernel<<<dim3(8, 16, 8), 256, FLASH_SMEM>>>();
    reduce_kernel<<<1024, 256>>>(bv, out);
}

// round 9
// speedup vs baseline: 1.7921x; 1.0124x over previous
#include <cuda_runtime.h>
#include <cuda_bf16.h>
#include <math.h>
#include <stdint.h>

#define N_ 1024
#define M_ 1024
#define D_ 1024
#define G_ 16
#define DG_ 64
#define SPLITS 8

typedef unsigned long long u64;

// ---------------- scratch ----------------
__device__ float g_qt[(size_t)D_ * N_];          // q transposed: [d_global][n]
__device__ float g_kt[(size_t)D_ * M_];          // k transposed: [d_global][m]
__device__ float g_v [(size_t)M_ * D_];          // [m][g*64+o]
__device__ float g_w[(size_t)N_ * G_ * M_];      // (N, G, M)
__device__ float g_boxA[N_ * 4];
__device__ float g_boxB[M_ * 4];
__device__ float g_trigA[N_ * 32];
__device__ float g_trigBt[32 * M_];
__device__ float g_pacc[SPLITS][(size_t)N_ * D_];
__device__ float g_pl[SPLITS][(size_t)N_ * G_];

// bf16 hi/lo operand buffers
#define MEG (1024 * 1024)
__device__ __align__(16) uint16_t g_roiH[MEG], g_roiL[MEG];
__device__ __align__(16) uint16_t g_refH[MEG], g_refL[MEG];
__device__ __align__(16) uint16_t g_wvH[MEG],  g_wvL[MEG];
__device__ __align__(16) uint16_t g_wqtH[MEG], g_wqtL[MEG];   // Wq^T [j][k]
__device__ __align__(16) uint16_t g_wktH[MEG], g_wktL[MEG];   // Wk^T [j][k]

// ---------------- f32x2 helpers ----------------
__device__ __forceinline__ void fma2(u64& d, u64 a, u64 b) {
    asm("fma.rn.f32x2 %0, %1, %2, %0;" : "+l"(d) : "l"(a), "l"(b));
}
__device__ __forceinline__ u64 pack2(float x, float y) {
    u64 r;
    asm("mov.b64 %0, {%1, %2};" : "=l"(r) : "f"(x), "f"(y));
    return r;
}
__device__ __forceinline__ void unpack2(u64 p, float& x, float& y) {
    asm("mov.b64 {%0, %1}, %2;" : "=f"(x), "=f"(y) : "l"(p));
}
__device__ __forceinline__ u64 dup2(float x) { return pack2(x, x); }

__device__ __forceinline__ float fast_exp(float x) {
    float t = x * 1.4426950408889634f;
    t = fminf(fmaxf(t, -120.0f), 120.0f);
    float fi = floorf(t);
    float f = t - fi;
    float p = 1.5403530393e-4f;
    p = fmaf(p, f, 1.3333558146e-3f);
    p = fmaf(p, f, 9.6181291076e-3f);
    p = fmaf(p, f, 5.5504108664e-2f);
    p = fmaf(p, f, 2.4022650696e-1f);
    p = fmaf(p, f, 6.9314718056e-1f);
    p = fmaf(p, f, 1.0f);
    return p * __int_as_float(((int)fi + 127) << 23);
}

__constant__ float c_cf[8] = {100.0f, 42.169650f, 17.782794f, 7.4989421f,
                              3.1622776f, 1.3335214f, 0.56234133f, 0.23713737f};

// ---------------- warp-mma helpers (baseline PTX) ----------------
__device__ __forceinline__ uint32_t smem_to_u32(const void* p) {
    uint32_t a;
    asm("{ .reg .u64 t; cvta.to.shared.u64 t, %1; cvt.u32.u64 %0, t; }" : "=r"(a) : "l"(p));
    return a;
}
__device__ __forceinline__ void mma16816(float* d, const uint32_t* a, const uint32_t* b) {
    asm volatile(
        "mma.sync.aligned.m16n8k16.row.col.f32.bf16.bf16.f32 "
        "{%0,%1,%2,%3}, {%4,%5,%6,%7}, {%8,%9}, {%0,%1,%2,%3};"
        : "+f"(d[0]), "+f"(d[1]), "+f"(d[2]), "+f"(d[3])
        : "r"(a[0]), "r"(a[1]), "r"(a[2]), "r"(a[3]), "r"(b[0]), "r"(b[1]));
}
__device__ __forceinline__ void ldsm_x4(uint32_t* r, uint32_t addr) {
    asm volatile("ldmatrix.sync.aligned.m8n8.x4.shared.b16 {%0,%1,%2,%3}, [%4];"
                 : "=r"(r[0]), "=r"(r[1]), "=r"(r[2]), "=r"(r[3]) : "r"(addr));
}
__device__ __forceinline__ void ldsm_x2(uint32_t* r, uint32_t addr) {
    asm volatile("ldmatrix.sync.aligned.m8n8.x2.shared.b16 {%0,%1}, [%2];"
                 : "=r"(r[0]), "=r"(r[1]) : "r"(addr));
}
__device__ __forceinline__ void cp16(uint32_t saddr, const void* gptr) {
    asm volatile("cp.async.cg.shared.global [%0], [%1], 16;" :: "r"(saddr), "l"(gptr));
}
#define CP_COMMIT() asm volatile("cp.async.commit_group;" ::: "memory")
#define SWZ(bo) ((bo) ^ (((bo) >> 3) & 0x70))

// ---------------- box prep ----------------
__global__ void box_prep(const float* __restrict__ rois1, const float* __restrict__ rois2) {
    int i = blockIdx.x * blockDim.x + threadIdx.x;
    if (i >= N_) return;
    {
        float xmin = rois1[i*4+0], ymin = rois1[i*4+1], xmax = rois1[i*4+2], ymax = rois1[i*4+3];
        float w = xmax - xmin + 1.0f, h = ymax - ymin + 1.0f;
        g_boxA[i*4+0] = 0.5f*(xmin+xmax); g_boxA[i*4+1] = 0.5f*(ymin+ymax);
        g_boxA[i*4+2] = 1.0f/w;           g_boxA[i*4+3] = 1.0f/h;
        float lw = logf(w), lh = logf(h);
#pragma unroll
        for (int f = 0; f < 8; f++) {
            float s, c;
            sincosf(lw * c_cf[f], &s, &c);
            g_trigA[i*32 + f] = s;      g_trigA[i*32 + 8 + f] = c;
            sincosf(lh * c_cf[f], &s, &c);
            g_trigA[i*32 + 16 + f] = s; g_trigA[i*32 + 24 + f] = c;
        }
    }
    {
        float xmin = rois2[i*4+0], ymin = rois2[i*4+1], xmax = rois2[i*4+2], ymax = rois2[i*4+3];
        float w = xmax - xmin + 1.0f, h = ymax - ymin + 1.0f;
        g_boxB[i*4+0] = 0.5f*(xmin+xmax); g_boxB[i*4+1] = 0.5f*(ymin+ymax);
        g_boxB[i*4+2] = 1.0f/w;           g_boxB[i*4+3] = 1.0f/h;
        float lw = logf(w), lh = logf(h);
#pragma unroll
        for (int f = 0; f < 8; f++) {
            float s, c;
            sincosf(lw * c_cf[f], &s, &c);
            g_trigBt[f*M_ + i] = s;        g_trigBt[(8+f)*M_ + i] = c;
            sincosf(lh * c_cf[f], &s, &c);
            g_trigBt[(16+f)*M_ + i] = s;   g_trigBt[(24+f)*M_ + i] = c;
        }
    }
}

// ---------------- fp32 -> bf16 hi/lo (row-major tensors) ----------------
__global__ __launch_bounds__(256) void conv_a(const float* __restrict__ roi,
                                              const float* __restrict__ ref,
                                              const float* __restrict__ wv) {
    const int z = blockIdx.y;
    const float4* src = (const float4*)(z == 0 ? roi : z == 1 ? ref : wv);
    uint2* dh = (uint2*)(z == 0 ? g_roiH : z == 1 ? g_refH : g_wvH);
    uint2* dl = (uint2*)(z == 0 ? g_roiL : z == 1 ? g_refL : g_wvL);
    int i = blockIdx.x * 256 + threadIdx.x;
    float4 x = src[i];
    __nv_bfloat16 h0 = __float2bfloat16(x.x), h1 = __float2bfloat16(x.y);
    __nv_bfloat16 h2 = __float2bfloat16(x.z), h3 = __float2bfloat16(x.w);
    __nv_bfloat16 e0 = __float2bfloat16(x.x - __bfloat162float(h0));
    __nv_bfloat16 e1 = __float2bfloat16(x.y - __bfloat162float(h1));
    __nv_bfloat16 e2 = __float2bfloat16(x.z - __bfloat162float(h2));
    __nv_bfloat16 e3 = __float2bfloat16(x.w - __bfloat162float(h3));
    uint2 H, L;
    H.x = ((uint32_t)__bfloat16_as_ushort(h1) << 16) | __bfloat16_as_ushort(h0);
    H.y = ((uint32_t)__bfloat16_as_ushort(h3) << 16) | __bfloat16_as_ushort(h2);
    L.x = ((uint32_t)__bfloat16_as_ushort(e1) << 16) | __bfloat16_as_ushort(e0);
    L.y = ((uint32_t)__bfloat16_as_ushort(e3) << 16) | __bfloat16_as_ushort(e2);
    dh[i] = H;
    dl[i] = L;
}

// ---------------- Wq/Wk transpose + bf16 hi/lo: W[k][j] -> Wt[j][k] ----------------
__global__ __launch_bounds__(256) void conv_w(const float* __restrict__ Wq,
                                              const float* __restrict__ Wk) {
    __shared__ float ts[64][65];
    const int z = blockIdx.z;
    const float* W = z ? Wk : Wq;
    uint2* dh = (uint2*)(z ? g_wktH : g_wqtH);
    uint2* dl = (uint2*)(z ? g_wktL : g_wqtL);
    const int j0 = blockIdx.x * 64, k0 = blockIdx.y * 64;
    const int t = threadIdx.x;
#pragma unroll
    for (int it = 0; it < 4; it++) {
        int lin = it * 256 + t;
        int k = lin >> 4, j4 = (lin & 15) << 2;
        float4 v = *(const float4*)&W[(size_t)(k0 + k) * D_ + j0 + j4];
        ts[j4 + 0][k] = v.x; ts[j4 + 1][k] = v.y; ts[j4 + 2][k] = v.z; ts[j4 + 3][k] = v.w;
    }
    __syncthreads();
#pragma unroll
    for (int it = 0; it < 4; it++) {
        int lin = it * 256 + t;
        int j = lin >> 4, k4 = (lin & 15) << 2;
        float a = ts[j][k4 + 0], b = ts[j][k4 + 1], c = ts[j][k4 + 2], d = ts[j][k4 + 3];
        __nv_bfloat16 h0 = __float2bfloat16(a), h1 = __float2bfloat16(b);
        __nv_bfloat16 h2 = __float2bfloat16(c), h3 = __float2bfloat16(d);
        __nv_bfloat16 e0 = __float2bfloat16(a - __bfloat162float(h0));
        __nv_bfloat16 e1 = __float2bfloat16(b - __bfloat162float(h1));
        __nv_bfloat16 e2 = __float2bfloat16(c - __bfloat162float(h2));
        __nv_bfloat16 e3 = __float2bfloat16(d - __bfloat162float(h3));
        uint2 H, L;
        H.x = ((uint32_t)__bfloat16_as_ushort(h1) << 16) | __bfloat16_as_ushort(h0);
        H.y = ((uint32_t)__bfloat16_as_ushort(h3) << 16) | __bfloat16_as_ushort(h2);
        L.x = ((uint32_t)__bfloat16_as_ushort(e1) << 16) | __bfloat16_as_ushort(e0);
        L.y = ((uint32_t)__bfloat16_as_ushort(e3) << 16) | __bfloat16_as_ushort(e2);
        size_t idx = ((size_t)(j0 + j) * D_ + k0 + k4) >> 2;
        dh[idx] = H;
        dl[idx] = L;
    }
}

// ---------------- tensor-core GEMM, cp.async double-buffered ----------------
// grid (8 j, 8 i, 3 mats), 256 thr (8 warps; warp tile 64m x 32n).
#define OFF_AH 0
#define OFF_AL 16384
#define OFF_BH 32768
#define OFF_BL 49152
#define STAGE_BYTES 65536
#define TC_SMEM (2 * STAGE_BYTES)   // 131072

__global__ __launch_bounds__(256) void tc_gemm(const float* __restrict__ bq,
                                               const float* __restrict__ bk) {
    extern __shared__ char smem[];
    const uint32_t sb = smem_to_u32(smem);
    const int t = threadIdx.x;
    const int wid = t >> 5, lane = t & 31;
    const int j0 = blockIdx.x * 128, i0 = blockIdx.y * 128;
    const int mat = blockIdx.z;

    const uint16_t* Ah;
    const uint16_t* Al;
    const uint16_t* Bh;
    const uint16_t* Bl;
    if (mat == 0)      { Ah = g_roiH; Al = g_roiL; Bh = g_wqtH; Bl = g_wqtL; }
    else if (mat == 1) { Ah = g_refH; Al = g_refL; Bh = g_wktH; Bl = g_wktL; }
    else               { Ah = g_refH; Al = g_refL; Bh = g_wvH;  Bl = g_wvL; }

    const int wm = wid & 1, wn = wid >> 1;    // warp tile origin: (wm*64, wn*32)
    const int lr = lane & 7, lq = lane >> 3;

    float d[4][4][4];
#pragma unroll
    for (int a = 0; a < 4; a++)
#pragma unroll
        for (int b = 0; b < 4; b++)
#pragma unroll
            for (int c = 0; c < 4; c++) d[a][b][c] = 0.0f;

    // ldmatrix lane-address offsets (within a 128x64bf16 SW128 tile)
    const uint32_t a_off0 = (uint32_t)((wm*64 + (lq & 1)*8 + lr) * 128 + (lq >> 1) * 16);
    const uint32_t b_off0 = (uint32_t)((wn*32 + lr) * 128 + (lq & 1) * 16);

    // per-thread cp.async indices: 4 rows x (A hi/lo, B hi/lo)
    const int crow = t >> 1, cu = (t & 1) << 2;    // row 0..127, u 0/4 (two 16B each x4 below)

    auto loadChunk = [&](int ch, int stage) {
        const uint32_t sbase = sb + stage * STAGE_BYTES;
        // 128 rows x 8 u(16B) per tile; 256 thr -> each thread 4 u per tile
#pragma unroll
        for (int uu = 0; uu < 4; uu++) {
            int u = (cu + uu);
            uint32_t so = SWZ((uint32_t)(crow * 128 + u * 16));
            const uint16_t* gia = Ah + ((size_t)(i0 + crow) * 1024 + ch * 64 + u * 8);
            const uint16_t* gil = Al + ((size_t)(i0 + crow) * 1024 + ch * 64 + u * 8);
            const uint16_t* gjh = Bh + ((size_t)(j0 + crow) * 1024 + ch * 64 + u * 8);
            const uint16_t* gjl = Bl + ((size_t)(j0 + crow) * 1024 + ch * 64 + u * 8);
            cp16(sbase + OFF_AH + so, gia);
            cp16(sbase + OFF_AL + so, gil);
            cp16(sbase + OFF_BH + so, gjh);
            cp16(sbase + OFF_BL + so, gjl);
        }
    };

    loadChunk(0, 0);
    CP_COMMIT();

    for (int ch = 0; ch < 16; ch++) {
        if (ch + 1 < 16) {
            loadChunk(ch + 1, (ch + 1) & 1);
            CP_COMMIT();
            asm volatile("cp.async.wait_group 1;" ::: "memory");
        } else {
            asm volatile("cp.async.wait_group 0;" ::: "memory");
        }
        __syncthreads();

        const uint32_t st = sb + (ch & 1) * STAGE_BYTES;
#pragma unroll
        for (int ks = 0; ks < 4; ks++) {
            const uint32_t kb = (uint32_t)(ks * 32);   // 16 bf16 = 32 bytes
            uint32_t ah[4][4], al[4][4], bh[4][2], bl[4][2];
#pragma unroll
            for (int ma = 0; ma < 4; ma++) {
                uint32_t off = SWZ(a_off0 + (uint32_t)(ma * 16 * 128) + kb);
                ldsm_x4(ah[ma], st + OFF_AH + off);
                ldsm_x4(al[ma], st + OFF_AL + off);
            }
#pragma unroll
            for (int na = 0; na < 4; na++) {
                uint32_t off = SWZ(b_off0 + (uint32_t)(na * 8 * 128) + kb);
                ldsm_x2(bh[na], st + OFF_BH + off);
                ldsm_x2(bl[na], st + OFF_BL + off);
            }
            // reordered: all hh, then hl, then lh -> accumulator reuse distance 16
#pragma unroll
            for (int ma = 0; ma < 4; ma++)
#pragma unroll
                for (int na = 0; na < 4; na++)
                    mma16816(d[ma][na], ah[ma], bh[na]);
#pragma unroll
            for (int ma = 0; ma < 4; ma++)
#pragma unroll
                for (int na = 0; na < 4; na++)
                    mma16816(d[ma][na], ah[ma], bl[na]);
#pragma unroll
            for (int ma = 0; ma < 4; ma++)
#pragma unroll
                for (int na = 0; na < 4; na++)
                    mma16816(d[ma][na], al[ma], bh[na]);
        }
        __syncthreads();
    }

    // stage D in smem: sd[128 i][132] cols j
    float* sd = (float*)smem;
    const int gid = lane >> 2, tig = lane & 3;
#pragma unroll
    for (int ma = 0; ma < 4; ma++)
#pragma unroll
        for (int na = 0; na < 4; na++) {
            int row = wm * 64 + ma * 16 + gid;
            int col = wn * 32 + na * 8 + 2 * tig;
            sd[row * 132 + col]           = d[ma][na][0];
            sd[row * 132 + col + 1]       = d[ma][na][1];
            sd[(row + 8) * 132 + col]     = d[ma][na][2];
            sd[(row + 8) * 132 + col + 1] = d[ma][na][3];
        }
    __syncthreads();

    if (mat != 2) {
        const float* bias = (mat == 0) ? bq : bk;
        float* dst = (mat == 0) ? g_qt : g_kt;
        int j = t >> 1, mh = (t & 1) * 64;
        float bb = bias[j0 + j];
#pragma unroll
        for (int mm = 0; mm < 64; mm += 4) {
            float4 v;
            v.x = sd[(mh + mm + 0) * 132 + j] + bb;
            v.y = sd[(mh + mm + 1) * 132 + j] + bb;
            v.z = sd[(mh + mm + 2) * 132 + j] + bb;
            v.w = sd[(mh + mm + 3) * 132 + j] + bb;
            *(float4*)&dst[(size_t)(j0 + j) * N_ + i0 + mh + mm] = v;
        }
    } else {
        int m = t >> 1, jh = (t & 1) * 64;
#pragma unroll
        for (int jj = 0; jj < 64; jj += 4) {
            float4 v = *(const float4*)&sd[m * 132 + jh + jj];
            *(float4*)&g_v[(size_t)(i0 + m) * D_ + j0 + jh + jj] = v;
        }
    }
}

// ---------------- position-weight kernel: 2 m per thread, transposed weights ----------------
__global__ __launch_bounds__(256, 2) void posw_kernel(const float* __restrict__ Wg,
                                                      const float* __restrict__ bg) {
    __shared__ float wgt[64][16];
    __shared__ float bgs[G_];
    const int t = threadIdx.x;
#pragma unroll
    for (int i = t; i < 1024; i += 256) {
        int g = i >> 6, e = i & 63;
        wgt[e][g] = Wg[i];
    }
    if (t < G_) bgs[t] = bg[t];
    __syncthreads();

    const int n = blockIdx.y;
    const int m0 = blockIdx.x * 512 + t;
    const int m1 = m0 + 256;

    u64 acc0[8], acc1[8];
#pragma unroll
    for (int gp = 0; gp < 8; gp++) {
        u64 b2 = pack2(bgs[2*gp], bgs[2*gp+1]);
        acc0[gp] = b2;
        acc1[gp] = b2;
    }

    auto upd = [&](int e, float v0, float v1) {
        const ulonglong2* wr = (const ulonglong2*)&wgt[e][0];
        ulonglong2 wa = wr[0], wb = wr[1];
        u64 d0 = dup2(v0), d1 = dup2(v1);
        fma2(acc0[0], d0, wa.x); fma2(acc1[0], d1, wa.x);
        fma2(acc0[1], d0, wa.y); fma2(acc1[1], d1, wa.y);
        fma2(acc0[2], d0, wb.x); fma2(acc1[2], d1, wb.x);
        fma2(acc0[3], d0, wb.y); fma2(acc1[3], d1, wb.y);
        ulonglong2 wc = wr[2], wd = wr[3];
        fma2(acc0[4], d0, wc.x); fma2(acc1[4], d1, wc.x);
        fma2(acc0[5], d0, wc.y); fma2(acc1[5], d1, wc.y);
        fma2(acc0[6], d0, wd.x); fma2(acc1[6], d1, wd.x);
        fma2(acc0[7], d0, wd.y); fma2(acc1[7], d1, wd.y);
    };

    const float4 bn = *(const float4*)&g_boxA[n * 4];
    const float4 bm0 = *(const float4*)&g_boxB[m0 * 4];
    const float4 bm1 = *(const float4*)&g_boxB[m1 * 4];

    {
        float px0 = __logf(fabsf(bn.x - bm0.x) * bn.z + 1e-3f);
        float px1 = __logf(fabsf(bn.x - bm1.x) * bn.z + 1e-3f);
#pragma unroll
        for (int f = 0; f < 8; f++) {
            float s0, c0, s1, c1;
            __sincosf(px0 * c_cf[f], &s0, &c0);
            __sincosf(px1 * c_cf[f], &s1, &c1);
            upd(f, s0, s1);
            upd(8 + f, c0, c1);
        }
        float py0 = __logf(fabsf(bn.y - bm0.y) * bn.w + 1e-3f);
        float py1 = __logf(fabsf(bn.y - bm1.y) * bn.w + 1e-3f);
#pragma unroll
        for (int f = 0; f < 8; f++) {
            float s0, c0, s1, c1;
            __sincosf(py0 * c_cf[f], &s0, &c0);
            __sincosf(py1 * c_cf[f], &s1, &c1);
            upd(16 + f, s0, s1);
            upd(24 + f, c0, c1);
        }
    }

#pragma unroll
    for (int f = 0; f < 8; f++) {
        float snf = g_trigA[n*32 + f], cnf = g_trigA[n*32 + 8 + f];
        float sm0 = g_trigBt[f*M_ + m0], cm0 = g_trigBt[(8+f)*M_ + m0];
        float sm1 = g_trigBt[f*M_ + m1], cm1 = g_trigBt[(8+f)*M_ + m1];
        upd(32 + f, snf*cm0 - cnf*sm0, snf*cm1 - cnf*sm1);
        upd(40 + f, fmaf(cnf, cm0, snf*sm0), fmaf(cnf, cm1, snf*sm1));
    }
#pragma unroll
    for (int f = 0; f < 8; f++) {
        float snf = g_trigA[n*32 + 16 + f], cnf = g_trigA[n*32 + 24 + f];
        float sm0 = g_trigBt[(16+f)*M_ + m0], cm0 = g_trigBt[(24+f)*M_ + m0];
        float sm1 = g_trigBt[(16+f)*M_ + m1], cm1 = g_trigBt[(24+f)*M_ + m1];
        upd(48 + f, snf*cm0 - cnf*sm0, snf*cm1 - cnf*sm1);
        upd(56 + f, fmaf(cnf, cm0, snf*sm0), fmaf(cnf, cm1, snf*sm1));
    }

    const size_t base = (size_t)n * G_ * M_;
#pragma unroll
    for (int gp = 0; gp < 8; gp++) {
        float x0, y0, x1, y1;
        unpack2(acc0[gp], x0, y0);
        unpack2(acc1[gp], x1, y1);
        g_w[base + (size_t)(2*gp)   * M_ + m0] = fmaxf(x0, 0.0f) + 1e-6f;
        g_w[base + (size_t)(2*gp+1) * M_ + m0] = fmaxf(y0, 0.0f) + 1e-6f;
        g_w[base + (size_t)(2*gp)   * M_ + m1] = fmaxf(x1, 0.0f) + 1e-6f;
        g_w[base + (size_t)(2*gp+1) * M_ + m1] = fmaxf(y1, 0.0f) + 1e-6f;
    }
}

// ---------------- fused attention: 128n x 64m tiles, f32x2 micro, M-split8 ----------------
__global__ __launch_bounds__(256, 2) void flash_kernel() {
    extern __shared__ float smemf[];
    float(*qs)[128] = (float(*)[128])smemf;
    float(*ks)[64]  = (float(*)[64])(smemf + 64 * 128);
    float(*vs)[64]  = (float(*)[64])(smemf + 64*128 + 64*64);
    float(*ps)[128] = (float(*)[128])(smemf + 64*128 + 2*64*64);

    const int t = threadIdx.x;
    const int tx = t & 15, ty = t >> 4;
    const int g = blockIdx.y;
    const int n0 = blockIdx.x * 128;
    const int z = blockIdx.z;

#pragma unroll
    for (int it = 0; it < 8; it++) {
        int idx = it * 256 + t;
        int d = idx >> 5, r4 = (idx & 31) << 2;
        *(float4*)&qs[d][r4] = *(const float4*)&g_qt[(size_t)(g*64 + d) * N_ + n0 + r4];
    }

    u64 acc2[4][4];
#pragma unroll
    for (int a = 0; a < 4; a++)
#pragma unroll
        for (int b = 0; b < 4; b++) acc2[a][b] = 0ull;
    float lrun[8] = {};

    for (int mi = 0; mi < 2; mi++) {
        const int m0 = (z * 2 + mi) * 64;
        __syncthreads();
#pragma unroll
        for (int it = 0; it < 4; it++) {
            int idx = it * 256 + t;
            int d = idx >> 4, m4 = (idx & 15) << 2;
            *(float4*)&ks[d][m4] = *(const float4*)&g_kt[(size_t)(g*64 + d) * M_ + m0 + m4];
        }
#pragma unroll
        for (int it = 0; it < 4; it++) {
            int idx = it * 256 + t;
            int m = idx >> 4, o4 = (idx & 15) << 2;
            *(float4*)&vs[m][o4] = *(const float4*)&g_v[(size_t)(m0 + m) * D_ + g*64 + o4];
        }
        __syncthreads();

        u64 s2[4][4];
#pragma unroll
        for (int a = 0; a < 4; a++)
#pragma unroll
            for (int b = 0; b < 4; b++) s2[a][b] = 0ull;

#pragma unroll 8
        for (int d = 0; d < 64; d++) {
            ulonglong2 A0 = *(const ulonglong2*)&qs[d][ty * 8];
            ulonglong2 A1 = *(const ulonglong2*)&qs[d][ty * 8 + 4];
            u64 pa[4] = {A0.x, A0.y, A1.x, A1.y};
            float4 b4 = *(const float4*)&ks[d][tx * 4];
            u64 bd[4] = {dup2(b4.x), dup2(b4.y), dup2(b4.z), dup2(b4.w)};
#pragma unroll
            for (int rp = 0; rp < 4; rp++)
#pragma unroll
                for (int jm = 0; jm < 4; jm++)
                    fma2(s2[rp][jm], pa[rp], bd[jm]);
        }

#pragma unroll
        for (int rp = 0; rp < 4; rp++) {
            const int r0 = ty * 8 + 2 * rp;
            float4 w0 = *(const float4*)&g_w[((size_t)(n0 + r0) * G_ + g) * M_ + m0 + tx * 4];
            float4 w1 = *(const float4*)&g_w[((size_t)(n0 + r0 + 1) * G_ + g) * M_ + m0 + tx * 4];
            float wl[4] = {w0.x, w0.y, w0.z, w0.w};
            float wh[4] = {w1.x, w1.y, w1.z, w1.w};
#pragma unroll
            for (int jm = 0; jm < 4; jm++) {
                float a0, a1;
                unpack2(s2[rp][jm], a0, a1);
                float p0 = wl[jm] * fast_exp(a0 * 0.125f);
                float p1 = wh[jm] * fast_exp(a1 * 0.125f);
                lrun[2*rp]   += p0;
                lrun[2*rp+1] += p1;
                s2[rp][jm] = pack2(p0, p1);
            }
        }
#pragma unroll
        for (int jm = 0; jm < 4; jm++) {
            ulonglong2 v0; v0.x = s2[0][jm]; v0.y = s2[1][jm];
            ulonglong2 v1; v1.x = s2[2][jm]; v1.y = s2[3][jm];
            *(ulonglong2*)&ps[tx * 4 + jm][ty * 8] = v0;
            *(ulonglong2*)&ps[tx * 4 + jm][ty * 8 + 4] = v1;
        }
        __syncthreads();

#pragma unroll 4
        for (int m = 0; m < 64; m++) {
            ulonglong2 P0 = *(const ulonglong2*)&ps[m][ty * 8];
            ulonglong2 P1 = *(const ulonglong2*)&ps[m][ty * 8 + 4];
            u64 pp[4] = {P0.x, P0.y, P1.x, P1.y};
            float4 v4 = *(const float4*)&vs[m][tx * 4];
            u64 vd[4] = {dup2(v4.x), dup2(v4.y), dup2(v4.z), dup2(v4.w)};
#pragma unroll
            for (int rp = 0; rp < 4; rp++)
#pragma unroll
                for (int o = 0; o < 4; o++)
                    fma2(acc2[rp][o], pp[rp], vd[o]);
        }
    }

    const int col = g * 64 + tx * 4;
#pragma unroll
    for (int rp = 0; rp < 4; rp++) {
        float a0[4], a1[4];
#pragma unroll
        for (int o = 0; o < 4; o++) unpack2(acc2[rp][o], a0[o], a1[o]);
        const int r0 = n0 + ty * 8 + 2 * rp;
        *(float4*)&g_pacc[z][(size_t)r0 * D_ + col]       = make_float4(a0[0], a0[1], a0[2], a0[3]);
        *(float4*)&g_pacc[z][(size_t)(r0 + 1) * D_ + col] = make_float4(a1[0], a1[1], a1[2], a1[3]);
    }
#pragma unroll
    for (int r = 0; r < 8; r++) {
        float l = lrun[r];
#pragma unroll
        for (int off = 1; off < 16; off <<= 1)
            l += __shfl_xor_sync(0xffffffffu, l, off, 16);
        if (tx == 0) g_pl[z][(size_t)(n0 + ty * 8 + r) * G_ + g] = l;
    }
}

// ---------------- combine 8 partials ----------------
__global__ __launch_bounds__(256) void reduce_kernel(const float* __restrict__ bv,
                                                     float* __restrict__ out) {
    int idx = blockIdx.x * 256 + threadIdx.x;
    int n = idx >> 8;
    int col = (idx & 255) << 2;
    int g = col >> 6;
    float l = 0.0f;
    float4 a = make_float4(0.f, 0.f, 0.f, 0.f);
#pragma unroll
    for (int zz = 0; zz < SPLITS; zz++) {
        l += g_pl[zz][(size_t)n * G_ + g];
        float4 p = *(const float4*)&g_pacc[zz][(size_t)n * D_ + col];
        a.x += p.x; a.y += p.y; a.z += p.z; a.w += p.w;
    }
    float inv = 1.0f / l;
    float4 b4 = *(const float4*)&bv[col];
    float4 o;
    o.x = fmaf(a.x, inv, b4.x);
    o.y = fmaf(a.y, inv, b4.y);
    o.z = fmaf(a.z, inv, b4.z);
    o.w = fmaf(a.w, inv, b4.w);
    *(float4*)&out[(size_t)n * D_ + col] = o;
}

// ---------------- host launcher ----------------
extern "C" void kernel_launch(void* const* d_in, const int* in_sizes, int n_in,
                              void* d_out, int out_size) {
    const float* roi   = (const float*)d_in[0];
    const float* ref   = (const float*)d_in[1];
    const float* rois1 = (const float*)d_in[2];
    const float* rois2 = (const float*)d_in[3];
    const float* Wq    = (const float*)d_in[4];
    const float* bq    = (const float*)d_in[5];
    const float* Wk    = (const float*)d_in[6];
    const float* bk    = (const float*)d_in[7];
    const float* Wg    = (const float*)d_in[8];
    const float* bg    = (const float*)d_in[9];
    const float* Wv    = (const float*)d_in[10];
    const float* bv    = (const float*)d_in[11];
    float* out = (float*)d_out;

    const int FLASH_SMEM = (64*128 + 64*64 + 64*64 + 64*128) * (int)sizeof(float); // 98304
    static bool attr_set = false;
    if (!attr_set) {
        cudaFuncSetAttribute(flash_kernel, cudaFuncAttributeMaxDynamicSharedMemorySize, FLASH_SMEM);
        cudaFuncSetAttribute(tc_gemm, cudaFuncAttributeMaxDynamicSharedMemorySize, TC_SMEM);
        attr_set = true;
    }

    box_prep<<<4, 256>>>(rois1, rois2);
    conv_a<<<dim3(1024, 3), 256>>>(roi, ref, Wv);
    conv_w<<<dim3(16, 16, 2), 256>>>(Wq, Wk);
    tc_gemm<<<dim3(8, 8, 3), 256, TC_SMEM>>>(bq, bk);
    posw_kernel<<<dim3(2, 1024), 256>>>(Wg, bg);
    flash_kernel<<<dim3(8, 16, 8), 256, FLASH_SMEM>>>();
    reduce_kernel<<<1024, 256>>>(bv, out);
}

// round 10
// speedup vs baseline: 1.9264x; 1.0749x over previous
#include <cuda_runtime.h>
#include <cuda_bf16.h>
#include <math.h>
#include <stdint.h>

#define N_ 1024
#define M_ 1024
#define D_ 1024
#define G_ 16
#define DG_ 64
#define SPLITS 8

typedef unsigned long long u64;

// ---------------- scratch ----------------
__device__ float g_qt[(size_t)D_ * N_];          // q transposed: [d_global][n]
__device__ float g_kt[(size_t)D_ * M_];          // k transposed: [d_global][m]
__device__ float g_v [(size_t)M_ * D_];          // [m][g*64+o]
__device__ float g_w[(size_t)N_ * G_ * M_];      // (N, G, M)
__device__ float g_boxA[N_ * 4];
__device__ float g_boxB[M_ * 4];
__device__ float g_trigA[N_ * 32];
__device__ float g_trigBt[32 * M_];
__device__ float g_pacc[SPLITS][(size_t)N_ * D_];
__device__ float g_pl[SPLITS][(size_t)N_ * G_];

// bf16 hi/lo operand buffers
#define MEG (1024 * 1024)
__device__ __align__(16) uint16_t g_roiH[MEG], g_roiL[MEG];
__device__ __align__(16) uint16_t g_refH[MEG], g_refL[MEG];
__device__ __align__(16) uint16_t g_wvH[MEG],  g_wvL[MEG];
__device__ __align__(16) uint16_t g_wqtH[MEG], g_wqtL[MEG];   // Wq^T [j][k]
__device__ __align__(16) uint16_t g_wktH[MEG], g_wktL[MEG];   // Wk^T [j][k]

// ---------------- f32x2 helpers ----------------
__device__ __forceinline__ void fma2(u64& d, u64 a, u64 b) {
    asm("fma.rn.f32x2 %0, %1, %2, %0;" : "+l"(d) : "l"(a), "l"(b));
}
__device__ __forceinline__ u64 pack2(float x, float y) {
    u64 r;
    asm("mov.b64 %0, {%1, %2};" : "=l"(r) : "f"(x), "f"(y));
    return r;
}
__device__ __forceinline__ void unpack2(u64 p, float& x, float& y) {
    asm("mov.b64 {%0, %1}, %2;" : "=f"(x), "=f"(y) : "l"(p));
}
__device__ __forceinline__ u64 dup2(float x) { return pack2(x, x); }

__device__ __forceinline__ float fast_exp(float x) {
    float t = x * 1.4426950408889634f;
    t = fminf(fmaxf(t, -120.0f), 120.0f);
    float fi = floorf(t);
    float f = t - fi;
    float p = 1.5403530393e-4f;
    p = fmaf(p, f, 1.3333558146e-3f);
    p = fmaf(p, f, 9.6181291076e-3f);
    p = fmaf(p, f, 5.5504108664e-2f);
    p = fmaf(p, f, 2.4022650696e-1f);
    p = fmaf(p, f, 6.9314718056e-1f);
    p = fmaf(p, f, 1.0f);
    return p * __int_as_float(((int)fi + 127) << 23);
}

__constant__ float c_cf[8] = {100.0f, 42.169650f, 17.782794f, 7.4989421f,
                              3.1622776f, 1.3335214f, 0.56234133f, 0.23713737f};

// ---------------- warp-mma helpers (baseline PTX) ----------------
__device__ __forceinline__ uint32_t smem_to_u32(const void* p) {
    uint32_t a;
    asm("{ .reg .u64 t; cvta.to.shared.u64 t, %1; cvt.u32.u64 %0, t; }" : "=r"(a) : "l"(p));
    return a;
}
__device__ __forceinline__ void mma16816(float* d, const uint32_t* a, const uint32_t* b) {
    asm volatile(
        "mma.sync.aligned.m16n8k16.row.col.f32.bf16.bf16.f32 "
        "{%0,%1,%2,%3}, {%4,%5,%6,%7}, {%8,%9}, {%0,%1,%2,%3};"
        : "+f"(d[0]), "+f"(d[1]), "+f"(d[2]), "+f"(d[3])
        : "r"(a[0]), "r"(a[1]), "r"(a[2]), "r"(a[3]), "r"(b[0]), "r"(b[1]));
}
__device__ __forceinline__ void ldsm_x4(uint32_t* r, uint32_t addr) {
    asm volatile("ldmatrix.sync.aligned.m8n8.x4.shared.b16 {%0,%1,%2,%3}, [%4];"
                 : "=r"(r[0]), "=r"(r[1]), "=r"(r[2]), "=r"(r[3]) : "r"(addr));
}
__device__ __forceinline__ void ldsm_x2(uint32_t* r, uint32_t addr) {
    asm volatile("ldmatrix.sync.aligned.m8n8.x2.shared.b16 {%0,%1}, [%2];"
                 : "=r"(r[0]), "=r"(r[1]) : "r"(addr));
}
__device__ __forceinline__ void cp16(uint32_t saddr, const void* gptr) {
    asm volatile("cp.async.cg.shared.global [%0], [%1], 16;" :: "r"(saddr), "l"(gptr));
}
#define CP_COMMIT() asm volatile("cp.async.commit_group;" ::: "memory")
#define SWZ(bo) ((bo) ^ (((bo) >> 3) & 0x70))

// ---------------- box prep ----------------
__global__ void box_prep(const float* __restrict__ rois1, const float* __restrict__ rois2) {
    int i = blockIdx.x * blockDim.x + threadIdx.x;
    if (i >= N_) return;
    {
        float xmin = rois1[i*4+0], ymin = rois1[i*4+1], xmax = rois1[i*4+2], ymax = rois1[i*4+3];
        float w = xmax - xmin + 1.0f, h = ymax - ymin + 1.0f;
        g_boxA[i*4+0] = 0.5f*(xmin+xmax); g_boxA[i*4+1] = 0.5f*(ymin+ymax);
        g_boxA[i*4+2] = 1.0f/w;           g_boxA[i*4+3] = 1.0f/h;
        float lw = logf(w), lh = logf(h);
#pragma unroll
        for (int f = 0; f < 8; f++) {
            float s, c;
            sincosf(lw * c_cf[f], &s, &c);
            g_trigA[i*32 + f] = s;      g_trigA[i*32 + 8 + f] = c;
            sincosf(lh * c_cf[f], &s, &c);
            g_trigA[i*32 + 16 + f] = s; g_trigA[i*32 + 24 + f] = c;
        }
    }
    {
        float xmin = rois2[i*4+0], ymin = rois2[i*4+1], xmax = rois2[i*4+2], ymax = rois2[i*4+3];
        float w = xmax - xmin + 1.0f, h = ymax - ymin + 1.0f;
        g_boxB[i*4+0] = 0.5f*(xmin+xmax); g_boxB[i*4+1] = 0.5f*(ymin+ymax);
        g_boxB[i*4+2] = 1.0f/w;           g_boxB[i*4+3] = 1.0f/h;
        float lw = logf(w), lh = logf(h);
#pragma unroll
        for (int f = 0; f < 8; f++) {
            float s, c;
            sincosf(lw * c_cf[f], &s, &c);
            g_trigBt[f*M_ + i] = s;        g_trigBt[(8+f)*M_ + i] = c;
            sincosf(lh * c_cf[f], &s, &c);
            g_trigBt[(16+f)*M_ + i] = s;   g_trigBt[(24+f)*M_ + i] = c;
        }
    }
}

// ---------------- fp32 -> bf16 hi/lo (row-major tensors) ----------------
__global__ __launch_bounds__(256) void conv_a(const float* __restrict__ roi,
                                              const float* __restrict__ ref,
                                              const float* __restrict__ wv) {
    const int z = blockIdx.y;
    const float4* src = (const float4*)(z == 0 ? roi : z == 1 ? ref : wv);
    uint2* dh = (uint2*)(z == 0 ? g_roiH : z == 1 ? g_refH : g_wvH);
    uint2* dl = (uint2*)(z == 0 ? g_roiL : z == 1 ? g_refL : g_wvL);
    int i = blockIdx.x * 256 + threadIdx.x;
    float4 x = src[i];
    __nv_bfloat16 h0 = __float2bfloat16(x.x), h1 = __float2bfloat16(x.y);
    __nv_bfloat16 h2 = __float2bfloat16(x.z), h3 = __float2bfloat16(x.w);
    __nv_bfloat16 e0 = __float2bfloat16(x.x - __bfloat162float(h0));
    __nv_bfloat16 e1 = __float2bfloat16(x.y - __bfloat162float(h1));
    __nv_bfloat16 e2 = __float2bfloat16(x.z - __bfloat162float(h2));
    __nv_bfloat16 e3 = __float2bfloat16(x.w - __bfloat162float(h3));
    uint2 H, L;
    H.x = ((uint32_t)__bfloat16_as_ushort(h1) << 16) | __bfloat16_as_ushort(h0);
    H.y = ((uint32_t)__bfloat16_as_ushort(h3) << 16) | __bfloat16_as_ushort(h2);
    L.x = ((uint32_t)__bfloat16_as_ushort(e1) << 16) | __bfloat16_as_ushort(e0);
    L.y = ((uint32_t)__bfloat16_as_ushort(e3) << 16) | __bfloat16_as_ushort(e2);
    dh[i] = H;
    dl[i] = L;
}

// ---------------- Wq/Wk transpose + bf16 hi/lo: W[k][j] -> Wt[j][k] ----------------
__global__ __launch_bounds__(256) void conv_w(const float* __restrict__ Wq,
                                              const float* __restrict__ Wk) {
    __shared__ float ts[64][65];
    const int z = blockIdx.z;
    const float* W = z ? Wk : Wq;
    uint2* dh = (uint2*)(z ? g_wktH : g_wqtH);
    uint2* dl = (uint2*)(z ? g_wktL : g_wqtL);
    const int j0 = blockIdx.x * 64, k0 = blockIdx.y * 64;
    const int t = threadIdx.x;
#pragma unroll
    for (int it = 0; it < 4; it++) {
        int lin = it * 256 + t;
        int k = lin >> 4, j4 = (lin & 15) << 2;
        float4 v = *(const float4*)&W[(size_t)(k0 + k) * D_ + j0 + j4];
        ts[j4 + 0][k] = v.x; ts[j4 + 1][k] = v.y; ts[j4 + 2][k] = v.z; ts[j4 + 3][k] = v.w;
    }
    __syncthreads();
#pragma unroll
    for (int it = 0; it < 4; it++) {
        int lin = it * 256 + t;
        int j = lin >> 4, k4 = (lin & 15) << 2;
        float a = ts[j][k4 + 0], b = ts[j][k4 + 1], c = ts[j][k4 + 2], d = ts[j][k4 + 3];
        __nv_bfloat16 h0 = __float2bfloat16(a), h1 = __float2bfloat16(b);
        __nv_bfloat16 h2 = __float2bfloat16(c), h3 = __float2bfloat16(d);
        __nv_bfloat16 e0 = __float2bfloat16(a - __bfloat162float(h0));
        __nv_bfloat16 e1 = __float2bfloat16(b - __bfloat162float(h1));
        __nv_bfloat16 e2 = __float2bfloat16(c - __bfloat162float(h2));
        __nv_bfloat16 e3 = __float2bfloat16(d - __bfloat162float(h3));
        uint2 H, L;
        H.x = ((uint32_t)__bfloat16_as_ushort(h1) << 16) | __bfloat16_as_ushort(h0);
        H.y = ((uint32_t)__bfloat16_as_ushort(h3) << 16) | __bfloat16_as_ushort(h2);
        L.x = ((uint32_t)__bfloat16_as_ushort(e1) << 16) | __bfloat16_as_ushort(e0);
        L.y = ((uint32_t)__bfloat16_as_ushort(e3) << 16) | __bfloat16_as_ushort(e2);
        size_t idx = ((size_t)(j0 + j) * D_ + k0 + k4) >> 2;
        dh[idx] = H;
        dl[idx] = L;
    }
}

// ---------------- tensor-core GEMM: 128m x 64n tiles, 2 blocks/SM ----------------
// grid (16 j, 8 i, 3 mats), 256 thr (8 warps in 4m x 2n; warp tile 32m x 32n).
#define OFF_AH 0
#define OFF_AL 16384
#define OFF_BH 32768
#define OFF_BL 40960
#define STAGE_BYTES 49152
#define TC_SMEM (2 * STAGE_BYTES)   // 98304

__global__ __launch_bounds__(256, 2) void tc_gemm(const float* __restrict__ bq,
                                                  const float* __restrict__ bk) {
    extern __shared__ char smem[];
    const uint32_t sb = smem_to_u32(smem);
    const int t = threadIdx.x;
    const int wid = t >> 5, lane = t & 31;
    const int j0 = blockIdx.x * 64, i0 = blockIdx.y * 128;
    const int mat = blockIdx.z;

    const uint16_t* Ah;
    const uint16_t* Al;
    const uint16_t* Bh;
    const uint16_t* Bl;
    if (mat == 0)      { Ah = g_roiH; Al = g_roiL; Bh = g_wqtH; Bl = g_wqtL; }
    else if (mat == 1) { Ah = g_refH; Al = g_refL; Bh = g_wktH; Bl = g_wktL; }
    else               { Ah = g_refH; Al = g_refL; Bh = g_wvH;  Bl = g_wvL; }

    const int wm = wid & 3, wn = wid >> 2;    // warp tile origin: (wm*32, wn*32)
    const int lr = lane & 7, lq = lane >> 3;

    float d[2][4][4];
#pragma unroll
    for (int a = 0; a < 2; a++)
#pragma unroll
        for (int b = 0; b < 4; b++)
#pragma unroll
            for (int c = 0; c < 4; c++) d[a][b][c] = 0.0f;

    // ldmatrix lane-address offsets (within 128x64bf16 / 64x64bf16 SW128 tiles)
    const uint32_t a_off0 = (uint32_t)((wm*32 + (lq & 1)*8 + lr) * 128 + (lq >> 1) * 16);
    const uint32_t b_off0 = (uint32_t)((wn*32 + lr) * 128 + (lq & 1) * 16);

    auto loadChunk = [&](int ch, int stage) {
        const uint32_t sbase = sb + stage * STAGE_BYTES;
        // A: 128 rows x 8 u(16B) per tile -> 4 u/thread/tile
        {
            int row = t >> 1;
#pragma unroll
            for (int uu = 0; uu < 4; uu++) {
                int u = (t & 1) * 4 + uu;
                uint32_t so = SWZ((uint32_t)(row * 128 + u * 16));
                const uint16_t* gh = Ah + ((size_t)(i0 + row) * 1024 + ch * 64 + u * 8);
                const uint16_t* gl = Al + ((size_t)(i0 + row) * 1024 + ch * 64 + u * 8);
                cp16(sbase + OFF_AH + so, gh);
                cp16(sbase + OFF_AL + so, gl);
            }
        }
        // B: 64 rows x 8 u -> 2 u/thread/tile
        {
            int row = t >> 2;
#pragma unroll
            for (int uu = 0; uu < 2; uu++) {
                int u = (t & 3) * 2 + uu;
                uint32_t so = SWZ((uint32_t)(row * 128 + u * 16));
                const uint16_t* gh = Bh + ((size_t)(j0 + row) * 1024 + ch * 64 + u * 8);
                const uint16_t* gl = Bl + ((size_t)(j0 + row) * 1024 + ch * 64 + u * 8);
                cp16(sbase + OFF_BH + so, gh);
                cp16(sbase + OFF_BL + so, gl);
            }
        }
    };

    loadChunk(0, 0);
    CP_COMMIT();

    for (int ch = 0; ch < 16; ch++) {
        if (ch + 1 < 16) {
            loadChunk(ch + 1, (ch + 1) & 1);
            CP_COMMIT();
            asm volatile("cp.async.wait_group 1;" ::: "memory");
        } else {
            asm volatile("cp.async.wait_group 0;" ::: "memory");
        }
        __syncthreads();

        const uint32_t st = sb + (ch & 1) * STAGE_BYTES;
#pragma unroll
        for (int ks = 0; ks < 4; ks++) {
            const uint32_t kb = (uint32_t)(ks * 32);   // 16 bf16 = 32 bytes
            uint32_t ah[2][4], al[2][4], bh[4][2], bl[4][2];
#pragma unroll
            for (int ma = 0; ma < 2; ma++) {
                uint32_t off = SWZ(a_off0 + (uint32_t)(ma * 16 * 128) + kb);
                ldsm_x4(ah[ma], st + OFF_AH + off);
                ldsm_x4(al[ma], st + OFF_AL + off);
            }
#pragma unroll
            for (int na = 0; na < 4; na++) {
                uint32_t off = SWZ(b_off0 + (uint32_t)(na * 8 * 128) + kb);
                ldsm_x2(bh[na], st + OFF_BH + off);
                ldsm_x2(bl[na], st + OFF_BL + off);
            }
            // hh first, then hl, then lh: accumulator reuse distance 8
#pragma unroll
            for (int ma = 0; ma < 2; ma++)
#pragma unroll
                for (int na = 0; na < 4; na++)
                    mma16816(d[ma][na], ah[ma], bh[na]);
#pragma unroll
            for (int ma = 0; ma < 2; ma++)
#pragma unroll
                for (int na = 0; na < 4; na++)
                    mma16816(d[ma][na], ah[ma], bl[na]);
#pragma unroll
            for (int ma = 0; ma < 2; ma++)
#pragma unroll
                for (int na = 0; na < 4; na++)
                    mma16816(d[ma][na], al[ma], bh[na]);
        }
        __syncthreads();
    }

    // stage D in smem: sd[128 i][68] cols j
    float* sd = (float*)smem;
    const int gid = lane >> 2, tig = lane & 3;
#pragma unroll
    for (int ma = 0; ma < 2; ma++)
#pragma unroll
        for (int na = 0; na < 4; na++) {
            int row = wm * 32 + ma * 16 + gid;
            int col = wn * 32 + na * 8 + 2 * tig;
            sd[row * 68 + col]           = d[ma][na][0];
            sd[row * 68 + col + 1]       = d[ma][na][1];
            sd[(row + 8) * 68 + col]     = d[ma][na][2];
            sd[(row + 8) * 68 + col + 1] = d[ma][na][3];
        }
    __syncthreads();

    if (mat != 2) {
        const float* bias = (mat == 0) ? bq : bk;
        float* dst = (mat == 0) ? g_qt : g_kt;
        int j = t >> 2, ih = (t & 3) * 32;
        float bb = bias[j0 + j];
#pragma unroll
        for (int mm = 0; mm < 32; mm += 4) {
            float4 v;
            v.x = sd[(ih + mm + 0) * 68 + j] + bb;
            v.y = sd[(ih + mm + 1) * 68 + j] + bb;
            v.z = sd[(ih + mm + 2) * 68 + j] + bb;
            v.w = sd[(ih + mm + 3) * 68 + j] + bb;
            *(float4*)&dst[(size_t)(j0 + j) * N_ + i0 + ih + mm] = v;
        }
    } else {
        int m = t >> 1, jh = (t & 1) * 32;
#pragma unroll
        for (int jj = 0; jj < 32; jj += 4) {
            float4 v = *(const float4*)&sd[m * 68 + jh + jj];
            *(float4*)&g_v[(size_t)(i0 + m) * D_ + j0 + jh + jj] = v;
        }
    }
}

// ---------------- position-weight kernel: 2 m per thread, transposed weights ----------------
__global__ __launch_bounds__(256, 2) void posw_kernel(const float* __restrict__ Wg,
                                                      const float* __restrict__ bg) {
    __shared__ float wgt[64][16];
    __shared__ float bgs[G_];
    const int t = threadIdx.x;
#pragma unroll
    for (int i = t; i < 1024; i += 256) {
        int g = i >> 6, e = i & 63;
        wgt[e][g] = Wg[i];
    }
    if (t < G_) bgs[t] = bg[t];
    __syncthreads();

    const int n = blockIdx.y;
    const int m0 = blockIdx.x * 512 + t;
    const int m1 = m0 + 256;

    u64 acc0[8], acc1[8];
#pragma unroll
    for (int gp = 0; gp < 8; gp++) {
        u64 b2 = pack2(bgs[2*gp], bgs[2*gp+1]);
        acc0[gp] = b2;
        acc1[gp] = b2;
    }

    auto upd = [&](int e, float v0, float v1) {
        const ulonglong2* wr = (const ulonglong2*)&wgt[e][0];
        ulonglong2 wa = wr[0], wb = wr[1];
        u64 d0 = dup2(v0), d1 = dup2(v1);
        fma2(acc0[0], d0, wa.x); fma2(acc1[0], d1, wa.x);
        fma2(acc0[1], d0, wa.y); fma2(acc1[1], d1, wa.y);
        fma2(acc0[2], d0, wb.x); fma2(acc1[2], d1, wb.x);
        fma2(acc0[3], d0, wb.y); fma2(acc1[3], d1, wb.y);
        ulonglong2 wc = wr[2], wd = wr[3];
        fma2(acc0[4], d0, wc.x); fma2(acc1[4], d1, wc.x);
        fma2(acc0[5], d0, wc.y); fma2(acc1[5], d1, wc.y);
        fma2(acc0[6], d0, wd.x); fma2(acc1[6], d1, wd.x);
        fma2(acc0[7], d0, wd.y); fma2(acc1[7], d1, wd.y);
    };

    const float4 bn = *(const float4*)&g_boxA[n * 4];
    const float4 bm0 = *(const float4*)&g_boxB[m0 * 4];
    const float4 bm1 = *(const float4*)&g_boxB[m1 * 4];

    {
        float px0 = __logf(fabsf(bn.x - bm0.x) * bn.z + 1e-3f);
        float px1 = __logf(fabsf(bn.x - bm1.x) * bn.z + 1e-3f);
#pragma unroll
        for (int f = 0; f < 8; f++) {
            float s0, c0, s1, c1;
            __sincosf(px0 * c_cf[f], &s0, &c0);
            __sincosf(px1 * c_cf[f], &s1, &c1);
            upd(f, s0, s1);
            upd(8 + f, c0, c1);
        }
        float py0 = __logf(fabsf(bn.y - bm0.y) * bn.w + 1e-3f);
        float py1 = __logf(fabsf(bn.y - bm1.y) * bn.w + 1e-3f);
#pragma unroll
        for (int f = 0; f < 8; f++) {
            float s0, c0, s1, c1;
            __sincosf(py0 * c_cf[f], &s0, &c0);
            __sincosf(py1 * c_cf[f], &s1, &c1);
            upd(16 + f, s0, s1);
            upd(24 + f, c0, c1);
        }
    }

#pragma unroll
    for (int f = 0; f < 8; f++) {
        float snf = g_trigA[n*32 + f], cnf = g_trigA[n*32 + 8 + f];
        float sm0 = g_trigBt[f*M_ + m0], cm0 = g_trigBt[(8+f)*M_ + m0];
        float sm1 = g_trigBt[f*M_ + m1], cm1 = g_trigBt[(8+f)*M_ + m1];
        upd(32 + f, snf*cm0 - cnf*sm0, snf*cm1 - cnf*sm1);
        upd(40 + f, fmaf(cnf, cm0, snf*sm0), fmaf(cnf, cm1, snf*sm1));
    }
#pragma unroll
    for (int f = 0; f < 8; f++) {
        float snf = g_trigA[n*32 + 16 + f], cnf = g_trigA[n*32 + 24 + f];
        float sm0 = g_trigBt[(16+f)*M_ + m0], cm0 = g_trigBt[(24+f)*M_ + m0];
        float sm1 = g_trigBt[(16+f)*M_ + m1], cm1 = g_trigBt[(24+f)*M_ + m1];
        upd(48 + f, snf*cm0 - cnf*sm0, snf*cm1 - cnf*sm1);
        upd(56 + f, fmaf(cnf, cm0, snf*sm0), fmaf(cnf, cm1, snf*sm1));
    }

    const size_t base = (size_t)n * G_ * M_;
#pragma unroll
    for (int gp = 0; gp < 8; gp++) {
        float x0, y0, x1, y1;
        unpack2(acc0[gp], x0, y0);
        unpack2(acc1[gp], x1, y1);
        g_w[base + (size_t)(2*gp)   * M_ + m0] = fmaxf(x0, 0.0f) + 1e-6f;
        g_w[base + (size_t)(2*gp+1) * M_ + m0] = fmaxf(y0, 0.0f) + 1e-6f;
        g_w[base + (size_t)(2*gp)   * M_ + m1] = fmaxf(x1, 0.0f) + 1e-6f;
        g_w[base + (size_t)(2*gp+1) * M_ + m1] = fmaxf(y1, 0.0f) + 1e-6f;
    }
}

// ---------------- fused attention: 128n x 64m tiles, f32x2 micro, M-split8 ----------------
__global__ __launch_bounds__(256, 2) void flash_kernel() {
    extern __shared__ float smemf[];
    float(*qs)[128] = (float(*)[128])smemf;
    float(*ks)[64]  = (float(*)[64])(smemf + 64 * 128);
    float(*vs)[64]  = (float(*)[64])(smemf + 64*128 + 64*64);
    float(*ps)[128] = (float(*)[128])(smemf + 64*128 + 2*64*64);

    const int t = threadIdx.x;
    const int tx = t & 15, ty = t >> 4;
    const int g = blockIdx.y;
    const int n0 = blockIdx.x * 128;
    const int z = blockIdx.z;

#pragma unroll
    for (int it = 0; it < 8; it++) {
        int idx = it * 256 + t;
        int d = idx >> 5, r4 = (idx & 31) << 2;
        *(float4*)&qs[d][r4] = *(const float4*)&g_qt[(size_t)(g*64 + d) * N_ + n0 + r4];
    }

    u64 acc2[4][4];
#pragma unroll
    for (int a = 0; a < 4; a++)
#pragma unroll
        for (int b = 0; b < 4; b++) acc2[a][b] = 0ull;
    float lrun[8] = {};

    for (int mi = 0; mi < 2; mi++) {
        const int m0 = (z * 2 + mi) * 64;
        __syncthreads();
#pragma unroll
        for (int it = 0; it < 4; it++) {
            int idx = it * 256 + t;
            int d = idx >> 4, m4 = (idx & 15) << 2;
            *(float4*)&ks[d][m4] = *(const float4*)&g_kt[(size_t)(g*64 + d) * M_ + m0 + m4];
        }
#pragma unroll
        for (int it = 0; it < 4; it++) {
            int idx = it * 256 + t;
            int m = idx >> 4, o4 = (idx & 15) << 2;
            *(float4*)&vs[m][o4] = *(const float4*)&g_v[(size_t)(m0 + m) * D_ + g*64 + o4];
        }
        __syncthreads();

        u64 s2[4][4];
#pragma unroll
        for (int a = 0; a < 4; a++)
#pragma unroll
            for (int b = 0; b < 4; b++) s2[a][b] = 0ull;

#pragma unroll 8
        for (int d = 0; d < 64; d++) {
            ulonglong2 A0 = *(const ulonglong2*)&qs[d][ty * 8];
            ulonglong2 A1 = *(const ulonglong2*)&qs[d][ty * 8 + 4];
            u64 pa[4] = {A0.x, A0.y, A1.x, A1.y};
            float4 b4 = *(const float4*)&ks[d][tx * 4];
            u64 bd[4] = {dup2(b4.x), dup2(b4.y), dup2(b4.z), dup2(b4.w)};
#pragma unroll
            for (int rp = 0; rp < 4; rp++)
#pragma unroll
                for (int jm = 0; jm < 4; jm++)
                    fma2(s2[rp][jm], pa[rp], bd[jm]);
        }

#pragma unroll
        for (int rp = 0; rp < 4; rp++) {
            const int r0 = ty * 8 + 2 * rp;
            float4 w0 = *(const float4*)&g_w[((size_t)(n0 + r0) * G_ + g) * M_ + m0 + tx * 4];
            float4 w1 = *(const float4*)&g_w[((size_t)(n0 + r0 + 1) * G_ + g) * M_ + m0 + tx * 4];
            float wl[4] = {w0.x, w0.y, w0.z, w0.w};
            float wh[4] = {w1.x, w1.y, w1.z, w1.w};
#pragma unroll
            for (int jm = 0; jm < 4; jm++) {
                float a0, a1;
                unpack2(s2[rp][jm], a0, a1);
                float p0 = wl[jm] * fast_exp(a0 * 0.125f);
                float p1 = wh[jm] * fast_exp(a1 * 0.125f);
                lrun[2*rp]   += p0;
                lrun[2*rp+1] += p1;
                s2[rp][jm] = pack2(p0, p1);
            }
        }
#pragma unroll
        for (int jm = 0; jm < 4; jm++) {
            ulonglong2 v0; v0.x = s2[0][jm]; v0.y = s2[1][jm];
            ulonglong2 v1; v1.x = s2[2][jm]; v1.y = s2[3][jm];
            *(ulonglong2*)&ps[tx * 4 + jm][ty * 8] = v0;
            *(ulonglong2*)&ps[tx * 4 + jm][ty * 8 + 4] = v1;
        }
        __syncthreads();

#pragma unroll 4
        for (int m = 0; m < 64; m++) {
            ulonglong2 P0 = *(const ulonglong2*)&ps[m][ty * 8];
            ulonglong2 P1 = *(const ulonglong2*)&ps[m][ty * 8 + 4];
            u64 pp[4] = {P0.x, P0.y, P1.x, P1.y};
            float4 v4 = *(const float4*)&vs[m][tx * 4];
            u64 vd[4] = {dup2(v4.x), dup2(v4.y), dup2(v4.z), dup2(v4.w)};
#pragma unroll
            for (int rp = 0; rp < 4; rp++)
#pragma unroll
                for (int o = 0; o < 4; o++)
                    fma2(acc2[rp][o], pp[rp], vd[o]);
        }
    }

    const int col = g * 64 + tx * 4;
#pragma unroll
    for (int rp = 0; rp < 4; rp++) {
        float a0[4], a1[4];
#pragma unroll
        for (int o = 0; o < 4; o++) unpack2(acc2[rp][o], a0[o], a1[o]);
        const int r0 = n0 + ty * 8 + 2 * rp;
        *(float4*)&g_pacc[z][(size_t)r0 * D_ + col]       = make_float4(a0[0], a0[1], a0[2], a0[3]);
        *(float4*)&g_pacc[z][(size_t)(r0 + 1) * D_ + col] = make_float4(a1[0], a1[1], a1[2], a1[3]);
    }
#pragma unroll
    for (int r = 0; r < 8; r++) {
        float l = lrun[r];
#pragma unroll
        for (int off = 1; off < 16; off <<= 1)
            l += __shfl_xor_sync(0xffffffffu, l, off, 16);
        if (tx == 0) g_pl[z][(size_t)(n0 + ty * 8 + r) * G_ + g] = l;
    }
}

// ---------------- combine 8 partials ----------------
__global__ __launch_bounds__(256) void reduce_kernel(const float* __restrict__ bv,
                                                     float* __restrict__ out) {
    int idx = blockIdx.x * 256 + threadIdx.x;
    int n = idx >> 8;
    int col = (idx & 255) << 2;
    int g = col >> 6;
    float l = 0.0f;
    float4 a = make_float4(0.f, 0.f, 0.f, 0.f);
#pragma unroll
    for (int zz = 0; zz < SPLITS; zz++) {
        l += g_pl[zz][(size_t)n * G_ + g];
        float4 p = *(const float4*)&g_pacc[zz][(size_t)n * D_ + col];
        a.x += p.x; a.y += p.y; a.z += p.z; a.w += p.w;
    }
    float inv = 1.0f / l;
    float4 b4 = *(const float4*)&bv[col];
    float4 o;
    o.x = fmaf(a.x, inv, b4.x);
    o.y = fmaf(a.y, inv, b4.y);
    o.z = fmaf(a.z, inv, b4.z);
    o.w = fmaf(a.w, inv, b4.w);
    *(float4*)&out[(size_t)n * D_ + col] = o;
}

// ---------------- host launcher ----------------
extern "C" void kernel_launch(void* const* d_in, const int* in_sizes, int n_in,
                              void* d_out, int out_size) {
    const float* roi   = (const float*)d_in[0];
    const float* ref   = (const float*)d_in[1];
    const float* rois1 = (const float*)d_in[2];
    const float* rois2 = (const float*)d_in[3];
    const float* Wq    = (const float*)d_in[4];
    const float* bq    = (const float*)d_in[5];
    const float* Wk    = (const float*)d_in[6];
    const float* bk    = (const float*)d_in[7];
    const float* Wg    = (const float*)d_in[8];
    const float* bg    = (const float*)d_in[9];
    const float* Wv    = (const float*)d_in[10];
    const float* bv    = (const float*)d_in[11];
    float* out = (float*)d_out;

    const int FLASH_SMEM = (64*128 + 64*64 + 64*64 + 64*128) * (int)sizeof(float); // 98304
    static bool attr_set = false;
    if (!attr_set) {
        cudaFuncSetAttribute(flash_kernel, cudaFuncAttributeMaxDynamicSharedMemorySize, FLASH_SMEM);
        cudaFuncSetAttribute(tc_gemm, cudaFuncAttributeMaxDynamicSharedMemorySize, TC_SMEM);
        attr_set = true;
    }

    box_prep<<<4, 256>>>(rois1, rois2);
    conv_a<<<dim3(1024, 3), 256>>>(roi, ref, Wv);
    conv_w<<<dim3(16, 16, 2), 256>>>(Wq, Wk);
    tc_gemm<<<dim3(16, 8, 3), 256, TC_SMEM>>>(bq, bk);
    posw_kernel<<<dim3(2, 1024), 256>>>(Wg, bg);
    flash_kernel<<<dim3(8, 16, 8), 256, FLASH_SMEM>>>();
    reduce_kernel<<<1024, 256>>>(bv, out);
}

// round 11
// speedup vs baseline: 2.3862x; 1.2387x over previous
#include <cuda_runtime.h>
#include <cuda_bf16.h>
#include <math.h>
#include <stdint.h>

#define N_ 1024
#define M_ 1024
#define D_ 1024
#define G_ 16
#define DG_ 64
#define SPLITS 2

typedef unsigned long long u64;

// ---------------- scratch ----------------
__device__ float g_w[(size_t)N_ * G_ * M_];      // (N, G, M)
__device__ float g_boxA[N_ * 4];
__device__ float g_boxB[M_ * 4];
__device__ float g_trigA[N_ * 32];
__device__ float g_trigBt[32 * M_];
__device__ float g_pacc[SPLITS][(size_t)N_ * D_];
__device__ float g_pl[SPLITS][(size_t)N_ * G_];

// bf16 hi/lo operand buffers
#define MEG (1024 * 1024)
__device__ __align__(16) uint16_t g_roiH[MEG], g_roiL[MEG];
__device__ __align__(16) uint16_t g_refH[MEG], g_refL[MEG];
__device__ __align__(16) uint16_t g_wvH[MEG],  g_wvL[MEG];
__device__ __align__(16) uint16_t g_wqtH[MEG], g_wqtL[MEG];   // Wq^T [j][k]
__device__ __align__(16) uint16_t g_wktH[MEG], g_wktL[MEG];   // Wk^T [j][k]
// GEMM outputs (bf16 hi/lo), MMA-ready layouts for flash
__device__ __align__(16) uint16_t g_qbH[MEG], g_qbL[MEG];     // q [n][d]
__device__ __align__(16) uint16_t g_kbH[MEG], g_kbL[MEG];     // k [m][d]
__device__ __align__(16) uint16_t g_vtH[MEG], g_vtL[MEG];     // v^T [o][m]

// ---------------- f32x2 helpers ----------------
__device__ __forceinline__ void fma2(u64& d, u64 a, u64 b) {
    asm("fma.rn.f32x2 %0, %1, %2, %0;" : "+l"(d) : "l"(a), "l"(b));
}
__device__ __forceinline__ u64 pack2(float x, float y) {
    u64 r;
    asm("mov.b64 %0, {%1, %2};" : "=l"(r) : "f"(x), "f"(y));
    return r;
}
__device__ __forceinline__ void unpack2(u64 p, float& x, float& y) {
    asm("mov.b64 {%0, %1}, %2;" : "=f"(x), "=f"(y) : "l"(p));
}
__device__ __forceinline__ u64 dup2(float x) { return pack2(x, x); }

__device__ __forceinline__ float fast_exp(float x) {
    float t = x * 1.4426950408889634f;
    t = fminf(fmaxf(t, -120.0f), 120.0f);
    float fi = floorf(t);
    float f = t - fi;
    float p = 1.5403530393e-4f;
    p = fmaf(p, f, 1.3333558146e-3f);
    p = fmaf(p, f, 9.6181291076e-3f);
    p = fmaf(p, f, 5.5504108664e-2f);
    p = fmaf(p, f, 2.4022650696e-1f);
    p = fmaf(p, f, 6.9314718056e-1f);
    p = fmaf(p, f, 1.0f);
    return p * __int_as_float(((int)fi + 127) << 23);
}

__constant__ float c_cf[8] = {100.0f, 42.169650f, 17.782794f, 7.4989421f,
                              3.1622776f, 1.3335214f, 0.56234133f, 0.23713737f};

// ---------------- mma / bf16 helpers (baseline PTX) ----------------
__device__ __forceinline__ uint32_t smem_to_u32(const void* p) {
    uint32_t a;
    asm("{ .reg .u64 t; cvta.to.shared.u64 t, %1; cvt.u32.u64 %0, t; }" : "=r"(a) : "l"(p));
    return a;
}
__device__ __forceinline__ void mma16816(float* d, const uint32_t* a, const uint32_t* b) {
    asm volatile(
        "mma.sync.aligned.m16n8k16.row.col.f32.bf16.bf16.f32 "
        "{%0,%1,%2,%3}, {%4,%5,%6,%7}, {%8,%9}, {%0,%1,%2,%3};"
        : "+f"(d[0]), "+f"(d[1]), "+f"(d[2]), "+f"(d[3])
        : "r"(a[0]), "r"(a[1]), "r"(a[2]), "r"(a[3]), "r"(b[0]), "r"(b[1]));
}
__device__ __forceinline__ void ldsm_x4(uint32_t* r, uint32_t addr) {
    asm volatile("ldmatrix.sync.aligned.m8n8.x4.shared.b16 {%0,%1,%2,%3}, [%4];"
                 : "=r"(r[0]), "=r"(r[1]), "=r"(r[2]), "=r"(r[3]) : "r"(addr));
}
__device__ __forceinline__ void ldsm_x2(uint32_t* r, uint32_t addr) {
    asm volatile("ldmatrix.sync.aligned.m8n8.x2.shared.b16 {%0,%1}, [%2];"
                 : "=r"(r[0]), "=r"(r[1]) : "r"(addr));
}
__device__ __forceinline__ void cp16(uint32_t saddr, const void* gptr) {
    asm volatile("cp.async.cg.shared.global [%0], [%1], 16;" :: "r"(saddr), "l"(gptr));
}
#define CP_COMMIT() asm volatile("cp.async.commit_group;" ::: "memory")
#define SWZ(bo) ((bo) ^ (((bo) >> 3) & 0x70))

// pack (lo, hi) floats -> bf16x2 register (lo in bits [0:16))
__device__ __forceinline__ uint32_t cvt2bf(float lo, float hi) {
    uint32_t r;
    asm("cvt.rn.satfinite.bf16x2.f32 %0, %1, %2;" : "=r"(r) : "f"(hi), "f"(lo));
    return r;
}
__device__ __forceinline__ float bflo(uint32_t p) { return __uint_as_float(p << 16); }
__device__ __forceinline__ float bfhi(uint32_t p) { return __uint_as_float(p & 0xFFFF0000u); }

// ---------------- box prep ----------------
__global__ void box_prep(const float* __restrict__ rois1, const float* __restrict__ rois2) {
    int i = blockIdx.x * blockDim.x + threadIdx.x;
    if (i >= N_) return;
    {
        float xmin = rois1[i*4+0], ymin = rois1[i*4+1], xmax = rois1[i*4+2], ymax = rois1[i*4+3];
        float w = xmax - xmin + 1.0f, h = ymax - ymin + 1.0f;
        g_boxA[i*4+0] = 0.5f*(xmin+xmax); g_boxA[i*4+1] = 0.5f*(ymin+ymax);
        g_boxA[i*4+2] = 1.0f/w;           g_boxA[i*4+3] = 1.0f/h;
        float lw = logf(w), lh = logf(h);
#pragma unroll
        for (int f = 0; f < 8; f++) {
            float s, c;
            sincosf(lw * c_cf[f], &s, &c);
            g_trigA[i*32 + f] = s;      g_trigA[i*32 + 8 + f] = c;
            sincosf(lh * c_cf[f], &s, &c);
            g_trigA[i*32 + 16 + f] = s; g_trigA[i*32 + 24 + f] = c;
        }
    }
    {
        float xmin = rois2[i*4+0], ymin = rois2[i*4+1], xmax = rois2[i*4+2], ymax = rois2[i*4+3];
        float w = xmax - xmin + 1.0f, h = ymax - ymin + 1.0f;
        g_boxB[i*4+0] = 0.5f*(xmin+xmax); g_boxB[i*4+1] = 0.5f*(ymin+ymax);
        g_boxB[i*4+2] = 1.0f/w;           g_boxB[i*4+3] = 1.0f/h;
        float lw = logf(w), lh = logf(h);
#pragma unroll
        for (int f = 0; f < 8; f++) {
            float s, c;
            sincosf(lw * c_cf[f], &s, &c);
            g_trigBt[f*M_ + i] = s;        g_trigBt[(8+f)*M_ + i] = c;
            sincosf(lh * c_cf[f], &s, &c);
            g_trigBt[(16+f)*M_ + i] = s;   g_trigBt[(24+f)*M_ + i] = c;
        }
    }
}

// ---------------- fp32 -> bf16 hi/lo (row-major tensors) ----------------
__global__ __launch_bounds__(256) void conv_a(const float* __restrict__ roi,
                                              const float* __restrict__ ref,
                                              const float* __restrict__ wv) {
    const int z = blockIdx.y;
    const float4* src = (const float4*)(z == 0 ? roi : z == 1 ? ref : wv);
    uint2* dh = (uint2*)(z == 0 ? g_roiH : z == 1 ? g_refH : g_wvH);
    uint2* dl = (uint2*)(z == 0 ? g_roiL : z == 1 ? g_refL : g_wvL);
    int i = blockIdx.x * 256 + threadIdx.x;
    float4 x = src[i];
    uint32_t h01 = cvt2bf(x.x, x.y), h23 = cvt2bf(x.z, x.w);
    float l0 = x.x - bflo(h01), l1 = x.y - bfhi(h01);
    float l2 = x.z - bflo(h23), l3 = x.w - bfhi(h23);
    dh[i] = make_uint2(h01, h23);
    dl[i] = make_uint2(cvt2bf(l0, l1), cvt2bf(l2, l3));
}

// ---------------- Wq/Wk transpose + bf16 hi/lo: W[k][j] -> Wt[j][k] ----------------
__global__ __launch_bounds__(256) void conv_w(const float* __restrict__ Wq,
                                              const float* __restrict__ Wk) {
    __shared__ float ts[64][65];
    const int z = blockIdx.z;
    const float* W = z ? Wk : Wq;
    uint2* dh = (uint2*)(z ? g_wktH : g_wqtH);
    uint2* dl = (uint2*)(z ? g_wktL : g_wqtL);
    const int j0 = blockIdx.x * 64, k0 = blockIdx.y * 64;
    const int t = threadIdx.x;
#pragma unroll
    for (int it = 0; it < 4; it++) {
        int lin = it * 256 + t;
        int k = lin >> 4, j4 = (lin & 15) << 2;
        float4 v = *(const float4*)&W[(size_t)(k0 + k) * D_ + j0 + j4];
        ts[j4 + 0][k] = v.x; ts[j4 + 1][k] = v.y; ts[j4 + 2][k] = v.z; ts[j4 + 3][k] = v.w;
    }
    __syncthreads();
#pragma unroll
    for (int it = 0; it < 4; it++) {
        int lin = it * 256 + t;
        int j = lin >> 4, k4 = (lin & 15) << 2;
        float a = ts[j][k4 + 0], b = ts[j][k4 + 1], c = ts[j][k4 + 2], d = ts[j][k4 + 3];
        uint32_t h01 = cvt2bf(a, b), h23 = cvt2bf(c, d);
        float l0 = a - bflo(h01), l1 = b - bfhi(h01);
        float l2 = c - bflo(h23), l3 = d - bfhi(h23);
        size_t idx = ((size_t)(j0 + j) * D_ + k0 + k4) >> 2;
        dh[idx] = make_uint2(h01, h23);
        dl[idx] = make_uint2(cvt2bf(l0, l1), cvt2bf(l2, l3));
    }
}

// ---------------- tensor-core GEMM: 128m x 64n tiles, 2 blocks/SM ----------------
// grid (16 j, 8 i, 3 mats). Outputs bf16 hi/lo:
// mat 0: q[n][d] (+bq), mat 1: k[m][d] (+bk), mat 2: vt[o][m] (transposed).
#define OFF_AH 0
#define OFF_AL 16384
#define OFF_BH 32768
#define OFF_BL 40960
#define STAGE_BYTES 49152
#define TC_SMEM (2 * STAGE_BYTES)   // 98304

__global__ __launch_bounds__(256, 2) void tc_gemm(const float* __restrict__ bq,
                                                  const float* __restrict__ bk) {
    extern __shared__ char smem[];
    const uint32_t sb = smem_to_u32(smem);
    const int t = threadIdx.x;
    const int wid = t >> 5, lane = t & 31;
    const int j0 = blockIdx.x * 64, i0 = blockIdx.y * 128;
    const int mat = blockIdx.z;

    const uint16_t* Ah;
    const uint16_t* Al;
    const uint16_t* Bh;
    const uint16_t* Bl;
    if (mat == 0)      { Ah = g_roiH; Al = g_roiL; Bh = g_wqtH; Bl = g_wqtL; }
    else if (mat == 1) { Ah = g_refH; Al = g_refL; Bh = g_wktH; Bl = g_wktL; }
    else               { Ah = g_refH; Al = g_refL; Bh = g_wvH;  Bl = g_wvL; }

    const int wm = wid & 3, wn = wid >> 2;
    const int lr = lane & 7, lq = lane >> 3;

    float d[2][4][4];
#pragma unroll
    for (int a = 0; a < 2; a++)
#pragma unroll
        for (int b = 0; b < 4; b++)
#pragma unroll
            for (int c = 0; c < 4; c++) d[a][b][c] = 0.0f;

    const uint32_t a_off0 = (uint32_t)((wm*32 + (lq & 1)*8 + lr) * 128 + (lq >> 1) * 16);
    const uint32_t b_off0 = (uint32_t)((wn*32 + lr) * 128 + (lq & 1) * 16);

    auto loadChunk = [&](int ch, int stage) {
        const uint32_t sbase = sb + stage * STAGE_BYTES;
        {
            int row = t >> 1;
#pragma unroll
            for (int uu = 0; uu < 4; uu++) {
                int u = (t & 1) * 4 + uu;
                uint32_t so = SWZ((uint32_t)(row * 128 + u * 16));
                cp16(sbase + OFF_AH + so, Ah + ((size_t)(i0 + row) * 1024 + ch * 64 + u * 8));
                cp16(sbase + OFF_AL + so, Al + ((size_t)(i0 + row) * 1024 + ch * 64 + u * 8));
            }
        }
        {
            int row = t >> 2;
#pragma unroll
            for (int uu = 0; uu < 2; uu++) {
                int u = (t & 3) * 2 + uu;
                uint32_t so = SWZ((uint32_t)(row * 128 + u * 16));
                cp16(sbase + OFF_BH + so, Bh + ((size_t)(j0 + row) * 1024 + ch * 64 + u * 8));
                cp16(sbase + OFF_BL + so, Bl + ((size_t)(j0 + row) * 1024 + ch * 64 + u * 8));
            }
        }
    };

    loadChunk(0, 0);
    CP_COMMIT();

    for (int ch = 0; ch < 16; ch++) {
        if (ch + 1 < 16) {
            loadChunk(ch + 1, (ch + 1) & 1);
            CP_COMMIT();
            asm volatile("cp.async.wait_group 1;" ::: "memory");
        } else {
            asm volatile("cp.async.wait_group 0;" ::: "memory");
        }
        __syncthreads();

        const uint32_t st = sb + (ch & 1) * STAGE_BYTES;
#pragma unroll
        for (int ks = 0; ks < 4; ks++) {
            const uint32_t kb = (uint32_t)(ks * 32);
            uint32_t ah[2][4], al[2][4], bh[4][2], bl[4][2];
#pragma unroll
            for (int ma = 0; ma < 2; ma++) {
                uint32_t off = SWZ(a_off0 + (uint32_t)(ma * 16 * 128) + kb);
                ldsm_x4(ah[ma], st + OFF_AH + off);
                ldsm_x4(al[ma], st + OFF_AL + off);
            }
#pragma unroll
            for (int na = 0; na < 4; na++) {
                uint32_t off = SWZ(b_off0 + (uint32_t)(na * 8 * 128) + kb);
                ldsm_x2(bh[na], st + OFF_BH + off);
                ldsm_x2(bl[na], st + OFF_BL + off);
            }
#pragma unroll
            for (int ma = 0; ma < 2; ma++)
#pragma unroll
                for (int na = 0; na < 4; na++)
                    mma16816(d[ma][na], ah[ma], bh[na]);
#pragma unroll
            for (int ma = 0; ma < 2; ma++)
#pragma unroll
                for (int na = 0; na < 4; na++)
                    mma16816(d[ma][na], ah[ma], bl[na]);
#pragma unroll
            for (int ma = 0; ma < 2; ma++)
#pragma unroll
                for (int na = 0; na < 4; na++)
                    mma16816(d[ma][na], al[ma], bh[na]);
        }
        __syncthreads();
    }

    // stage D in smem: sd[128 i][68] cols j
    float* sd = (float*)smem;
    const int gid = lane >> 2, tig = lane & 3;
#pragma unroll
    for (int ma = 0; ma < 2; ma++)
#pragma unroll
        for (int na = 0; na < 4; na++) {
            int row = wm * 32 + ma * 16 + gid;
            int col = wn * 32 + na * 8 + 2 * tig;
            sd[row * 68 + col]           = d[ma][na][0];
            sd[row * 68 + col + 1]       = d[ma][na][1];
            sd[(row + 8) * 68 + col]     = d[ma][na][2];
            sd[(row + 8) * 68 + col + 1] = d[ma][na][3];
        }
    __syncthreads();

    if (mat != 2) {
        // row-major bf16 hi/lo store with bias: dst[n/m][d]
        const float* bias = (mat == 0) ? bq : bk;
        uint16_t* dH = (mat == 0) ? g_qbH : g_kbH;
        uint16_t* dL = (mat == 0) ? g_qbL : g_kbL;
        int i = t >> 1, jh = (t & 1) * 32;
#pragma unroll
        for (int jj = 0; jj < 32; jj += 4) {
            float4 v = *(const float4*)&sd[i * 68 + jh + jj];
            float4 bb = *(const float4*)&bias[j0 + jh + jj];
            v.x += bb.x; v.y += bb.y; v.z += bb.z; v.w += bb.w;
            uint32_t h01 = cvt2bf(v.x, v.y), h23 = cvt2bf(v.z, v.w);
            float l0 = v.x - bflo(h01), l1 = v.y - bfhi(h01);
            float l2 = v.z - bflo(h23), l3 = v.w - bfhi(h23);
            size_t off = (size_t)(i0 + i) * 1024 + j0 + jh + jj;
            *(uint2*)&dH[off] = make_uint2(h01, h23);
            *(uint2*)&dL[off] = make_uint2(cvt2bf(l0, l1), cvt2bf(l2, l3));
        }
    } else {
        // transposed bf16 hi/lo store: vt[o][m]
        int j = t >> 2, ih = (t & 3) * 32;
#pragma unroll
        for (int mm = 0; mm < 32; mm += 4) {
            float v0 = sd[(ih + mm + 0) * 68 + j];
            float v1 = sd[(ih + mm + 1) * 68 + j];
            float v2 = sd[(ih + mm + 2) * 68 + j];
            float v3 = sd[(ih + mm + 3) * 68 + j];
            uint32_t h01 = cvt2bf(v0, v1), h23 = cvt2bf(v2, v3);
            float l0 = v0 - bflo(h01), l1 = v1 - bfhi(h01);
            float l2 = v2 - bflo(h23), l3 = v3 - bfhi(h23);
            size_t off = (size_t)(j0 + j) * 1024 + i0 + ih + mm;
            *(uint2*)&g_vtH[off] = make_uint2(h01, h23);
            *(uint2*)&g_vtL[off] = make_uint2(cvt2bf(l0, l1), cvt2bf(l2, l3));
        }
    }
}

// ---------------- position-weight kernel (unchanged) ----------------
__global__ __launch_bounds__(256, 2) void posw_kernel(const float* __restrict__ Wg,
                                                      const float* __restrict__ bg) {
    __shared__ float wgt[64][16];
    __shared__ float bgs[G_];
    const int t = threadIdx.x;
#pragma unroll
    for (int i = t; i < 1024; i += 256) {
        int g = i >> 6, e = i & 63;
        wgt[e][g] = Wg[i];
    }
    if (t < G_) bgs[t] = bg[t];
    __syncthreads();

    const int n = blockIdx.y;
    const int m0 = blockIdx.x * 512 + t;
    const int m1 = m0 + 256;

    u64 acc0[8], acc1[8];
#pragma unroll
    for (int gp = 0; gp < 8; gp++) {
        u64 b2 = pack2(bgs[2*gp], bgs[2*gp+1]);
        acc0[gp] = b2;
        acc1[gp] = b2;
    }

    auto upd = [&](int e, float v0, float v1) {
        const ulonglong2* wr = (const ulonglong2*)&wgt[e][0];
        ulonglong2 wa = wr[0], wb = wr[1];
        u64 d0 = dup2(v0), d1 = dup2(v1);
        fma2(acc0[0], d0, wa.x); fma2(acc1[0], d1, wa.x);
        fma2(acc0[1], d0, wa.y); fma2(acc1[1], d1, wa.y);
        fma2(acc0[2], d0, wb.x); fma2(acc1[2], d1, wb.x);
        fma2(acc0[3], d0, wb.y); fma2(acc1[3], d1, wb.y);
        ulonglong2 wc = wr[2], wd = wr[3];
        fma2(acc0[4], d0, wc.x); fma2(acc1[4], d1, wc.x);
        fma2(acc0[5], d0, wc.y); fma2(acc1[5], d1, wc.y);
        fma2(acc0[6], d0, wd.x); fma2(acc1[6], d1, wd.x);
        fma2(acc0[7], d0, wd.y); fma2(acc1[7], d1, wd.y);
    };

    const float4 bn = *(const float4*)&g_boxA[n * 4];
    const float4 bm0 = *(const float4*)&g_boxB[m0 * 4];
    const float4 bm1 = *(const float4*)&g_boxB[m1 * 4];

    {
        float px0 = __logf(fabsf(bn.x - bm0.x) * bn.z + 1e-3f);
        float px1 = __logf(fabsf(bn.x - bm1.x) * bn.z + 1e-3f);
#pragma unroll
        for (int f = 0; f < 8; f++) {
            float s0, c0, s1, c1;
            __sincosf(px0 * c_cf[f], &s0, &c0);
            __sincosf(px1 * c_cf[f], &s1, &c1);
            upd(f, s0, s1);
            upd(8 + f, c0, c1);
        }
        float py0 = __logf(fabsf(bn.y - bm0.y) * bn.w + 1e-3f);
        float py1 = __logf(fabsf(bn.y - bm1.y) * bn.w + 1e-3f);
#pragma unroll
        for (int f = 0; f < 8; f++) {
            float s0, c0, s1, c1;
            __sincosf(py0 * c_cf[f], &s0, &c0);
            __sincosf(py1 * c_cf[f], &s1, &c1);
            upd(16 + f, s0, s1);
            upd(24 + f, c0, c1);
        }
    }

#pragma unroll
    for (int f = 0; f < 8; f++) {
        float snf = g_trigA[n*32 + f], cnf = g_trigA[n*32 + 8 + f];
        float sm0 = g_trigBt[f*M_ + m0], cm0 = g_trigBt[(8+f)*M_ + m0];
        float sm1 = g_trigBt[f*M_ + m1], cm1 = g_trigBt[(8+f)*M_ + m1];
        upd(32 + f, snf*cm0 - cnf*sm0, snf*cm1 - cnf*sm1);
        upd(40 + f, fmaf(cnf, cm0, snf*sm0), fmaf(cnf, cm1, snf*sm1));
    }
#pragma unroll
    for (int f = 0; f < 8; f++) {
        float snf = g_trigA[n*32 + 16 + f], cnf = g_trigA[n*32 + 24 + f];
        float sm0 = g_trigBt[(16+f)*M_ + m0], cm0 = g_trigBt[(24+f)*M_ + m0];
        float sm1 = g_trigBt[(16+f)*M_ + m1], cm1 = g_trigBt[(24+f)*M_ + m1];
        upd(48 + f, snf*cm0 - cnf*sm0, snf*cm1 - cnf*sm1);
        upd(56 + f, fmaf(cnf, cm0, snf*sm0), fmaf(cnf, cm1, snf*sm1));
    }

    const size_t base = (size_t)n * G_ * M_;
#pragma unroll
    for (int gp = 0; gp < 8; gp++) {
        float x0, y0, x1, y1;
        unpack2(acc0[gp], x0, y0);
        unpack2(acc1[gp], x1, y1);
        g_w[base + (size_t)(2*gp)   * M_ + m0] = fmaxf(x0, 0.0f) + 1e-6f;
        g_w[base + (size_t)(2*gp+1) * M_ + m0] = fmaxf(y0, 0.0f) + 1e-6f;
        g_w[base + (size_t)(2*gp)   * M_ + m1] = fmaxf(x1, 0.0f) + 1e-6f;
        g_w[base + (size_t)(2*gp+1) * M_ + m1] = fmaxf(y1, 0.0f) + 1e-6f;
    }
}

// ---------------- flash on tensor cores ----------------
// grid (8 n-tiles, 16 g, 2 m-splits), 256 thr = 8 warps x 16n.
// Per iter: 64 m. QK: qh*kh+qh*kl+ql*kh; P->bf16 hi/lo in regs; PV: Ph*Vh+Ph*Vl+Pl*Vh.
#define FQ_H 0
#define FQ_L 16384
#define FSTG 32768
#define FS_KH 0
#define FS_KL 8192
#define FS_VH 16384
#define FS_VL 24576
#define FSTG_BYTES 32768
#define FLASH_SMEM (32768 + 2 * 32768)   // 98304

__global__ __launch_bounds__(256, 2) void flash_kernel() {
    extern __shared__ char smem[];
    const uint32_t sb = smem_to_u32(smem);
    const int t = threadIdx.x;
    const int wid = t >> 5, lane = t & 31;
    const int lr = lane & 7, lq = lane >> 3;
    const int gid = lane >> 2, tig = lane & 3;
    const int g = blockIdx.y;
    const int n0 = blockIdx.x * 128;
    const int z = blockIdx.z;

    const uint32_t a_off0 = (uint32_t)((wid*16 + (lq & 1)*8 + lr) * 128 + (lq >> 1) * 16);
    const uint32_t b_off0 = (uint32_t)(lr * 128 + (lq & 1) * 16);

    // load q tile (128n x 64d, hi+lo)
    {
        int row = t >> 1;
#pragma unroll
        for (int uu = 0; uu < 4; uu++) {
            int u = (t & 1) * 4 + uu;
            uint32_t so = SWZ((uint32_t)(row * 128 + u * 16));
            cp16(sb + FQ_H + so, g_qbH + ((size_t)(n0 + row) * 1024 + g * 64 + u * 8));
            cp16(sb + FQ_L + so, g_qbL + ((size_t)(n0 + row) * 1024 + g * 64 + u * 8));
        }
    }
    auto loadStage = [&](int it, int stg) {
        const uint32_t sbase = sb + FSTG + stg * FSTG_BYTES;
        const int m0 = z * 512 + it * 64;
        int row = t >> 2;
#pragma unroll
        for (int uu = 0; uu < 2; uu++) {
            int u = (t & 3) * 2 + uu;
            uint32_t so = SWZ((uint32_t)(row * 128 + u * 16));
            cp16(sbase + FS_KH + so, g_kbH + ((size_t)(m0 + row) * 1024 + g * 64 + u * 8));
            cp16(sbase + FS_KL + so, g_kbL + ((size_t)(m0 + row) * 1024 + g * 64 + u * 8));
            cp16(sbase + FS_VH + so, g_vtH + ((size_t)(g * 64 + row) * 1024 + m0 + u * 8));
            cp16(sbase + FS_VL + so, g_vtL + ((size_t)(g * 64 + row) * 1024 + m0 + u * 8));
        }
    };

    loadStage(0, 0);
    CP_COMMIT();

    float o_[8][4];
#pragma unroll
    for (int a = 0; a < 8; a++)
#pragma unroll
        for (int b = 0; b < 4; b++) o_[a][b] = 0.0f;
    float lr0 = 0.0f, lr1 = 0.0f;

    for (int it = 0; it < 8; it++) {
        if (it + 1 < 8) {
            loadStage(it + 1, (it + 1) & 1);
            CP_COMMIT();
            asm volatile("cp.async.wait_group 1;" ::: "memory");
        } else {
            asm volatile("cp.async.wait_group 0;" ::: "memory");
        }
        __syncthreads();

        const uint32_t st = sb + FSTG + (it & 1) * FSTG_BYTES;
        const int m0 = z * 512 + it * 64;

        // S = q . k^T (hi/lo, drop lo*lo)
        float s[8][4];
#pragma unroll
        for (int a = 0; a < 8; a++)
#pragma unroll
            for (int b = 0; b < 4; b++) s[a][b] = 0.0f;

#pragma unroll
        for (int dc = 0; dc < 4; dc++) {
            uint32_t aoff = SWZ(a_off0 + (uint32_t)(dc * 32));
            uint32_t aqh[4], aql[4];
            ldsm_x4(aqh, sb + FQ_H + aoff);
            ldsm_x4(aql, sb + FQ_L + aoff);
#pragma unroll
            for (int mt = 0; mt < 8; mt++) {
                uint32_t boff = SWZ(b_off0 + (uint32_t)(mt * 8 * 128 + dc * 32));
                uint32_t bkh[2], bkl[2];
                ldsm_x2(bkh, st + FS_KH + boff);
                ldsm_x2(bkl, st + FS_KL + boff);
                mma16816(s[mt], aqh, bkh);
                mma16816(s[mt], aqh, bkl);
                mma16816(s[mt], aql, bkh);
            }
        }

        // softmax numerators -> P bf16 hi/lo A-fragments (FA2 C->A identity)
        uint32_t paH[4][4], paL[4][4];
        const size_t wbase0 = ((size_t)(n0 + wid * 16 + gid) * G_ + g) * M_;
        const size_t wbase1 = wbase0 + (size_t)8 * G_ * M_;
#pragma unroll
        for (int mt = 0; mt < 8; mt++) {
            int mcol = m0 + mt * 8 + 2 * tig;
            float2 w0 = *(const float2*)&g_w[wbase0 + mcol];
            float2 w1 = *(const float2*)&g_w[wbase1 + mcol];
            float p0 = w0.x * fast_exp(s[mt][0] * 0.125f);
            float p1 = w0.y * fast_exp(s[mt][1] * 0.125f);
            float p2 = w1.x * fast_exp(s[mt][2] * 0.125f);
            float p3 = w1.y * fast_exp(s[mt][3] * 0.125f);
            lr0 += p0 + p1;
            lr1 += p2 + p3;
            uint32_t h01 = cvt2bf(p0, p1), h23 = cvt2bf(p2, p3);
            float l0 = p0 - bflo(h01), l1 = p1 - bfhi(h01);
            float l2 = p2 - bflo(h23), l3 = p3 - bfhi(h23);
            int kc = mt >> 1, hf = (mt & 1) * 2;
            paH[kc][hf + 0] = h01;
            paH[kc][hf + 1] = h23;
            paL[kc][hf + 0] = cvt2bf(l0, l1);
            paL[kc][hf + 1] = cvt2bf(l2, l3);
        }

        // out += P . V (hi/lo, drop lo*lo)
#pragma unroll
        for (int kc = 0; kc < 4; kc++) {
#pragma unroll
            for (int ot = 0; ot < 8; ot++) {
                uint32_t boff = SWZ(b_off0 + (uint32_t)(ot * 8 * 128 + kc * 32));
                uint32_t bvh[2], bvl[2];
                ldsm_x2(bvh, st + FS_VH + boff);
                ldsm_x2(bvl, st + FS_VL + boff);
                mma16816(o_[ot], paH[kc], bvh);
                mma16816(o_[ot], paH[kc], bvl);
                mma16816(o_[ot], paL[kc], bvh);
            }
        }
        __syncthreads();
    }

    // reduce lrun across the quad (lanes sharing gid)
    lr0 += __shfl_xor_sync(0xffffffffu, lr0, 1);
    lr0 += __shfl_xor_sync(0xffffffffu, lr0, 2);
    lr1 += __shfl_xor_sync(0xffffffffu, lr1, 1);
    lr1 += __shfl_xor_sync(0xffffffffu, lr1, 2);

    const int r0 = n0 + wid * 16 + gid;
    if (tig == 0) {
        g_pl[z][(size_t)r0 * G_ + g] = lr0;
        g_pl[z][(size_t)(r0 + 8) * G_ + g] = lr1;
    }
#pragma unroll
    for (int ot = 0; ot < 8; ot++) {
        int col = g * 64 + ot * 8 + 2 * tig;
        *(float2*)&g_pacc[z][(size_t)r0 * D_ + col] = make_float2(o_[ot][0], o_[ot][1]);
        *(float2*)&g_pacc[z][(size_t)(r0 + 8) * D_ + col] = make_float2(o_[ot][2], o_[ot][3]);
    }
}

// ---------------- combine partials ----------------
__global__ __launch_bounds__(256) void reduce_kernel(const float* __restrict__ bv,
                                                     float* __restrict__ out) {
    int idx = blockIdx.x * 256 + threadIdx.x;
    int n = idx >> 8;
    int col = (idx & 255) << 2;
    int g = col >> 6;
    float l = 0.0f;
    float4 a = make_float4(0.f, 0.f, 0.f, 0.f);
#pragma unroll
    for (int zz = 0; zz < SPLITS; zz++) {
        l += g_pl[zz][(size_t)n * G_ + g];
        float4 p = *(const float4*)&g_pacc[zz][(size_t)n * D_ + col];
        a.x += p.x; a.y += p.y; a.z += p.z; a.w += p.w;
    }
    float inv = 1.0f / l;
    float4 b4 = *(const float4*)&bv[col];
    float4 o;
    o.x = fmaf(a.x, inv, b4.x);
    o.y = fmaf(a.y, inv, b4.y);
    o.z = fmaf(a.z, inv, b4.z);
    o.w = fmaf(a.w, inv, b4.w);
    *(float4*)&out[(size_t)n * D_ + col] = o;
}

// ---------------- host launcher ----------------
extern "C" void kernel_launch(void* const* d_in, const int* in_sizes, int n_in,
                              void* d_out, int out_size) {
    const float* roi   = (const float*)d_in[0];
    const float* ref   = (const float*)d_in[1];
    const float* rois1 = (const float*)d_in[2];
    const float* rois2 = (const float*)d_in[3];
    const float* Wq    = (const float*)d_in[4];
    const float* bq    = (const float*)d_in[5];
    const float* Wk    = (const float*)d_in[6];
    const float* bk    = (const float*)d_in[7];
    const float* Wg    = (const float*)d_in[8];
    const float* bg    = (const float*)d_in[9];
    const float* Wv    = (const float*)d_in[10];
    const float* bv    = (const float*)d_in[11];
    float* out = (float*)d_out;

    static bool attr_set = false;
    if (!attr_set) {
        cudaFuncSetAttribute(flash_kernel, cudaFuncAttributeMaxDynamicSharedMemorySize, FLASH_SMEM);
        cudaFuncSetAttribute(tc_gemm, cudaFuncAttributeMaxDynamicSharedMemorySize, TC_SMEM);
        attr_set = true;
    }

    box_prep<<<4, 256>>>(rois1, rois2);
    conv_a<<<dim3(1024, 3), 256>>>(roi, ref, Wv);
    conv_w<<<dim3(16, 16, 2), 256>>>(Wq, Wk);
    tc_gemm<<<dim3(16, 8, 3), 256, TC_SMEM>>>(bq, bk);
    posw_kernel<<<dim3(2, 1024), 256>>>(Wg, bg);
    flash_kernel<<<dim3(8, 16, 2), 256, FLASH_SMEM>>>();
    reduce_kernel<<<1024, 256>>>(bv, out);
}